// round 5
// baseline (speedup 1.0000x reference)
#include <cuda_runtime.h>
#include <math.h>

#define NN   20000
#define EE   320000
#define CC   64
#define NBF  16
#define RCUT 5.0f
#define CSP  (RCUT/(NBF-1))
#define WIDTH (RCUT/NBF)
#define PI_F 3.14159265358979f
#define FULLMASK 0xffffffffu

// ---------------- device scratch ------------------------------------------
static __device__ int   g_cnt;
static __device__ int   g_hist[2*NN];     // statically zero; re-zeroed by scan_k
static __device__ int   g_cur[2*NN];
static __device__ __align__(16) int2   g_Iij[EE];
static __device__ __align__(16) float4 g_Im[EE];
static __device__ __align__(16) int2   g_Jij[EE];
static __device__ __align__(16) float4 g_Jm[EE];

static __device__ __align__(16) float g_h0a[NN*CC];
static __device__ __align__(16) float g_h0b[NN*CC];
static __device__ __align__(16) float g_h0c[NN*CC];
static __device__ __align__(16) float g_s0[NN*CC];
static __device__ __align__(16) float g_s1[NN*CC];
static __device__ __align__(16) float g_h1b[NN*3*CC];
static __device__ __align__(16) float g_M[NN*CC*4];      // M0 | M1
static __device__ __align__(16) float g_gM0[NN*CC];
static __device__ __align__(16) float g_gM1[NN*3*CC];
static __device__ __align__(16) float g_gA[NN*CC];
static __device__ __align__(16) float g_gB[NN*CC];
static __device__ __align__(16) float g_gh1[NN*3*CC];

__device__ __forceinline__ float warpRed(float v){
#pragma unroll
    for(int o=16;o>0;o>>=1) v += __shfl_xor_sync(FULLMASK, v, o);
    return v;
}

__device__ __forceinline__ void red2(float* addr, float a, float b){
    asm volatile("red.global.add.v2.f32 [%0], {%1, %2};"
                 :: "l"(addr), "f"(a), "f"(b) : "memory");
}

// ---------------- embedding gather + M-buffer zero (fused) -----------------
__global__ void embed_zero_k(const float* __restrict__ emb, const int* __restrict__ z)
{
    const int NH = NN*16;          // h0a in float4
    const int NM = NN*64;          // M buffer in float4 (NN*CC*4 floats)
    for(int idx = blockIdx.x*blockDim.x + threadIdx.x; idx < NH + NM;
        idx += gridDim.x*blockDim.x){
        if(idx < NH){
            int n = idx >> 4, q = idx & 15;
            int zn = __ldg(&z[n]);
            ((float4*)g_h0a)[idx] = ((const float4*)emb)[zn*16 + q];
        } else {
            ((float4*)g_M)[idx - NH] = make_float4(0.f,0.f,0.f,0.f);
        }
    }
}

// ---------------- geometry pass 1: histograms ------------------------------
__global__ void geomA_k(const float* __restrict__ coord,
                        const int* __restrict__ ei, const int* __restrict__ ej)
{
    int e = blockIdx.x*blockDim.x + threadIdx.x;
    if(e >= EE) return;
    int i = ei[e], j = ej[e];
    float dx = coord[j*3+0] - coord[i*3+0];
    float dy = coord[j*3+1] - coord[i*3+1];
    float dz = coord[j*3+2] - coord[i*3+2];
    float d2 = dx*dx + dy*dy + dz*dz + 1e-12f;
    if(d2 < RCUT*RCUT){
        atomicAdd(&g_hist[i], 1);
        atomicAdd(&g_hist[NN+j], 1);
    }
}

// ---------------- exclusive scans; re-zero histogram for next replay -------
__global__ __launch_bounds__(1024) void scan_k()
{
    __shared__ int swarp[32];
    int t = threadIdx.x;
    int lane = t & 31, wid = t >> 5;
    for(int pass=0; pass<2; pass++){
        int* hist = g_hist + pass*NN;
        int* cur = g_cur + pass*NN;
        int base = t*20;
        int local[20];
        int s = 0;
#pragma unroll
        for(int q=0;q<20;q++){
            int idx = base + q;
            int v = (idx < NN) ? hist[idx] : 0;
            local[q] = s; s += v;
            if(idx < NN) hist[idx] = 0;       // re-zero for next replay
        }
        int inc = s;
#pragma unroll
        for(int o=1;o<32;o<<=1){
            int n = __shfl_up_sync(FULLMASK, inc, o);
            if(lane >= o) inc += n;
        }
        if(lane == 31) swarp[wid] = inc;
        __syncthreads();
        if(wid == 0){
            int v = swarp[lane];
#pragma unroll
            for(int o=1;o<32;o<<=1){
                int n = __shfl_up_sync(FULLMASK, v, o);
                if(lane >= o) v += n;
            }
            swarp[lane] = v;
        }
        __syncthreads();
        int offset = inc - s + ((wid > 0) ? swarp[wid-1] : 0);
#pragma unroll
        for(int q=0;q<20;q++){
            int idx = base + q;
            if(idx < NN) cur[idx] = offset + local[q];
        }
        if(pass == 0 && t == 1023) g_cnt = offset + s;
        __syncthreads();
    }
}

// ---------------- geometry pass 2: write both sorted orders ----------------
__global__ void geomB_k(const float* __restrict__ coord,
                        const int* __restrict__ ei, const int* __restrict__ ej)
{
    int e = blockIdx.x*blockDim.x + threadIdx.x;
    if(e >= EE) return;
    int i = ei[e], j = ej[e];
    float dx = coord[j*3+0] - coord[i*3+0];
    float dy = coord[j*3+1] - coord[i*3+1];
    float dz = coord[j*3+2] - coord[i*3+2];
    float d2 = dx*dx + dy*dy + dz*dz + 1e-12f;
    if(d2 >= RCUT*RCUT) return;
    float d = sqrtf(d2);
    float inv = 1.0f/d;
    float4 m = make_float4(d, dx*inv, dy*inv, dz*inv);
    int2 ij = make_int2(i, j);
    int posI = atomicAdd(&g_cur[i], 1);
    g_Iij[posI] = ij;  g_Im[posI] = m;
    int posJ = atomicAdd(&g_cur[NN+j], 1);
    g_Jij[posJ] = ij;  g_Jm[posJ] = m;
}

// ---------------- forward layer-0 edge kernel (i-sorted; paths {0,1}) ------
__global__ __launch_bounds__(128) void edge_fwd0_k(
    const float* __restrict__ Wr_l, const float* __restrict__ br_l,
    const float* __restrict__ h0)
{
    int tid = threadIdx.x;
    int cnt = g_cnt;
    int e0 = (blockIdx.x*4 + (tid>>5))*8;
    if(e0 >= cnt) return;
    int lane = tid & 31;
    int c = 2*lane;
    int eend = min(e0 + 8, cnt);

    float2 WA[NBF], WB[NBF];
    const float2* wa = (const float2*)Wr_l;          // path 0
    const float2* wb = (const float2*)Wr_l + 512;    // path 1
#pragma unroll
    for(int b=0;b<NBF;b++){ WA[b] = wa[b*32+lane]; WB[b] = wb[b*32+lane]; }
    float2 bA = ((const float2*)br_l)[lane];
    float2 bB = ((const float2*)br_l)[32+lane];

    float* M0 = g_M;
    float* M1 = g_M + NN*CC;

    float2 a0c = make_float2(0.f,0.f);
    float2 a1c[3] = {{0,0},{0,0},{0,0}};
    int curi = g_Iij[e0].x;

    for(int e=e0;e<eend;e++){
        int2 ij = g_Iij[e];
        if(ij.x != curi){
            red2(&M0[curi*64+c], a0c.x, a0c.y);
#pragma unroll
            for(int x=0;x<3;x++) red2(&M1[(curi*3+x)*64+c], a1c[x].x, a1c[x].y);
            a0c = make_float2(0.f,0.f);
#pragma unroll
            for(int x=0;x<3;x++) a1c[x] = make_float2(0.f,0.f);
            curi = ij.x;
        }
        int j = ij.y;
        float4 m = g_Im[e];
        float d = m.x;
        float rh[3] = {m.y, m.z, m.w};
        float fc = 0.5f*(__cosf(PI_F*d/RCUT) + 1.0f);
        float rb = 0.f;
        if(lane < NBF){
            float zz = (d - lane*CSP)/WIDTH;
            rb = __expf(-zz*zz);
        }
        float2 p0 = bA, p1 = bB;
#pragma unroll
        for(int b=0;b<NBF;b++){
            float r = __shfl_sync(FULLMASK, rb, b);
            p0.x = fmaf(r, WA[b].x, p0.x); p0.y = fmaf(r, WA[b].y, p0.y);
            p1.x = fmaf(r, WB[b].x, p1.x); p1.y = fmaf(r, WB[b].y, p1.y);
        }
        float2 h0j = *(const float2*)&h0[j*64+c];
        a0c.x = fmaf(fc*p0.x, h0j.x, a0c.x);
        a0c.y = fmaf(fc*p0.y, h0j.y, a0c.y);
        float g1x = fc*p1.x*h0j.x, g1y = fc*p1.y*h0j.y;
#pragma unroll
        for(int x=0;x<3;x++){
            a1c[x].x = fmaf(g1x, rh[x], a1c[x].x);
            a1c[x].y = fmaf(g1y, rh[x], a1c[x].y);
        }
    }
    red2(&M0[curi*64+c], a0c.x, a0c.y);
#pragma unroll
    for(int x=0;x<3;x++) red2(&M1[(curi*3+x)*64+c], a1c[x].x, a1c[x].y);
}

// ---------------- forward layer-1 edge kernel (i-sorted; paths {0,2}) ------
__global__ __launch_bounds__(128) void edge_fwd1_k(
    const float* __restrict__ Wr_l, const float* __restrict__ br_l,
    const float* __restrict__ h0,   const float* __restrict__ h1)
{
    int tid = threadIdx.x;
    int cnt = g_cnt;
    int e0 = (blockIdx.x*4 + (tid>>5))*8;
    if(e0 >= cnt) return;
    int lane = tid & 31;
    int c = 2*lane;
    int eend = min(e0 + 8, cnt);

    float2 WA[NBF], WB[NBF];
    const float2* wa = (const float2*)Wr_l;           // path 0
    const float2* wb = (const float2*)Wr_l + 1024;    // path 2
#pragma unroll
    for(int b=0;b<NBF;b++){ WA[b] = wa[b*32+lane]; WB[b] = wb[b*32+lane]; }
    float2 bA = ((const float2*)br_l)[lane];
    float2 bB = ((const float2*)br_l)[64+lane];

    float* M0 = g_M;
    float2 a0c = make_float2(0.f,0.f);
    int curi = g_Iij[e0].x;

    for(int e=e0;e<eend;e++){
        int2 ij = g_Iij[e];
        if(ij.x != curi){
            red2(&M0[curi*64+c], a0c.x, a0c.y);
            a0c = make_float2(0.f,0.f);
            curi = ij.x;
        }
        int j = ij.y;
        float4 m = g_Im[e];
        float d = m.x;
        float rh[3] = {m.y, m.z, m.w};
        float fc = 0.5f*(__cosf(PI_F*d/RCUT) + 1.0f);
        float rb = 0.f;
        if(lane < NBF){
            float zz = (d - lane*CSP)/WIDTH;
            rb = __expf(-zz*zz);
        }
        float2 p0 = bA, p2 = bB;
#pragma unroll
        for(int b=0;b<NBF;b++){
            float r = __shfl_sync(FULLMASK, rb, b);
            p0.x = fmaf(r, WA[b].x, p0.x); p0.y = fmaf(r, WA[b].y, p0.y);
            p2.x = fmaf(r, WB[b].x, p2.x); p2.y = fmaf(r, WB[b].y, p2.y);
        }
        float2 h0j = *(const float2*)&h0[j*64+c];
        float2 v[3];
#pragma unroll
        for(int x=0;x<3;x++) v[x] = *(const float2*)&h1[(j*3+x)*64+c];
        float tx = v[0].x*rh[0] + v[1].x*rh[1] + v[2].x*rh[2];
        float ty = v[0].y*rh[0] + v[1].y*rh[1] + v[2].y*rh[2];
        a0c.x += fc*(p0.x*h0j.x + p2.x*tx);
        a0c.y += fc*(p0.y*h0j.y + p2.y*ty);
    }
    red2(&M0[curi*64+c], a0c.x, a0c.y);
}

// ---------------- backward layer-0 (i-sorted; paths {0,1}; h1==0) ----------
__global__ __launch_bounds__(128) void edge_bwd0_k(
    const float* __restrict__ Wr_l, const float* __restrict__ br_l,
    const float* __restrict__ h0,
    const float* __restrict__ gM0,  const float* __restrict__ gM1,
    float* __restrict__ F)
{
    int tid = threadIdx.x;
    int cnt = g_cnt;
    int e0 = (blockIdx.x*4 + (tid>>5))*8;
    if(e0 >= cnt) return;
    int lane = tid & 31;
    int c = 2*lane;
    int eend = min(e0 + 8, cnt);

    float2 WA[NBF], WB[NBF];
    const float2* wa = (const float2*)Wr_l;
    const float2* wb = (const float2*)Wr_l + 512;    // path 1
#pragma unroll
    for(int b=0;b<NBF;b++){ WA[b] = wa[b*32+lane]; WB[b] = wb[b*32+lane]; }
    float2 bA = ((const float2*)br_l)[lane];
    float2 bB = ((const float2*)br_l)[32+lane];

    int curi = g_Iij[e0].x;
    float2 gm0 = *(const float2*)&gM0[curi*64+c];
    float2 gm1[3];
#pragma unroll
    for(int x=0;x<3;x++) gm1[x] = *(const float2*)&gM1[(curi*3+x)*64+c];
    float fi = 0.f;

    for(int e=e0;e<eend;e++){
        int2 ij = g_Iij[e];
        if(ij.x != curi){
            if(lane < 3) atomicAdd(&F[curi*3+lane], fi);
            fi = 0.f;
            curi = ij.x;
            gm0 = *(const float2*)&gM0[curi*64+c];
#pragma unroll
            for(int x=0;x<3;x++) gm1[x] = *(const float2*)&gM1[(curi*3+x)*64+c];
        }
        int j = ij.y;
        float4 m = g_Im[e];
        float d = m.x;
        float rh[3] = {m.y, m.z, m.w};
        float fc = 0.5f*(__cosf(PI_F*d/RCUT) + 1.0f);
        float rb = 0.f, wbv = 0.f;
        if(lane < NBF){
            float zz = (d - lane*CSP)/WIDTH;
            rb = __expf(-zz*zz);
            wbv = rb * (-2.0f*zz/WIDTH);
        }
        float2 preA = bA, preB = bB;
        float2 qA = make_float2(0,0), qB = make_float2(0,0);
#pragma unroll
        for(int b=0;b<NBF;b++){
            float r = __shfl_sync(FULLMASK, rb, b);
            float w = __shfl_sync(FULLMASK, wbv, b);
            preA.x = fmaf(r, WA[b].x, preA.x); preA.y = fmaf(r, WA[b].y, preA.y);
            preB.x = fmaf(r, WB[b].x, preB.x); preB.y = fmaf(r, WB[b].y, preB.y);
            qA.x = fmaf(w, WA[b].x, qA.x); qA.y = fmaf(w, WA[b].y, qA.y);
            qB.x = fmaf(w, WB[b].x, qB.x); qB.y = fmaf(w, WB[b].y, qB.y);
        }
        float2 h0j = *(const float2*)&h0[j*64+c];
        float gmrx = gm1[0].x*rh[0] + gm1[1].x*rh[1] + gm1[2].x*rh[2];
        float gmry = gm1[0].y*rh[0] + gm1[1].y*rh[1] + gm1[2].y*rh[2];

        float gf0x = gm0.x*h0j.x, gf0y = gm0.y*h0j.y;
        float gf1x = gmrx*h0j.x,  gf1y = gmry*h0j.y;
        float sfc = gf0x*preA.x + gf0y*preA.y + gf1x*preB.x + gf1y*preB.y;
        float sd  = gf0x*qA.x   + gf0y*qA.y   + gf1x*qB.x   + gf1y*qB.y;
        float f1x = fc*preB.x*h0j.x, f1y = fc*preB.y*h0j.y;
        float gr0 = gm1[0].x*f1x + gm1[0].y*f1y;
        float gr1 = gm1[1].x*f1x + gm1[1].y*f1y;
        float gr2 = gm1[2].x*f1x + gm1[2].y*f1y;

        sfc = warpRed(sfc);
        sd  = warpRed(sd);
        gr0 = warpRed(gr0);
        gr1 = warpRed(gr1);
        gr2 = warpRed(gr2);

        float dfc = -0.5f*(PI_F/RCUT)*__sinf(PI_F*d/RCUT);
        float gd  = fc*sd + sfc*dfc;
        float gdr = gr0*rh[0] + gr1*rh[1] + gr2*rh[2];
        float invd = 1.0f/d;
        if(lane < 3){
            float gx = (lane==0) ? gr0 : ((lane==1) ? gr1 : gr2);
            float rx = rh[lane];
            float grij = (gx - gdr*rx)*invd + gd*rx;
            fi += grij;
            atomicAdd(&F[j*3+lane], -grij);
        }
    }
    if(lane < 3) atomicAdd(&F[curi*3+lane], fi);
}

// ---------------- backward layer-1 (j-sorted; paths {0,2}) -----------------
__global__ __launch_bounds__(128) void edge_bwd1_k(
    const float* __restrict__ Wr_l, const float* __restrict__ br_l,
    const float* __restrict__ h0,   const float* __restrict__ h1,
    const float* __restrict__ gM0,
    float* __restrict__ gh0, float* __restrict__ gh1, float* __restrict__ F)
{
    int tid = threadIdx.x;
    int cnt = g_cnt;
    int e0 = (blockIdx.x*4 + (tid>>5))*8;
    if(e0 >= cnt) return;
    int lane = tid & 31;
    int c = 2*lane;
    int eend = min(e0 + 8, cnt);

    float2 WA[NBF], WB[NBF];
    const float2* wa = (const float2*)Wr_l;
    const float2* wb = (const float2*)Wr_l + 1024;   // path 2
#pragma unroll
    for(int b=0;b<NBF;b++){ WA[b] = wa[b*32+lane]; WB[b] = wb[b*32+lane]; }
    float2 bA = ((const float2*)br_l)[lane];
    float2 bB = ((const float2*)br_l)[64+lane];

    int curj = g_Jij[e0].y;
    float2 h0j = *(const float2*)&h0[curj*64+c];
    float2 v[3];
#pragma unroll
    for(int x=0;x<3;x++) v[x] = *(const float2*)&h1[(curj*3+x)*64+c];
    float2 acc0 = make_float2(0,0);
    float2 acc1[3] = {{0,0},{0,0},{0,0}};
    float fj = 0.f;

    for(int e=e0;e<eend;e++){
        int2 ij = g_Jij[e];
        if(ij.y != curj){
            red2(&gh0[curj*64+c], acc0.x, acc0.y);
#pragma unroll
            for(int x=0;x<3;x++) red2(&gh1[(curj*3+x)*64+c], acc1[x].x, acc1[x].y);
            if(lane < 3) atomicAdd(&F[curj*3+lane], fj);
            acc0 = make_float2(0,0);
#pragma unroll
            for(int x=0;x<3;x++) acc1[x] = make_float2(0,0);
            fj = 0.f;
            curj = ij.y;
            h0j = *(const float2*)&h0[curj*64+c];
#pragma unroll
            for(int x=0;x<3;x++) v[x] = *(const float2*)&h1[(curj*3+x)*64+c];
        }
        int i = ij.x;
        float4 m = g_Jm[e];
        float d = m.x;
        float rh[3] = {m.y, m.z, m.w};
        float fc = 0.5f*(__cosf(PI_F*d/RCUT) + 1.0f);
        float rb = 0.f, wbv = 0.f;
        if(lane < NBF){
            float zz = (d - lane*CSP)/WIDTH;
            rb = __expf(-zz*zz);
            wbv = rb * (-2.0f*zz/WIDTH);
        }
        float2 preA = bA, preB = bB;
        float2 qA = make_float2(0,0), qB = make_float2(0,0);
#pragma unroll
        for(int b=0;b<NBF;b++){
            float r = __shfl_sync(FULLMASK, rb, b);
            float w = __shfl_sync(FULLMASK, wbv, b);
            preA.x = fmaf(r, WA[b].x, preA.x); preA.y = fmaf(r, WA[b].y, preA.y);
            preB.x = fmaf(r, WB[b].x, preB.x); preB.y = fmaf(r, WB[b].y, preB.y);
            qA.x = fmaf(w, WA[b].x, qA.x); qA.y = fmaf(w, WA[b].y, qA.y);
            qB.x = fmaf(w, WB[b].x, qB.x); qB.y = fmaf(w, WB[b].y, qB.y);
        }
        float2 gm0 = *(const float2*)&gM0[i*64+c];
        float tx = v[0].x*rh[0] + v[1].x*rh[1] + v[2].x*rh[2];
        float ty = v[0].y*rh[0] + v[1].y*rh[1] + v[2].y*rh[2];

        float gf0x = gm0.x*h0j.x, gf0y = gm0.y*h0j.y;
        float gf2x = gm0.x*tx,    gf2y = gm0.y*ty;
        float sfc = gf0x*preA.x + gf0y*preA.y + gf2x*preB.x + gf2y*preB.y;
        float sd  = gf0x*qA.x   + gf0y*qA.y   + gf2x*qB.x   + gf2y*qB.y;
        float f2x = fc*preB.x*gm0.x, f2y = fc*preB.y*gm0.y;
        float gr0 = f2x*v[0].x + f2y*v[0].y;
        float gr1 = f2x*v[1].x + f2y*v[1].y;
        float gr2 = f2x*v[2].x + f2y*v[2].y;

        acc0.x += gm0.x*fc*preA.x;
        acc0.y += gm0.y*fc*preA.y;
#pragma unroll
        for(int x=0;x<3;x++){
            acc1[x].x += f2x*rh[x];
            acc1[x].y += f2y*rh[x];
        }

        sfc = warpRed(sfc);
        sd  = warpRed(sd);
        gr0 = warpRed(gr0);
        gr1 = warpRed(gr1);
        gr2 = warpRed(gr2);

        float dfc = -0.5f*(PI_F/RCUT)*__sinf(PI_F*d/RCUT);
        float gd  = fc*sd + sfc*dfc;
        float gdr = gr0*rh[0] + gr1*rh[1] + gr2*rh[2];
        float invd = 1.0f/d;
        if(lane < 3){
            float gx = (lane==0) ? gr0 : ((lane==1) ? gr1 : gr2);
            float rx = rh[lane];
            float grij = (gx - gdr*rx)*invd + gd*rx;
            atomicAdd(&F[i*3+lane], grij);
            fj -= grij;
        }
    }
    red2(&gh0[curj*64+c], acc0.x, acc0.y);
#pragma unroll
    for(int x=0;x<3;x++) red2(&gh1[(curj*3+x)*64+c], acc1[x].x, acc1[x].y);
    if(lane < 3) atomicAdd(&F[curj*3+lane], fj);
}

// ---------------- node GEMM: out = epilogue(A@W1 [+ B@W2] [+ bias]) --------
__global__ __launch_bounds__(256) void mm_fwd(
    const float* __restrict__ A, const float* __restrict__ W1,
    const float* __restrict__ B, const float* __restrict__ W2,
    const float* __restrict__ bias, const float* __restrict__ ro2,
    float* __restrict__ out, float* __restrict__ sOut, int rows)
{
    __shared__ float sW[64*64];
    __shared__ float sX[128*64];
    int tid = threadIdx.x;
    int row0 = blockIdx.x*128;
    int tc = tid & 15, tr = tid >> 4;
    float acc[8][4];
    if(bias){
        float4 b = *(const float4*)&bias[4*tc];
#pragma unroll
        for(int i=0;i<8;i++){ acc[i][0]=b.x; acc[i][1]=b.y; acc[i][2]=b.z; acc[i][3]=b.w; }
    } else {
#pragma unroll
        for(int i=0;i<8;i++){ acc[i][0]=acc[i][1]=acc[i][2]=acc[i][3]=0.f; }
    }
    int nph = B ? 2 : 1;
    for(int ph=0; ph<nph; ph++){
        const float* Xp = ph ? B : A;
        const float* Wp = ph ? W2 : W1;
        if(ph) __syncthreads();
        for(int k=tid;k<4096;k+=256) sW[k] = Wp[k];
        for(int k=tid;k<8192;k+=256){
            int r = k>>6, c = k&63;
            int gr = row0 + r;
            sX[k] = (gr < rows) ? Xp[gr*64+c] : 0.f;
        }
        __syncthreads();
        const float* xr = &sX[(tr*8)*64];
#pragma unroll 4
        for(int k=0;k<64;k++){
            float4 w = *(const float4*)&sW[k*64 + tc*4];
            float a[8];
#pragma unroll
            for(int i=0;i<8;i++) a[i] = xr[i*64+k];
#pragma unroll
            for(int i=0;i<8;i++){
                acc[i][0]=fmaf(a[i],w.x,acc[i][0]);
                acc[i][1]=fmaf(a[i],w.y,acc[i][1]);
                acc[i][2]=fmaf(a[i],w.z,acc[i][2]);
                acc[i][3]=fmaf(a[i],w.w,acc[i][3]);
            }
        }
    }
    float4 ro2v = make_float4(0,0,0,0);
    if(ro2) ro2v = *(const float4*)&ro2[4*tc];
#pragma unroll
    for(int i=0;i<8;i++){
        int r = row0 + tr*8 + i;
        if(r >= rows) continue;
        float4 o;
        float* oo = &o.x;
#pragma unroll
        for(int jj=0;jj<4;jj++){
            float u = acc[i][jj];
            float val;
            if(ro2){
                float sig = 1.f/(1.f + expf(-u));
                float rr = (&ro2v.x)[jj];
                val = rr*sig*fmaf(u, 1.f-sig, 1.f);
            } else if(sOut){
                float sig = 1.f/(1.f + expf(-u));
                val = u*sig;
            } else {
                val = u;
            }
            oo[jj] = val;
        }
        if(sOut){
            float4 so = make_float4(acc[i][0],acc[i][1],acc[i][2],acc[i][3]);
            *(float4*)&sOut[r*64 + tc*4] = so;
        }
        *(float4*)&out[r*64 + tc*4] = o;
    }
}

// ---------------- node GEMM transposed with fused dsilu --------------------
__global__ __launch_bounds__(256) void mm_bwdT(
    const float* __restrict__ G, const float* __restrict__ S,
    const float* __restrict__ W1, const float* __restrict__ W2,
    float* __restrict__ out1, float* __restrict__ out2, int rows)
{
    __shared__ float sWt[64*68];
    __shared__ float sG[64*65];
    int tid = threadIdx.x;
    int row0 = blockIdx.x*64;
    int tc = tid & 15, tr = tid >> 4;
    for(int k=tid;k<4096;k+=256){
        int r = k>>6, c = k&63;
        int gr = row0 + r;
        float v = 0.f;
        if(gr < rows){
            float g = G[gr*64+c];
            if(S){
                float x = S[gr*64+c];
                float sig = 1.f/(1.f + expf(-x));
                v = g*sig*fmaf(x, 1.f-sig, 1.f);
            } else v = g;
        }
        sG[r*65+c] = v;
    }
    int nph = out2 ? 2 : 1;
    for(int ph=0; ph<nph; ph++){
        const float* Wp = ph ? W2 : W1;
        float* op = ph ? out2 : out1;
        if(ph) __syncthreads();
        for(int k=tid;k<4096;k+=256){
            int cout = k>>6, dd = k&63;
            sWt[dd*68+cout] = Wp[k];
        }
        __syncthreads();
        float acc[4][4];
#pragma unroll
        for(int i=0;i<4;i++){ acc[i][0]=acc[i][1]=acc[i][2]=acc[i][3]=0.f; }
        const float* xr = &sG[(tr*4)*65];
#pragma unroll 8
        for(int k=0;k<64;k++){
            float a0 = xr[k], a1 = xr[65+k], a2 = xr[130+k], a3 = xr[195+k];
            float4 w = *(const float4*)&sWt[k*68 + tc*4];
            acc[0][0]=fmaf(a0,w.x,acc[0][0]); acc[0][1]=fmaf(a0,w.y,acc[0][1]);
            acc[0][2]=fmaf(a0,w.z,acc[0][2]); acc[0][3]=fmaf(a0,w.w,acc[0][3]);
            acc[1][0]=fmaf(a1,w.x,acc[1][0]); acc[1][1]=fmaf(a1,w.y,acc[1][1]);
            acc[1][2]=fmaf(a1,w.z,acc[1][2]); acc[1][3]=fmaf(a1,w.w,acc[1][3]);
            acc[2][0]=fmaf(a2,w.x,acc[2][0]); acc[2][1]=fmaf(a2,w.y,acc[2][1]);
            acc[2][2]=fmaf(a2,w.z,acc[2][2]); acc[2][3]=fmaf(a2,w.w,acc[2][3]);
            acc[3][0]=fmaf(a3,w.x,acc[3][0]); acc[3][1]=fmaf(a3,w.y,acc[3][1]);
            acc[3][2]=fmaf(a3,w.z,acc[3][2]); acc[3][3]=fmaf(a3,w.w,acc[3][3]);
        }
#pragma unroll
        for(int i=0;i<4;i++){
            int r = row0 + tr*4 + i;
            if(r >= rows) continue;
            float4 o = make_float4(acc[i][0],acc[i][1],acc[i][2],acc[i][3]);
            *(float4*)&op[r*64 + tc*4] = o;
        }
    }
}

// ---------------- fused readout backward -----------------------------------
__global__ __launch_bounds__(256) void readout_k(
    const float* __restrict__ A, const float* __restrict__ Wro1,
    const float* __restrict__ bro1, const float* __restrict__ Wro2,
    float* __restrict__ gA, int rows)
{
    __shared__ float sW[64*68];
    __shared__ float sX[64*65];
    int tid = threadIdx.x;
    int row0 = blockIdx.x*64;
    int tc = tid & 15, tr = tid >> 4;
    for(int k=tid;k<4096;k+=256) sW[k] = Wro1[k];
    for(int k=tid;k<4096;k+=256){
        int r = k>>6, c = k&63;
        int gr = row0 + r;
        sX[r*65+c] = (gr < rows) ? A[gr*64+c] : 0.f;
    }
    __syncthreads();
    float acc[4][4];
    {
        float4 b = *(const float4*)&bro1[4*tc];
#pragma unroll
        for(int i=0;i<4;i++){ acc[i][0]=b.x; acc[i][1]=b.y; acc[i][2]=b.z; acc[i][3]=b.w; }
    }
    {
        const float* xr = &sX[(tr*4)*65];
#pragma unroll 8
        for(int k=0;k<64;k++){
            float a0 = xr[k], a1 = xr[65+k], a2 = xr[130+k], a3 = xr[195+k];
            float4 w = *(const float4*)&sW[k*64 + tc*4];
            acc[0][0]=fmaf(a0,w.x,acc[0][0]); acc[0][1]=fmaf(a0,w.y,acc[0][1]);
            acc[0][2]=fmaf(a0,w.z,acc[0][2]); acc[0][3]=fmaf(a0,w.w,acc[0][3]);
            acc[1][0]=fmaf(a1,w.x,acc[1][0]); acc[1][1]=fmaf(a1,w.y,acc[1][1]);
            acc[1][2]=fmaf(a1,w.z,acc[1][2]); acc[1][3]=fmaf(a1,w.w,acc[1][3]);
            acc[2][0]=fmaf(a2,w.x,acc[2][0]); acc[2][1]=fmaf(a2,w.y,acc[2][1]);
            acc[2][2]=fmaf(a2,w.z,acc[2][2]); acc[2][3]=fmaf(a2,w.w,acc[2][3]);
            acc[3][0]=fmaf(a3,w.x,acc[3][0]); acc[3][1]=fmaf(a3,w.y,acc[3][1]);
            acc[3][2]=fmaf(a3,w.z,acc[3][2]); acc[3][3]=fmaf(a3,w.w,acc[3][3]);
        }
    }
    __syncthreads();
    {
        float4 ro2v = *(const float4*)&Wro2[4*tc];
#pragma unroll
        for(int i=0;i<4;i++){
#pragma unroll
            for(int jj=0;jj<4;jj++){
                float u = acc[i][jj];
                float sig = 1.f/(1.f + expf(-u));
                float w = (&ro2v.x)[jj]*sig*fmaf(u, 1.f-sig, 1.f);
                sX[(tr*4+i)*65 + tc*4 + jj] = w;
            }
        }
    }
    for(int k=tid;k<4096;k+=256){
        int cout = k>>6, dd = k&63;
        sW[dd*68+cout] = Wro1[k];
    }
    __syncthreads();
    float acc2[4][4];
#pragma unroll
    for(int i=0;i<4;i++){ acc2[i][0]=acc2[i][1]=acc2[i][2]=acc2[i][3]=0.f; }
    {
        const float* xr = &sX[(tr*4)*65];
#pragma unroll 8
        for(int k=0;k<64;k++){
            float a0 = xr[k], a1 = xr[65+k], a2 = xr[130+k], a3 = xr[195+k];
            float4 w = *(const float4*)&sW[k*68 + tc*4];
            acc2[0][0]=fmaf(a0,w.x,acc2[0][0]); acc2[0][1]=fmaf(a0,w.y,acc2[0][1]);
            acc2[0][2]=fmaf(a0,w.z,acc2[0][2]); acc2[0][3]=fmaf(a0,w.w,acc2[0][3]);
            acc2[1][0]=fmaf(a1,w.x,acc2[1][0]); acc2[1][1]=fmaf(a1,w.y,acc2[1][1]);
            acc2[1][2]=fmaf(a1,w.z,acc2[1][2]); acc2[1][3]=fmaf(a1,w.w,acc2[1][3]);
            acc2[2][0]=fmaf(a2,w.x,acc2[2][0]); acc2[2][1]=fmaf(a2,w.y,acc2[2][1]);
            acc2[2][2]=fmaf(a2,w.z,acc2[2][2]); acc2[2][3]=fmaf(a2,w.w,acc2[2][3]);
            acc2[3][0]=fmaf(a3,w.x,acc2[3][0]); acc2[3][1]=fmaf(a3,w.y,acc2[3][1]);
            acc2[3][2]=fmaf(a3,w.z,acc2[3][2]); acc2[3][3]=fmaf(a3,w.w,acc2[3][3]);
        }
    }
#pragma unroll
    for(int i=0;i<4;i++){
        int r = row0 + tr*4 + i;
        if(r >= rows) continue;
        float4 o = make_float4(acc2[i][0],acc2[i][1],acc2[i][2],acc2[i][3]);
        *(float4*)&gA[r*64 + tc*4] = o;
    }
}

// ---------------- host orchestration ---------------------------------------
extern "C" void kernel_launch(void* const* d_in, const int* in_sizes, int n_in,
                              void* d_out, int out_size)
{
    const float* coord  = (const float*)d_in[0];
    const float* emb    = (const float*)d_in[1];
    const float* Wr     = (const float*)d_in[2];
    const float* br     = (const float*)d_in[3];
    const float* Wself0 = (const float*)d_in[4];
    const float* Wmsg0  = (const float*)d_in[5];
    const float* b0     = (const float*)d_in[6];
    const float* Wmsg1  = (const float*)d_in[7];
    const float* Wro1   = (const float*)d_in[9];
    const float* bro1   = (const float*)d_in[10];
    const float* Wro2   = (const float*)d_in[11];
    const int*   z      = (const int*)d_in[13];
    const int*   ei     = (const int*)d_in[14];
    const int*   ej     = (const int*)d_in[15];
    float* F = (float*)d_out;
    (void)in_sizes; (void)n_in; (void)out_size;

    static cudaStream_t sSide = nullptr;
    static cudaEvent_t ev1 = nullptr, ev2 = nullptr, ev5 = nullptr, ev6 = nullptr;
    if(!sSide){
        cudaStreamCreateWithFlags(&sSide, cudaStreamNonBlocking);
        cudaEventCreateWithFlags(&ev1, cudaEventDisableTiming);
        cudaEventCreateWithFlags(&ev2, cudaEventDisableTiming);
        cudaEventCreateWithFlags(&ev5, cudaEventDisableTiming);
        cudaEventCreateWithFlags(&ev6, cudaEventDisableTiming);
    }

    float *h0a,*h0b,*h0c,*s0,*s1,*h1b,*Mbuf,*gM0p,*gM1p,*gA,*gB,*gh1;
    cudaGetSymbolAddress((void**)&h0a, g_h0a);
    cudaGetSymbolAddress((void**)&h0b, g_h0b);
    cudaGetSymbolAddress((void**)&h0c, g_h0c);
    cudaGetSymbolAddress((void**)&s0,  g_s0);
    cudaGetSymbolAddress((void**)&s1,  g_s1);
    cudaGetSymbolAddress((void**)&h1b, g_h1b);
    cudaGetSymbolAddress((void**)&Mbuf,g_M);
    cudaGetSymbolAddress((void**)&gM0p,g_gM0);
    cudaGetSymbolAddress((void**)&gM1p,g_gM1);
    cudaGetSymbolAddress((void**)&gA,  g_gA);
    cudaGetSymbolAddress((void**)&gB,  g_gB);
    cudaGetSymbolAddress((void**)&gh1, g_gh1);
    float* M0 = Mbuf;
    float* M1 = Mbuf + NN*CC;

    const int EB  = (EE + 31)/32;       // 4 warps x 8 edges per 128-thread block
    const int G1  = (NN + 127)/128;
    const int G3  = (3*NN + 127)/128;
    const int T1  = (NN + 63)/64;
    const int T3  = (3*NN + 63)/64;

    // #1..#5 (ncu -s 5 skips these; #6 = edge_fwd0_k gets profiled)
    cudaMemsetAsync(F, 0, NN*3*sizeof(float));                  // #1
    embed_zero_k<<<1024, 256>>>(emb, z);                        // #2 h0a fill + M zero
    geomA_k<<<(EE+255)/256, 256>>>(coord, ei, ej);              // #3 (hist zeroed by prev scan / static init)
    scan_k<<<1, 1024>>>();                                      // #4 (re-zeroes hist)
    geomB_k<<<(EE+255)/256, 256>>>(coord, ei, ej);              // #5

    // ---- layer 0 forward
    edge_fwd0_k<<<EB, 128>>>(Wr, br, h0a);                      // #6 (profiled)
    cudaEventRecord(ev1, 0);
    // side stream: h1b GEMM (3NN rows) + gh1 zero, concurrent with h0b GEMM
    cudaStreamWaitEvent(sSide, ev1, 0);
    mm_fwd<<<G3, 256, 0, sSide>>>(M1, Wmsg1, nullptr, nullptr, nullptr, nullptr, h1b, nullptr, 3*NN);
    cudaMemsetAsync(gh1, 0, NN*3*CC*sizeof(float), sSide);
    cudaEventRecord(ev2, sSide);

    mm_fwd<<<G1, 256>>>(M0, Wmsg0, h0a, Wself0, b0, nullptr, h0b, s0, NN);
    cudaMemsetAsync(M0, 0, NN*CC*sizeof(float));

    // ---- layer 1 forward (M1/h1 outputs dead)
    cudaStreamWaitEvent(0, ev2, 0);
    edge_fwd1_k<<<EB, 128>>>(Wr + 4096, br + 256, h0b, h1b);
    mm_fwd<<<G1, 256>>>(M0, Wmsg0 + 4096, h0b, Wself0 + 4096, b0 + 64, nullptr, h0c, s1, NN);

    // ---- readout backward (fused)
    readout_k<<<T1, 256>>>(h0c, Wro1, bro1, Wro2, gA, NN);

    // ---- layer 1 backward (j-sorted scatter)
    mm_bwdT<<<T1, 256>>>(gA, s1, Wmsg0 + 4096, Wself0 + 4096, gM0p, gB, NN);
    edge_bwd1_k<<<EB, 128>>>(Wr + 4096, br + 256, h0b, h1b, gM0p, gB, gh1, F);
    cudaEventRecord(ev5, 0);

    // side stream: gM1 GEMM (3NN rows) concurrent with gM0 GEMM
    cudaStreamWaitEvent(sSide, ev5, 0);
    mm_bwdT<<<T3, 256, 0, sSide>>>(gh1, nullptr, Wmsg1, nullptr, gM1p, nullptr, 3*NN);
    cudaEventRecord(ev6, sSide);

    // ---- layer 0 backward (i-sorted)
    mm_bwdT<<<T1, 256>>>(gB, s0, Wmsg0, nullptr, gM0p, nullptr, NN);
    cudaStreamWaitEvent(0, ev6, 0);
    edge_bwd0_k<<<EB, 128>>>(Wr, br, h0a, gM0p, gM1p, F);
}

// round 6
// speedup vs baseline: 1.0359x; 1.0359x over previous
#include <cuda_runtime.h>
#include <math.h>

#define NN   20000
#define EE   320000
#define CC   64
#define NBF  16
#define RCUT 5.0f
#define CSP  (RCUT/(NBF-1))
#define WIDTH (RCUT/NBF)
#define PI_F 3.14159265358979f
#define FULLMASK 0xffffffffu
#define EPW  16                      // edges per warp
#define EPB  (4*EPW)                 // edges per 128-thread block

// ---------------- device scratch ------------------------------------------
static __device__ int   g_cnt;
static __device__ int   g_hist[2*NN];     // statically zero; re-zeroed by scan_k
static __device__ int   g_cur[2*NN];
static __device__ __align__(16) int2   g_Iij[EE];
static __device__ __align__(16) float4 g_Im[EE];
static __device__ __align__(16) int2   g_Jij[EE];
static __device__ __align__(16) float4 g_Jm[EE];

static __device__ __align__(16) float g_h0a[NN*CC];
static __device__ __align__(16) float g_h0b[NN*CC];
static __device__ __align__(16) float g_h0c[NN*CC];
static __device__ __align__(16) float g_s0[NN*CC];
static __device__ __align__(16) float g_s1[NN*CC];
static __device__ __align__(16) float g_h1b[NN*3*CC];
static __device__ __align__(16) float g_M[NN*CC*4];      // M0 | M1
static __device__ __align__(16) float g_gM0[NN*CC];
static __device__ __align__(16) float g_gM1[NN*3*CC];
static __device__ __align__(16) float g_gA[NN*CC];
static __device__ __align__(16) float g_gB[NN*CC];
static __device__ __align__(16) float g_gh1[NN*3*CC];

__device__ __forceinline__ float warpRed(float v){
#pragma unroll
    for(int o=16;o>0;o>>=1) v += __shfl_xor_sync(FULLMASK, v, o);
    return v;
}

__device__ __forceinline__ void red2(float* addr, float a, float b){
    asm volatile("red.global.add.v2.f32 [%0], {%1, %2};"
                 :: "l"(addr), "f"(a), "f"(b) : "memory");
}

// ---------------- embedding gather + M zero + F zero (fused) ---------------
__global__ void embed_zero_k(const float* __restrict__ emb, const int* __restrict__ z,
                             float* __restrict__ F)
{
    const int NH = NN*16;          // h0a in float4
    const int NM = NN*64;          // M buffer in float4
    const int NF = NN*3;           // F in floats (not float4-aligned guaranteed? d_out is 16B-aligned; NN*3=60000 floats)
    for(int idx = blockIdx.x*blockDim.x + threadIdx.x; idx < NH + NM;
        idx += gridDim.x*blockDim.x){
        if(idx < NH){
            int n = idx >> 4, q = idx & 15;
            int zn = __ldg(&z[n]);
            ((float4*)g_h0a)[idx] = ((const float4*)emb)[zn*16 + q];
        } else {
            ((float4*)g_M)[idx - NH] = make_float4(0.f,0.f,0.f,0.f);
        }
    }
    for(int idx = blockIdx.x*blockDim.x + threadIdx.x; idx < NF;
        idx += gridDim.x*blockDim.x) F[idx] = 0.f;
}

// ---------------- geometry pass 1: histograms ------------------------------
__global__ void geomA_k(const float* __restrict__ coord,
                        const int* __restrict__ ei, const int* __restrict__ ej)
{
    int e = blockIdx.x*blockDim.x + threadIdx.x;
    if(e >= EE) return;
    int i = ei[e], j = ej[e];
    float dx = coord[j*3+0] - coord[i*3+0];
    float dy = coord[j*3+1] - coord[i*3+1];
    float dz = coord[j*3+2] - coord[i*3+2];
    float d2 = dx*dx + dy*dy + dz*dz + 1e-12f;
    if(d2 < RCUT*RCUT){
        atomicAdd(&g_hist[i], 1);
        atomicAdd(&g_hist[NN+j], 1);
    }
}

// ---------------- exclusive scans; re-zero histogram for next replay -------
__global__ __launch_bounds__(1024) void scan_k()
{
    __shared__ int swarp[32];
    int t = threadIdx.x;
    int lane = t & 31, wid = t >> 5;
    for(int pass=0; pass<2; pass++){
        int* hist = g_hist + pass*NN;
        int* cur = g_cur + pass*NN;
        int base = t*20;
        int local[20];
        int s = 0;
#pragma unroll
        for(int q=0;q<20;q++){
            int idx = base + q;
            int v = (idx < NN) ? hist[idx] : 0;
            local[q] = s; s += v;
            if(idx < NN) hist[idx] = 0;
        }
        int inc = s;
#pragma unroll
        for(int o=1;o<32;o<<=1){
            int n = __shfl_up_sync(FULLMASK, inc, o);
            if(lane >= o) inc += n;
        }
        if(lane == 31) swarp[wid] = inc;
        __syncthreads();
        if(wid == 0){
            int v = swarp[lane];
#pragma unroll
            for(int o=1;o<32;o<<=1){
                int n = __shfl_up_sync(FULLMASK, v, o);
                if(lane >= o) v += n;
            }
            swarp[lane] = v;
        }
        __syncthreads();
        int offset = inc - s + ((wid > 0) ? swarp[wid-1] : 0);
#pragma unroll
        for(int q=0;q<20;q++){
            int idx = base + q;
            if(idx < NN) cur[idx] = offset + local[q];
        }
        if(pass == 0 && t == 1023) g_cnt = offset + s;
        __syncthreads();
    }
}

// ---------------- geometry pass 2: write both sorted orders ----------------
__global__ void geomB_k(const float* __restrict__ coord,
                        const int* __restrict__ ei, const int* __restrict__ ej)
{
    int e = blockIdx.x*blockDim.x + threadIdx.x;
    if(e >= EE) return;
    int i = ei[e], j = ej[e];
    float dx = coord[j*3+0] - coord[i*3+0];
    float dy = coord[j*3+1] - coord[i*3+1];
    float dz = coord[j*3+2] - coord[i*3+2];
    float d2 = dx*dx + dy*dy + dz*dz + 1e-12f;
    if(d2 >= RCUT*RCUT) return;
    float d = sqrtf(d2);
    float inv = 1.0f/d;
    float4 m = make_float4(d, dx*inv, dy*inv, dz*inv);
    int2 ij = make_int2(i, j);
    int posI = atomicAdd(&g_cur[i], 1);
    g_Iij[posI] = ij;  g_Im[posI] = m;
    int posJ = atomicAdd(&g_cur[NN+j], 1);
    g_Jij[posJ] = ij;  g_Jm[posJ] = m;
}

// ---------------- forward layer-0 edge kernel (i-sorted; paths {0,1}) ------
__global__ __launch_bounds__(128) void edge_fwd0_k(
    const float* __restrict__ Wr_l, const float* __restrict__ br_l,
    const float* __restrict__ h0)
{
    int tid = threadIdx.x;
    int cnt = g_cnt;
    int e0 = (blockIdx.x*4 + (tid>>5))*EPW;
    if(e0 >= cnt) return;
    int lane = tid & 31;
    int c = 2*lane;
    int eend = min(e0 + EPW, cnt);

    float2 WA[NBF], WB[NBF];
    const float2* wa = (const float2*)Wr_l;          // path 0
    const float2* wb = (const float2*)Wr_l + 512;    // path 1
#pragma unroll
    for(int b=0;b<NBF;b++){ WA[b] = wa[b*32+lane]; WB[b] = wb[b*32+lane]; }
    float2 bA = ((const float2*)br_l)[lane];
    float2 bB = ((const float2*)br_l)[32+lane];

    float* M0 = g_M;
    float* M1 = g_M + NN*CC;

    float2 a0c = make_float2(0.f,0.f);
    float2 a1c[3] = {{0,0},{0,0},{0,0}};

    // prefetch edge e0
    int2   ijn = g_Iij[e0];
    float4 mn  = g_Im[e0];
    float2 hn  = *(const float2*)&h0[ijn.y*64+c];
    int curi = ijn.x;

    for(int e=e0;e<eend;e++){
        int2 ij = ijn; float4 m = mn; float2 h0j = hn;
        if(e+1 < eend){
            ijn = g_Iij[e+1];
            mn  = g_Im[e+1];
            hn  = *(const float2*)&h0[ijn.y*64+c];
        }
        if(ij.x != curi){
            red2(&M0[curi*64+c], a0c.x, a0c.y);
#pragma unroll
            for(int x=0;x<3;x++) red2(&M1[(curi*3+x)*64+c], a1c[x].x, a1c[x].y);
            a0c = make_float2(0.f,0.f);
#pragma unroll
            for(int x=0;x<3;x++) a1c[x] = make_float2(0.f,0.f);
            curi = ij.x;
        }
        float d = m.x;
        float rh[3] = {m.y, m.z, m.w};
        float fc = 0.5f*(__cosf(PI_F*d/RCUT) + 1.0f);
        float rb = 0.f;
        if(lane < NBF){
            float zz = (d - lane*CSP)/WIDTH;
            rb = __expf(-zz*zz);
        }
        float2 p0 = bA, p1 = bB;
#pragma unroll
        for(int b=0;b<NBF;b++){
            float r = __shfl_sync(FULLMASK, rb, b);
            p0.x = fmaf(r, WA[b].x, p0.x); p0.y = fmaf(r, WA[b].y, p0.y);
            p1.x = fmaf(r, WB[b].x, p1.x); p1.y = fmaf(r, WB[b].y, p1.y);
        }
        a0c.x = fmaf(fc*p0.x, h0j.x, a0c.x);
        a0c.y = fmaf(fc*p0.y, h0j.y, a0c.y);
        float g1x = fc*p1.x*h0j.x, g1y = fc*p1.y*h0j.y;
#pragma unroll
        for(int x=0;x<3;x++){
            a1c[x].x = fmaf(g1x, rh[x], a1c[x].x);
            a1c[x].y = fmaf(g1y, rh[x], a1c[x].y);
        }
    }
    red2(&M0[curi*64+c], a0c.x, a0c.y);
#pragma unroll
    for(int x=0;x<3;x++) red2(&M1[(curi*3+x)*64+c], a1c[x].x, a1c[x].y);
}

// ---------------- forward layer-1 edge kernel (i-sorted; paths {0,2}) ------
__global__ __launch_bounds__(128) void edge_fwd1_k(
    const float* __restrict__ Wr_l, const float* __restrict__ br_l,
    const float* __restrict__ h0,   const float* __restrict__ h1)
{
    int tid = threadIdx.x;
    int cnt = g_cnt;
    int e0 = (blockIdx.x*4 + (tid>>5))*EPW;
    if(e0 >= cnt) return;
    int lane = tid & 31;
    int c = 2*lane;
    int eend = min(e0 + EPW, cnt);

    float2 WA[NBF], WB[NBF];
    const float2* wa = (const float2*)Wr_l;           // path 0
    const float2* wb = (const float2*)Wr_l + 1024;    // path 2
#pragma unroll
    for(int b=0;b<NBF;b++){ WA[b] = wa[b*32+lane]; WB[b] = wb[b*32+lane]; }
    float2 bA = ((const float2*)br_l)[lane];
    float2 bB = ((const float2*)br_l)[64+lane];

    float* M0 = g_M;
    float2 a0c = make_float2(0.f,0.f);

    int2   ijn = g_Iij[e0];
    float4 mn  = g_Im[e0];
    float2 hn  = *(const float2*)&h0[ijn.y*64+c];
    float2 vn0 = *(const float2*)&h1[(ijn.y*3+0)*64+c];
    float2 vn1 = *(const float2*)&h1[(ijn.y*3+1)*64+c];
    float2 vn2 = *(const float2*)&h1[(ijn.y*3+2)*64+c];
    int curi = ijn.x;

    for(int e=e0;e<eend;e++){
        int2 ij = ijn; float4 m = mn; float2 h0j = hn;
        float2 v0 = vn0, v1 = vn1, v2 = vn2;
        if(e+1 < eend){
            ijn = g_Iij[e+1];
            mn  = g_Im[e+1];
            hn  = *(const float2*)&h0[ijn.y*64+c];
            vn0 = *(const float2*)&h1[(ijn.y*3+0)*64+c];
            vn1 = *(const float2*)&h1[(ijn.y*3+1)*64+c];
            vn2 = *(const float2*)&h1[(ijn.y*3+2)*64+c];
        }
        if(ij.x != curi){
            red2(&M0[curi*64+c], a0c.x, a0c.y);
            a0c = make_float2(0.f,0.f);
            curi = ij.x;
        }
        float d = m.x;
        float rh[3] = {m.y, m.z, m.w};
        float fc = 0.5f*(__cosf(PI_F*d/RCUT) + 1.0f);
        float rb = 0.f;
        if(lane < NBF){
            float zz = (d - lane*CSP)/WIDTH;
            rb = __expf(-zz*zz);
        }
        float2 p0 = bA, p2 = bB;
#pragma unroll
        for(int b=0;b<NBF;b++){
            float r = __shfl_sync(FULLMASK, rb, b);
            p0.x = fmaf(r, WA[b].x, p0.x); p0.y = fmaf(r, WA[b].y, p0.y);
            p2.x = fmaf(r, WB[b].x, p2.x); p2.y = fmaf(r, WB[b].y, p2.y);
        }
        float tx = v0.x*rh[0] + v1.x*rh[1] + v2.x*rh[2];
        float ty = v0.y*rh[0] + v1.y*rh[1] + v2.y*rh[2];
        a0c.x += fc*(p0.x*h0j.x + p2.x*tx);
        a0c.y += fc*(p0.y*h0j.y + p2.y*ty);
    }
    red2(&M0[curi*64+c], a0c.x, a0c.y);
}

// ---------------- backward layer-0 (i-sorted; paths {0,1}; h1==0) ----------
__global__ __launch_bounds__(128) void edge_bwd0_k(
    const float* __restrict__ Wr_l, const float* __restrict__ br_l,
    const float* __restrict__ h0,
    const float* __restrict__ gM0,  const float* __restrict__ gM1,
    float* __restrict__ F)
{
    int tid = threadIdx.x;
    int cnt = g_cnt;
    int e0 = (blockIdx.x*4 + (tid>>5))*EPW;
    if(e0 >= cnt) return;
    int lane = tid & 31;
    int c = 2*lane;
    int eend = min(e0 + EPW, cnt);

    float2 WA[NBF], WB[NBF];
    const float2* wa = (const float2*)Wr_l;
    const float2* wb = (const float2*)Wr_l + 512;    // path 1
#pragma unroll
    for(int b=0;b<NBF;b++){ WA[b] = wa[b*32+lane]; WB[b] = wb[b*32+lane]; }
    float2 bA = ((const float2*)br_l)[lane];
    float2 bB = ((const float2*)br_l)[32+lane];

    int2   ijn = g_Iij[e0];
    float4 mn  = g_Im[e0];
    float2 hn  = *(const float2*)&h0[ijn.y*64+c];
    int curi = ijn.x;
    float2 gm0 = *(const float2*)&gM0[curi*64+c];
    float2 gm1[3];
#pragma unroll
    for(int x=0;x<3;x++) gm1[x] = *(const float2*)&gM1[(curi*3+x)*64+c];
    float fi = 0.f;

    for(int e=e0;e<eend;e++){
        int2 ij = ijn; float4 m = mn; float2 h0j = hn;
        if(e+1 < eend){
            ijn = g_Iij[e+1];
            mn  = g_Im[e+1];
            hn  = *(const float2*)&h0[ijn.y*64+c];
        }
        if(ij.x != curi){
            if(lane < 3) atomicAdd(&F[curi*3+lane], fi);
            fi = 0.f;
            curi = ij.x;
            gm0 = *(const float2*)&gM0[curi*64+c];
#pragma unroll
            for(int x=0;x<3;x++) gm1[x] = *(const float2*)&gM1[(curi*3+x)*64+c];
        }
        int j = ij.y;
        float d = m.x;
        float rh[3] = {m.y, m.z, m.w};
        float fc = 0.5f*(__cosf(PI_F*d/RCUT) + 1.0f);
        float rb = 0.f, wbv = 0.f;
        if(lane < NBF){
            float zz = (d - lane*CSP)/WIDTH;
            rb = __expf(-zz*zz);
            wbv = rb * (-2.0f*zz/WIDTH);
        }
        float2 preA = bA, preB = bB;
        float2 qA = make_float2(0,0), qB = make_float2(0,0);
#pragma unroll
        for(int b=0;b<NBF;b++){
            float r = __shfl_sync(FULLMASK, rb, b);
            float w = __shfl_sync(FULLMASK, wbv, b);
            preA.x = fmaf(r, WA[b].x, preA.x); preA.y = fmaf(r, WA[b].y, preA.y);
            preB.x = fmaf(r, WB[b].x, preB.x); preB.y = fmaf(r, WB[b].y, preB.y);
            qA.x = fmaf(w, WA[b].x, qA.x); qA.y = fmaf(w, WA[b].y, qA.y);
            qB.x = fmaf(w, WB[b].x, qB.x); qB.y = fmaf(w, WB[b].y, qB.y);
        }
        float gmrx = gm1[0].x*rh[0] + gm1[1].x*rh[1] + gm1[2].x*rh[2];
        float gmry = gm1[0].y*rh[0] + gm1[1].y*rh[1] + gm1[2].y*rh[2];

        float gf0x = gm0.x*h0j.x, gf0y = gm0.y*h0j.y;
        float gf1x = gmrx*h0j.x,  gf1y = gmry*h0j.y;
        float sfc = gf0x*preA.x + gf0y*preA.y + gf1x*preB.x + gf1y*preB.y;
        float sd  = gf0x*qA.x   + gf0y*qA.y   + gf1x*qB.x   + gf1y*qB.y;
        float f1x = fc*preB.x*h0j.x, f1y = fc*preB.y*h0j.y;
        float gr0 = gm1[0].x*f1x + gm1[0].y*f1y;
        float gr1 = gm1[1].x*f1x + gm1[1].y*f1y;
        float gr2 = gm1[2].x*f1x + gm1[2].y*f1y;

        sfc = warpRed(sfc);
        sd  = warpRed(sd);
        gr0 = warpRed(gr0);
        gr1 = warpRed(gr1);
        gr2 = warpRed(gr2);

        float dfc = -0.5f*(PI_F/RCUT)*__sinf(PI_F*d/RCUT);
        float gd  = fc*sd + sfc*dfc;
        float gdr = gr0*rh[0] + gr1*rh[1] + gr2*rh[2];
        float invd = 1.0f/d;
        if(lane < 3){
            float gx = (lane==0) ? gr0 : ((lane==1) ? gr1 : gr2);
            float rx = rh[lane];
            float grij = (gx - gdr*rx)*invd + gd*rx;
            fi += grij;
            atomicAdd(&F[j*3+lane], -grij);
        }
    }
    if(lane < 3) atomicAdd(&F[curi*3+lane], fi);
}

// ---------------- backward layer-1 (j-sorted; paths {0,2}) -----------------
__global__ __launch_bounds__(128) void edge_bwd1_k(
    const float* __restrict__ Wr_l, const float* __restrict__ br_l,
    const float* __restrict__ h0,   const float* __restrict__ h1,
    const float* __restrict__ gM0,
    float* __restrict__ gh0, float* __restrict__ gh1, float* __restrict__ F)
{
    int tid = threadIdx.x;
    int cnt = g_cnt;
    int e0 = (blockIdx.x*4 + (tid>>5))*EPW;
    if(e0 >= cnt) return;
    int lane = tid & 31;
    int c = 2*lane;
    int eend = min(e0 + EPW, cnt);

    float2 WA[NBF], WB[NBF];
    const float2* wa = (const float2*)Wr_l;
    const float2* wb = (const float2*)Wr_l + 1024;   // path 2
#pragma unroll
    for(int b=0;b<NBF;b++){ WA[b] = wa[b*32+lane]; WB[b] = wb[b*32+lane]; }
    float2 bA = ((const float2*)br_l)[lane];
    float2 bB = ((const float2*)br_l)[64+lane];

    int2   ijn = g_Jij[e0];
    float4 mn  = g_Jm[e0];
    float2 gmn = *(const float2*)&gM0[ijn.x*64+c];
    int curj = ijn.y;
    float2 h0j = *(const float2*)&h0[curj*64+c];
    float2 v[3];
#pragma unroll
    for(int x=0;x<3;x++) v[x] = *(const float2*)&h1[(curj*3+x)*64+c];
    float2 acc0 = make_float2(0,0);
    float2 acc1[3] = {{0,0},{0,0},{0,0}};
    float fj = 0.f;

    for(int e=e0;e<eend;e++){
        int2 ij = ijn; float4 m = mn; float2 gm0 = gmn;
        if(e+1 < eend){
            ijn = g_Jij[e+1];
            mn  = g_Jm[e+1];
            gmn = *(const float2*)&gM0[ijn.x*64+c];
        }
        if(ij.y != curj){
            red2(&gh0[curj*64+c], acc0.x, acc0.y);
#pragma unroll
            for(int x=0;x<3;x++) red2(&gh1[(curj*3+x)*64+c], acc1[x].x, acc1[x].y);
            if(lane < 3) atomicAdd(&F[curj*3+lane], fj);
            acc0 = make_float2(0,0);
#pragma unroll
            for(int x=0;x<3;x++) acc1[x] = make_float2(0,0);
            fj = 0.f;
            curj = ij.y;
            h0j = *(const float2*)&h0[curj*64+c];
#pragma unroll
            for(int x=0;x<3;x++) v[x] = *(const float2*)&h1[(curj*3+x)*64+c];
        }
        int i = ij.x;
        float d = m.x;
        float rh[3] = {m.y, m.z, m.w};
        float fc = 0.5f*(__cosf(PI_F*d/RCUT) + 1.0f);
        float rb = 0.f, wbv = 0.f;
        if(lane < NBF){
            float zz = (d - lane*CSP)/WIDTH;
            rb = __expf(-zz*zz);
            wbv = rb * (-2.0f*zz/WIDTH);
        }
        float2 preA = bA, preB = bB;
        float2 qA = make_float2(0,0), qB = make_float2(0,0);
#pragma unroll
        for(int b=0;b<NBF;b++){
            float r = __shfl_sync(FULLMASK, rb, b);
            float w = __shfl_sync(FULLMASK, wbv, b);
            preA.x = fmaf(r, WA[b].x, preA.x); preA.y = fmaf(r, WA[b].y, preA.y);
            preB.x = fmaf(r, WB[b].x, preB.x); preB.y = fmaf(r, WB[b].y, preB.y);
            qA.x = fmaf(w, WA[b].x, qA.x); qA.y = fmaf(w, WA[b].y, qA.y);
            qB.x = fmaf(w, WB[b].x, qB.x); qB.y = fmaf(w, WB[b].y, qB.y);
        }
        float tx = v[0].x*rh[0] + v[1].x*rh[1] + v[2].x*rh[2];
        float ty = v[0].y*rh[0] + v[1].y*rh[1] + v[2].y*rh[2];

        float gf0x = gm0.x*h0j.x, gf0y = gm0.y*h0j.y;
        float gf2x = gm0.x*tx,    gf2y = gm0.y*ty;
        float sfc = gf0x*preA.x + gf0y*preA.y + gf2x*preB.x + gf2y*preB.y;
        float sd  = gf0x*qA.x   + gf0y*qA.y   + gf2x*qB.x   + gf2y*qB.y;
        float f2x = fc*preB.x*gm0.x, f2y = fc*preB.y*gm0.y;
        float gr0 = f2x*v[0].x + f2y*v[0].y;
        float gr1 = f2x*v[1].x + f2y*v[1].y;
        float gr2 = f2x*v[2].x + f2y*v[2].y;

        acc0.x += gm0.x*fc*preA.x;
        acc0.y += gm0.y*fc*preA.y;
#pragma unroll
        for(int x=0;x<3;x++){
            acc1[x].x += f2x*rh[x];
            acc1[x].y += f2y*rh[x];
        }

        sfc = warpRed(sfc);
        sd  = warpRed(sd);
        gr0 = warpRed(gr0);
        gr1 = warpRed(gr1);
        gr2 = warpRed(gr2);

        float dfc = -0.5f*(PI_F/RCUT)*__sinf(PI_F*d/RCUT);
        float gd  = fc*sd + sfc*dfc;
        float gdr = gr0*rh[0] + gr1*rh[1] + gr2*rh[2];
        float invd = 1.0f/d;
        if(lane < 3){
            float gx = (lane==0) ? gr0 : ((lane==1) ? gr1 : gr2);
            float rx = rh[lane];
            float grij = (gx - gdr*rx)*invd + gd*rx;
            atomicAdd(&F[i*3+lane], grij);
            fj -= grij;
        }
    }
    red2(&gh0[curj*64+c], acc0.x, acc0.y);
#pragma unroll
    for(int x=0;x<3;x++) red2(&gh1[(curj*3+x)*64+c], acc1[x].x, acc1[x].y);
    if(lane < 3) atomicAdd(&F[curj*3+lane], fj);
}

// ---------------- node GEMM: out = epilogue(A@W1 [+ B@W2] [+ bias]) --------
__global__ __launch_bounds__(256) void mm_fwd(
    const float* __restrict__ A, const float* __restrict__ W1,
    const float* __restrict__ B, const float* __restrict__ W2,
    const float* __restrict__ bias, const float* __restrict__ ro2,
    float* __restrict__ out, float* __restrict__ sOut, int rows)
{
    __shared__ float sW[64*64];
    __shared__ float sX[128*64];
    int tid = threadIdx.x;
    int row0 = blockIdx.x*128;
    int tc = tid & 15, tr = tid >> 4;
    float acc[8][4];
    if(bias){
        float4 b = *(const float4*)&bias[4*tc];
#pragma unroll
        for(int i=0;i<8;i++){ acc[i][0]=b.x; acc[i][1]=b.y; acc[i][2]=b.z; acc[i][3]=b.w; }
    } else {
#pragma unroll
        for(int i=0;i<8;i++){ acc[i][0]=acc[i][1]=acc[i][2]=acc[i][3]=0.f; }
    }
    int nph = B ? 2 : 1;
    for(int ph=0; ph<nph; ph++){
        const float* Xp = ph ? B : A;
        const float* Wp = ph ? W2 : W1;
        if(ph) __syncthreads();
        for(int k=tid;k<4096;k+=256) sW[k] = Wp[k];
        for(int k=tid;k<8192;k+=256){
            int r = k>>6, c = k&63;
            int gr = row0 + r;
            sX[k] = (gr < rows) ? Xp[gr*64+c] : 0.f;
        }
        __syncthreads();
        const float* xr = &sX[(tr*8)*64];
#pragma unroll 4
        for(int k=0;k<64;k++){
            float4 w = *(const float4*)&sW[k*64 + tc*4];
            float a[8];
#pragma unroll
            for(int i=0;i<8;i++) a[i] = xr[i*64+k];
#pragma unroll
            for(int i=0;i<8;i++){
                acc[i][0]=fmaf(a[i],w.x,acc[i][0]);
                acc[i][1]=fmaf(a[i],w.y,acc[i][1]);
                acc[i][2]=fmaf(a[i],w.z,acc[i][2]);
                acc[i][3]=fmaf(a[i],w.w,acc[i][3]);
            }
        }
    }
    float4 ro2v = make_float4(0,0,0,0);
    if(ro2) ro2v = *(const float4*)&ro2[4*tc];
#pragma unroll
    for(int i=0;i<8;i++){
        int r = row0 + tr*8 + i;
        if(r >= rows) continue;
        float4 o;
        float* oo = &o.x;
#pragma unroll
        for(int jj=0;jj<4;jj++){
            float u = acc[i][jj];
            float val;
            if(ro2){
                float sig = 1.f/(1.f + expf(-u));
                float rr = (&ro2v.x)[jj];
                val = rr*sig*fmaf(u, 1.f-sig, 1.f);
            } else if(sOut){
                float sig = 1.f/(1.f + expf(-u));
                val = u*sig;
            } else {
                val = u;
            }
            oo[jj] = val;
        }
        if(sOut){
            float4 so = make_float4(acc[i][0],acc[i][1],acc[i][2],acc[i][3]);
            *(float4*)&sOut[r*64 + tc*4] = so;
        }
        *(float4*)&out[r*64 + tc*4] = o;
    }
}

// ---------------- node GEMM transposed with fused dsilu --------------------
__global__ __launch_bounds__(256) void mm_bwdT(
    const float* __restrict__ G, const float* __restrict__ S,
    const float* __restrict__ W1, const float* __restrict__ W2,
    float* __restrict__ out1, float* __restrict__ out2, int rows)
{
    __shared__ float sWt[64*68];
    __shared__ float sG[64*65];
    int tid = threadIdx.x;
    int row0 = blockIdx.x*64;
    int tc = tid & 15, tr = tid >> 4;
    for(int k=tid;k<4096;k+=256){
        int r = k>>6, c = k&63;
        int gr = row0 + r;
        float v = 0.f;
        if(gr < rows){
            float g = G[gr*64+c];
            if(S){
                float x = S[gr*64+c];
                float sig = 1.f/(1.f + expf(-x));
                v = g*sig*fmaf(x, 1.f-sig, 1.f);
            } else v = g;
        }
        sG[r*65+c] = v;
    }
    int nph = out2 ? 2 : 1;
    for(int ph=0; ph<nph; ph++){
        const float* Wp = ph ? W2 : W1;
        float* op = ph ? out2 : out1;
        if(ph) __syncthreads();
        for(int k=tid;k<4096;k+=256){
            int cout = k>>6, dd = k&63;
            sWt[dd*68+cout] = Wp[k];
        }
        __syncthreads();
        float acc[4][4];
#pragma unroll
        for(int i=0;i<4;i++){ acc[i][0]=acc[i][1]=acc[i][2]=acc[i][3]=0.f; }
        const float* xr = &sG[(tr*4)*65];
#pragma unroll 8
        for(int k=0;k<64;k++){
            float a0 = xr[k], a1 = xr[65+k], a2 = xr[130+k], a3 = xr[195+k];
            float4 w = *(const float4*)&sWt[k*68 + tc*4];
            acc[0][0]=fmaf(a0,w.x,acc[0][0]); acc[0][1]=fmaf(a0,w.y,acc[0][1]);
            acc[0][2]=fmaf(a0,w.z,acc[0][2]); acc[0][3]=fmaf(a0,w.w,acc[0][3]);
            acc[1][0]=fmaf(a1,w.x,acc[1][0]); acc[1][1]=fmaf(a1,w.y,acc[1][1]);
            acc[1][2]=fmaf(a1,w.z,acc[1][2]); acc[1][3]=fmaf(a1,w.w,acc[1][3]);
            acc[2][0]=fmaf(a2,w.x,acc[2][0]); acc[2][1]=fmaf(a2,w.y,acc[2][1]);
            acc[2][2]=fmaf(a2,w.z,acc[2][2]); acc[2][3]=fmaf(a2,w.w,acc[2][3]);
            acc[3][0]=fmaf(a3,w.x,acc[3][0]); acc[3][1]=fmaf(a3,w.y,acc[3][1]);
            acc[3][2]=fmaf(a3,w.z,acc[3][2]); acc[3][3]=fmaf(a3,w.w,acc[3][3]);
        }
#pragma unroll
        for(int i=0;i<4;i++){
            int r = row0 + tr*4 + i;
            if(r >= rows) continue;
            float4 o = make_float4(acc[i][0],acc[i][1],acc[i][2],acc[i][3]);
            *(float4*)&op[r*64 + tc*4] = o;
        }
    }
}

// ---------------- fused readout backward -----------------------------------
__global__ __launch_bounds__(256) void readout_k(
    const float* __restrict__ A, const float* __restrict__ Wro1,
    const float* __restrict__ bro1, const float* __restrict__ Wro2,
    float* __restrict__ gA, int rows)
{
    __shared__ float sW[64*68];
    __shared__ float sX[64*65];
    int tid = threadIdx.x;
    int row0 = blockIdx.x*64;
    int tc = tid & 15, tr = tid >> 4;
    for(int k=tid;k<4096;k+=256) sW[k] = Wro1[k];
    for(int k=tid;k<4096;k+=256){
        int r = k>>6, c = k&63;
        int gr = row0 + r;
        sX[r*65+c] = (gr < rows) ? A[gr*64+c] : 0.f;
    }
    __syncthreads();
    float acc[4][4];
    {
        float4 b = *(const float4*)&bro1[4*tc];
#pragma unroll
        for(int i=0;i<4;i++){ acc[i][0]=b.x; acc[i][1]=b.y; acc[i][2]=b.z; acc[i][3]=b.w; }
    }
    {
        const float* xr = &sX[(tr*4)*65];
#pragma unroll 8
        for(int k=0;k<64;k++){
            float a0 = xr[k], a1 = xr[65+k], a2 = xr[130+k], a3 = xr[195+k];
            float4 w = *(const float4*)&sW[k*64 + tc*4];
            acc[0][0]=fmaf(a0,w.x,acc[0][0]); acc[0][1]=fmaf(a0,w.y,acc[0][1]);
            acc[0][2]=fmaf(a0,w.z,acc[0][2]); acc[0][3]=fmaf(a0,w.w,acc[0][3]);
            acc[1][0]=fmaf(a1,w.x,acc[1][0]); acc[1][1]=fmaf(a1,w.y,acc[1][1]);
            acc[1][2]=fmaf(a1,w.z,acc[1][2]); acc[1][3]=fmaf(a1,w.w,acc[1][3]);
            acc[2][0]=fmaf(a2,w.x,acc[2][0]); acc[2][1]=fmaf(a2,w.y,acc[2][1]);
            acc[2][2]=fmaf(a2,w.z,acc[2][2]); acc[2][3]=fmaf(a2,w.w,acc[2][3]);
            acc[3][0]=fmaf(a3,w.x,acc[3][0]); acc[3][1]=fmaf(a3,w.y,acc[3][1]);
            acc[3][2]=fmaf(a3,w.z,acc[3][2]); acc[3][3]=fmaf(a3,w.w,acc[3][3]);
        }
    }
    __syncthreads();
    {
        float4 ro2v = *(const float4*)&Wro2[4*tc];
#pragma unroll
        for(int i=0;i<4;i++){
#pragma unroll
            for(int jj=0;jj<4;jj++){
                float u = acc[i][jj];
                float sig = 1.f/(1.f + expf(-u));
                float w = (&ro2v.x)[jj]*sig*fmaf(u, 1.f-sig, 1.f);
                sX[(tr*4+i)*65 + tc*4 + jj] = w;
            }
        }
    }
    for(int k=tid;k<4096;k+=256){
        int cout = k>>6, dd = k&63;
        sW[dd*68+cout] = Wro1[k];
    }
    __syncthreads();
    float acc2[4][4];
#pragma unroll
    for(int i=0;i<4;i++){ acc2[i][0]=acc2[i][1]=acc2[i][2]=acc2[i][3]=0.f; }
    {
        const float* xr = &sX[(tr*4)*65];
#pragma unroll 8
        for(int k=0;k<64;k++){
            float a0 = xr[k], a1 = xr[65+k], a2 = xr[130+k], a3 = xr[195+k];
            float4 w = *(const float4*)&sW[k*68 + tc*4];
            acc2[0][0]=fmaf(a0,w.x,acc2[0][0]); acc2[0][1]=fmaf(a0,w.y,acc2[0][1]);
            acc2[0][2]=fmaf(a0,w.z,acc2[0][2]); acc2[0][3]=fmaf(a0,w.w,acc2[0][3]);
            acc2[1][0]=fmaf(a1,w.x,acc2[1][0]); acc2[1][1]=fmaf(a1,w.y,acc2[1][1]);
            acc2[1][2]=fmaf(a1,w.z,acc2[1][2]); acc2[1][3]=fmaf(a1,w.w,acc2[1][3]);
            acc2[2][0]=fmaf(a2,w.x,acc2[2][0]); acc2[2][1]=fmaf(a2,w.y,acc2[2][1]);
            acc2[2][2]=fmaf(a2,w.z,acc2[2][2]); acc2[2][3]=fmaf(a2,w.w,acc2[2][3]);
            acc2[3][0]=fmaf(a3,w.x,acc2[3][0]); acc2[3][1]=fmaf(a3,w.y,acc2[3][1]);
            acc2[3][2]=fmaf(a3,w.z,acc2[3][2]); acc2[3][3]=fmaf(a3,w.w,acc2[3][3]);
        }
    }
#pragma unroll
    for(int i=0;i<4;i++){
        int r = row0 + tr*4 + i;
        if(r >= rows) continue;
        float4 o = make_float4(acc2[i][0],acc2[i][1],acc2[i][2],acc2[i][3]);
        *(float4*)&gA[r*64 + tc*4] = o;
    }
}

// ---------------- host orchestration ---------------------------------------
extern "C" void kernel_launch(void* const* d_in, const int* in_sizes, int n_in,
                              void* d_out, int out_size)
{
    const float* coord  = (const float*)d_in[0];
    const float* emb    = (const float*)d_in[1];
    const float* Wr     = (const float*)d_in[2];
    const float* br     = (const float*)d_in[3];
    const float* Wself0 = (const float*)d_in[4];
    const float* Wmsg0  = (const float*)d_in[5];
    const float* b0     = (const float*)d_in[6];
    const float* Wmsg1  = (const float*)d_in[7];
    const float* Wro1   = (const float*)d_in[9];
    const float* bro1   = (const float*)d_in[10];
    const float* Wro2   = (const float*)d_in[11];
    const int*   z      = (const int*)d_in[13];
    const int*   ei     = (const int*)d_in[14];
    const int*   ej     = (const int*)d_in[15];
    float* F = (float*)d_out;
    (void)in_sizes; (void)n_in; (void)out_size;

    float *h0a,*h0b,*h0c,*s0,*s1,*h1b,*Mbuf,*gM0p,*gM1p,*gA,*gB,*gh1;
    cudaGetSymbolAddress((void**)&h0a, g_h0a);
    cudaGetSymbolAddress((void**)&h0b, g_h0b);
    cudaGetSymbolAddress((void**)&h0c, g_h0c);
    cudaGetSymbolAddress((void**)&s0,  g_s0);
    cudaGetSymbolAddress((void**)&s1,  g_s1);
    cudaGetSymbolAddress((void**)&h1b, g_h1b);
    cudaGetSymbolAddress((void**)&Mbuf,g_M);
    cudaGetSymbolAddress((void**)&gM0p,g_gM0);
    cudaGetSymbolAddress((void**)&gM1p,g_gM1);
    cudaGetSymbolAddress((void**)&gA,  g_gA);
    cudaGetSymbolAddress((void**)&gB,  g_gB);
    cudaGetSymbolAddress((void**)&gh1, g_gh1);
    float* M0 = Mbuf;
    float* M1 = Mbuf + NN*CC;

    const int EB  = (EE + EPB-1)/EPB;
    const int G1  = (NN + 127)/128;
    const int G3  = (3*NN + 127)/128;
    const int T1  = (NN + 63)/64;
    const int T3  = (3*NN + 63)/64;

    embed_zero_k<<<1024, 256>>>(emb, z, F);
    geomA_k<<<(EE+255)/256, 256>>>(coord, ei, ej);
    scan_k<<<1, 1024>>>();
    geomB_k<<<(EE+255)/256, 256>>>(coord, ei, ej);

    // ---- layer 0 forward
    edge_fwd0_k<<<EB, 128>>>(Wr, br, h0a);
    mm_fwd<<<G3, 256>>>(M1, Wmsg1, nullptr, nullptr, nullptr, nullptr, h1b, nullptr, 3*NN);
    mm_fwd<<<G1, 256>>>(M0, Wmsg0, h0a, Wself0, b0, nullptr, h0b, s0, NN);
    cudaMemsetAsync(M0, 0, NN*CC*sizeof(float));
    cudaMemsetAsync(gh1, 0, NN*3*CC*sizeof(float));

    // ---- layer 1 forward (M1/h1 outputs dead)
    edge_fwd1_k<<<EB, 128>>>(Wr + 4096, br + 256, h0b, h1b);
    mm_fwd<<<G1, 256>>>(M0, Wmsg0 + 4096, h0b, Wself0 + 4096, b0 + 64, nullptr, h0c, s1, NN);

    // ---- readout backward (fused)
    readout_k<<<T1, 256>>>(h0c, Wro1, bro1, Wro2, gA, NN);

    // ---- layer 1 backward (j-sorted scatter)
    mm_bwdT<<<T1, 256>>>(gA, s1, Wmsg0 + 4096, Wself0 + 4096, gM0p, gB, NN);
    edge_bwd1_k<<<EB, 128>>>(Wr + 4096, br + 256, h0b, h1b, gM0p, gB, gh1, F);

    // ---- layer 0 backward (i-sorted)
    mm_bwdT<<<T1, 256>>>(gB, s0, Wmsg0, nullptr, gM0p, nullptr, NN);
    mm_bwdT<<<T3, 256>>>(gh1, nullptr, Wmsg1, nullptr, gM1p, nullptr, 3*NN);
    edge_bwd0_k<<<EB, 128>>>(Wr, br, h0a, gM0p, gM1p, F);
}

// round 8
// speedup vs baseline: 1.1043x; 1.0660x over previous
#include <cuda_runtime.h>
#include <math.h>

#define NN   20000
#define EE   320000
#define CC   64
#define NBF  16
#define RCUT 5.0f
#define CSP  (RCUT/(NBF-1))
#define WIDTH (RCUT/NBF)
#define PI_F 3.14159265358979f
#define FULLMASK 0xffffffffu
#define EPW  16                      // edges per warp
#define EPB  (8*EPW)                 // edges per 256-thread block
#define NB2  2048
#define BINSCALE ((float)NB2/RCUT)

// ---------------- device scratch ------------------------------------------
static __device__ int   g_cnt;
static __device__ int   g_hist[2*NN];
static __device__ int   g_cur[2*NN];
static __device__ __align__(16) int2   g_Iij[EE];
static __device__ __align__(16) float4 g_Im[EE];
static __device__ __align__(16) int2   g_Jij[EE];
static __device__ __align__(16) float4 g_Jm[EE];

// filter tables: (G, G') interleaved per channel; sets: 0=(l0,p0) 1=(l0,p1) 2=(l1,p0) 3=(l1,p2)
static __device__ __align__(16) float2 g_tab0[(NB2+1)*CC];
static __device__ __align__(16) float2 g_tab1[(NB2+1)*CC];
static __device__ __align__(16) float2 g_tab2[(NB2+1)*CC];
static __device__ __align__(16) float2 g_tab3[(NB2+1)*CC];

static __device__ __align__(16) float g_h0a[NN*CC];
static __device__ __align__(16) float g_h0b[NN*CC];
static __device__ __align__(16) float g_h0c[NN*CC];
static __device__ __align__(16) float g_s0[NN*CC];
static __device__ __align__(16) float g_s1[NN*CC];
static __device__ __align__(16) float g_h1b[NN*3*CC];
static __device__ __align__(16) float g_M[NN*CC*4];      // M0 | M1
static __device__ __align__(16) float g_gM0[NN*CC];
static __device__ __align__(16) float g_gM1[NN*3*CC];
static __device__ __align__(16) float g_gA[NN*CC];
static __device__ __align__(16) float g_gB[NN*CC];
static __device__ __align__(16) float g_gh1[NN*3*CC];

__device__ __forceinline__ float warpRed(float v){
#pragma unroll
    for(int o=16;o>0;o>>=1) v += __shfl_xor_sync(FULLMASK, v, o);
    return v;
}

__device__ __forceinline__ void red2(float* addr, float a, float b){
    asm volatile("red.global.add.v2.f32 [%0], {%1, %2};"
                 :: "l"(addr), "f"(a), "f"(b) : "memory");
}

// ---------------- filter table build ---------------------------------------
// set s -> (layer, path): 0:(0,0) 1:(0,1) 2:(1,0) 3:(1,2)
__global__ void tabbuild_k(const float* __restrict__ Wr, const float* __restrict__ br)
{
    int idx = blockIdx.x*blockDim.x + threadIdx.x;
    const int per = (NB2+1)*CC;
    if(idx >= 4*per) return;
    int s = idx / per;
    int rem = idx - s*per;
    int bin = rem >> 6;
    int ch  = rem & 63;
    int l = (s >= 2) ? 1 : 0;
    int p = (s == 1) ? 1 : ((s == 3) ? 2 : 0);
    float d = (float)bin * (RCUT/(float)NB2);
    const float* W = Wr + ((l*4 + p)*NBF)*CC + ch;
    float pre = br[(l*4 + p)*CC + ch];
    float q = 0.f;
#pragma unroll
    for(int b=0;b<NBF;b++){
        float z = (d - b*CSP)/WIDTH;
        float rbf = expf(-z*z);
        float w = W[b*CC];
        pre = fmaf(rbf, w, pre);
        q   = fmaf(rbf*(-2.0f*z/WIDTH), w, q);
    }
    float fc  = (d < RCUT) ? 0.5f*(cosf(PI_F*d/RCUT) + 1.0f) : 0.f;
    float dfc = (d < RCUT) ? -0.5f*(PI_F/RCUT)*sinf(PI_F*d/RCUT) : 0.f;
    float2 out = make_float2(fc*pre, fc*q + dfc*pre);
    if(s == 0)      g_tab0[rem] = out;
    else if(s == 1) g_tab1[rem] = out;
    else if(s == 2) g_tab2[rem] = out;
    else            g_tab3[rem] = out;
}

// ---------------- embedding gather + M zero + F zero (fused) ---------------
__global__ void embed_zero_k(const float* __restrict__ emb, const int* __restrict__ z,
                             float* __restrict__ F)
{
    const int NH = NN*16;
    const int NM = NN*64;
    const int NF = NN*3;
    for(int idx = blockIdx.x*blockDim.x + threadIdx.x; idx < NH + NM;
        idx += gridDim.x*blockDim.x){
        if(idx < NH){
            int n = idx >> 4, q = idx & 15;
            int zn = __ldg(&z[n]);
            ((float4*)g_h0a)[idx] = ((const float4*)emb)[zn*16 + q];
        } else {
            ((float4*)g_M)[idx - NH] = make_float4(0.f,0.f,0.f,0.f);
        }
    }
    for(int idx = blockIdx.x*blockDim.x + threadIdx.x; idx < NF;
        idx += gridDim.x*blockDim.x) F[idx] = 0.f;
}

// ---------------- geometry pass 1: histograms ------------------------------
__global__ void geomA_k(const float* __restrict__ coord,
                        const int* __restrict__ ei, const int* __restrict__ ej)
{
    int e = blockIdx.x*blockDim.x + threadIdx.x;
    if(e >= EE) return;
    int i = ei[e], j = ej[e];
    float dx = coord[j*3+0] - coord[i*3+0];
    float dy = coord[j*3+1] - coord[i*3+1];
    float dz = coord[j*3+2] - coord[i*3+2];
    float d2 = dx*dx + dy*dy + dz*dz + 1e-12f;
    if(d2 < RCUT*RCUT){
        atomicAdd(&g_hist[i], 1);
        atomicAdd(&g_hist[NN+j], 1);
    }
}

// ---------------- exclusive scans; re-zero histogram for next replay -------
__global__ __launch_bounds__(1024) void scan_k()
{
    __shared__ int swarp[32];
    int t = threadIdx.x;
    int lane = t & 31, wid = t >> 5;
    for(int pass=0; pass<2; pass++){
        int* hist = g_hist + pass*NN;
        int* cur = g_cur + pass*NN;
        int base = t*20;
        int local[20];
        int s = 0;
#pragma unroll
        for(int q=0;q<20;q++){
            int idx = base + q;
            int v = (idx < NN) ? hist[idx] : 0;
            local[q] = s; s += v;
            if(idx < NN) hist[idx] = 0;
        }
        int inc = s;
#pragma unroll
        for(int o=1;o<32;o<<=1){
            int n = __shfl_up_sync(FULLMASK, inc, o);
            if(lane >= o) inc += n;
        }
        if(lane == 31) swarp[wid] = inc;
        __syncthreads();
        if(wid == 0){
            int v = swarp[lane];
#pragma unroll
            for(int o=1;o<32;o<<=1){
                int n = __shfl_up_sync(FULLMASK, v, o);
                if(lane >= o) v += n;
            }
            swarp[lane] = v;
        }
        __syncthreads();
        int offset = inc - s + ((wid > 0) ? swarp[wid-1] : 0);
#pragma unroll
        for(int q=0;q<20;q++){
            int idx = base + q;
            if(idx < NN) cur[idx] = offset + local[q];
        }
        if(pass == 0 && t == 1023) g_cnt = offset + s;
        __syncthreads();
    }
}

// ---------------- geometry pass 2: write both sorted orders ----------------
__global__ void geomB_k(const float* __restrict__ coord,
                        const int* __restrict__ ei, const int* __restrict__ ej)
{
    int e = blockIdx.x*blockDim.x + threadIdx.x;
    if(e >= EE) return;
    int i = ei[e], j = ej[e];
    float dx = coord[j*3+0] - coord[i*3+0];
    float dy = coord[j*3+1] - coord[i*3+1];
    float dz = coord[j*3+2] - coord[i*3+2];
    float d2 = dx*dx + dy*dy + dz*dz + 1e-12f;
    if(d2 >= RCUT*RCUT) return;
    float d = sqrtf(d2);
    float inv = 1.0f/d;
    float4 m = make_float4(d, dx*inv, dy*inv, dz*inv);
    int2 ij = make_int2(i, j);
    int posI = atomicAdd(&g_cur[i], 1);
    g_Iij[posI] = ij;  g_Im[posI] = m;
    int posJ = atomicAdd(&g_cur[NN+j], 1);
    g_Jij[posJ] = ij;  g_Jm[posJ] = m;
}

// ---------------- forward layer-0 edge kernel (i-sorted) -------------------
__global__ __launch_bounds__(256) void edge_fwd0_k(const float* __restrict__ h0)
{
    int tid = threadIdx.x;
    int cnt = g_cnt;
    int e0 = (blockIdx.x*8 + (tid>>5))*EPW;
    if(e0 >= cnt) return;
    int lane = tid & 31;
    int c = 2*lane;
    int eend = min(e0 + EPW, cnt);
    const float4* T0 = (const float4*)g_tab0;
    const float4* T1 = (const float4*)g_tab1;

    float* M0 = g_M;
    float* M1 = g_M + NN*CC;
    float2 a0c = make_float2(0.f,0.f);
    float2 a1c[3] = {{0,0},{0,0},{0,0}};

    int2   ijn = g_Iij[e0];
    float4 mn  = g_Im[e0];
    float2 hn  = *(const float2*)&h0[ijn.y*64+c];
    float  tn  = mn.x*BINSCALE; int bn = (int)tn; float frn = tn - bn;
    float4 A0n = T0[bn*32+lane], A1n = T0[(bn+1)*32+lane];
    float4 B0n = T1[bn*32+lane], B1n = T1[(bn+1)*32+lane];
    int curi = ijn.x;

    for(int e=e0;e<eend;e++){
        int2 ij = ijn; float4 m = mn; float2 h0j = hn; float fr = frn;
        float4 A0 = A0n, A1 = A1n, B0 = B0n, B1 = B1n;
        if(e+1 < eend){
            ijn = g_Iij[e+1];
            mn  = g_Im[e+1];
            hn  = *(const float2*)&h0[ijn.y*64+c];
            tn = mn.x*BINSCALE; bn = (int)tn; frn = tn - bn;
            A0n = T0[bn*32+lane]; A1n = T0[(bn+1)*32+lane];
            B0n = T1[bn*32+lane]; B1n = T1[(bn+1)*32+lane];
        }
        if(ij.x != curi){
            red2(&M0[curi*64+c], a0c.x, a0c.y);
#pragma unroll
            for(int x=0;x<3;x++) red2(&M1[(curi*3+x)*64+c], a1c[x].x, a1c[x].y);
            a0c = make_float2(0.f,0.f);
#pragma unroll
            for(int x=0;x<3;x++) a1c[x] = make_float2(0.f,0.f);
            curi = ij.x;
        }
        float rh[3] = {m.y, m.z, m.w};
        float G0x = fmaf(fr, A1.x-A0.x, A0.x), G0y = fmaf(fr, A1.z-A0.z, A0.z);
        float G1x = fmaf(fr, B1.x-B0.x, B0.x), G1y = fmaf(fr, B1.z-B0.z, B0.z);
        a0c.x = fmaf(G0x, h0j.x, a0c.x);
        a0c.y = fmaf(G0y, h0j.y, a0c.y);
        float g1x = G1x*h0j.x, g1y = G1y*h0j.y;
#pragma unroll
        for(int x=0;x<3;x++){
            a1c[x].x = fmaf(g1x, rh[x], a1c[x].x);
            a1c[x].y = fmaf(g1y, rh[x], a1c[x].y);
        }
    }
    red2(&M0[curi*64+c], a0c.x, a0c.y);
#pragma unroll
    for(int x=0;x<3;x++) red2(&M1[(curi*3+x)*64+c], a1c[x].x, a1c[x].y);
}

// ---------------- forward layer-1 edge kernel (i-sorted) -------------------
__global__ __launch_bounds__(256) void edge_fwd1_k(
    const float* __restrict__ h0, const float* __restrict__ h1)
{
    int tid = threadIdx.x;
    int cnt = g_cnt;
    int e0 = (blockIdx.x*8 + (tid>>5))*EPW;
    if(e0 >= cnt) return;
    int lane = tid & 31;
    int c = 2*lane;
    int eend = min(e0 + EPW, cnt);
    const float4* T0 = (const float4*)g_tab2;
    const float4* T1 = (const float4*)g_tab3;

    float* M0 = g_M;
    float2 a0c = make_float2(0.f,0.f);

    int2   ijn = g_Iij[e0];
    float4 mn  = g_Im[e0];
    float2 hn  = *(const float2*)&h0[ijn.y*64+c];
    float2 vn0 = *(const float2*)&h1[(ijn.y*3+0)*64+c];
    float2 vn1 = *(const float2*)&h1[(ijn.y*3+1)*64+c];
    float2 vn2 = *(const float2*)&h1[(ijn.y*3+2)*64+c];
    float  tn  = mn.x*BINSCALE; int bn = (int)tn; float frn = tn - bn;
    float4 A0n = T0[bn*32+lane], A1n = T0[(bn+1)*32+lane];
    float4 B0n = T1[bn*32+lane], B1n = T1[(bn+1)*32+lane];
    int curi = ijn.x;

    for(int e=e0;e<eend;e++){
        int2 ij = ijn; float4 m = mn; float2 h0j = hn; float fr = frn;
        float2 v0 = vn0, v1 = vn1, v2 = vn2;
        float4 A0 = A0n, A1 = A1n, B0 = B0n, B1 = B1n;
        if(e+1 < eend){
            ijn = g_Iij[e+1];
            mn  = g_Im[e+1];
            hn  = *(const float2*)&h0[ijn.y*64+c];
            vn0 = *(const float2*)&h1[(ijn.y*3+0)*64+c];
            vn1 = *(const float2*)&h1[(ijn.y*3+1)*64+c];
            vn2 = *(const float2*)&h1[(ijn.y*3+2)*64+c];
            tn = mn.x*BINSCALE; bn = (int)tn; frn = tn - bn;
            A0n = T0[bn*32+lane]; A1n = T0[(bn+1)*32+lane];
            B0n = T1[bn*32+lane]; B1n = T1[(bn+1)*32+lane];
        }
        if(ij.x != curi){
            red2(&M0[curi*64+c], a0c.x, a0c.y);
            a0c = make_float2(0.f,0.f);
            curi = ij.x;
        }
        float rh[3] = {m.y, m.z, m.w};
        float G0x = fmaf(fr, A1.x-A0.x, A0.x), G0y = fmaf(fr, A1.z-A0.z, A0.z);
        float G2x = fmaf(fr, B1.x-B0.x, B0.x), G2y = fmaf(fr, B1.z-B0.z, B0.z);
        float tx = v0.x*rh[0] + v1.x*rh[1] + v2.x*rh[2];
        float ty = v0.y*rh[0] + v1.y*rh[1] + v2.y*rh[2];
        a0c.x += G0x*h0j.x + G2x*tx;
        a0c.y += G0y*h0j.y + G2y*ty;
    }
    red2(&M0[curi*64+c], a0c.x, a0c.y);
}

// ---------------- backward layer-0 (i-sorted; h1==0) -----------------------
__global__ __launch_bounds__(256) void edge_bwd0_k(
    const float* __restrict__ h0,
    const float* __restrict__ gM0, const float* __restrict__ gM1,
    float* __restrict__ F)
{
    int tid = threadIdx.x;
    int cnt = g_cnt;
    int e0 = (blockIdx.x*8 + (tid>>5))*EPW;
    if(e0 >= cnt) return;
    int lane = tid & 31;
    int c = 2*lane;
    int eend = min(e0 + EPW, cnt);
    const float4* T0 = (const float4*)g_tab0;
    const float4* T1 = (const float4*)g_tab1;

    int2   ijn = g_Iij[e0];
    float4 mn  = g_Im[e0];
    float2 hn  = *(const float2*)&h0[ijn.y*64+c];
    float  tn  = mn.x*BINSCALE; int bn = (int)tn; float frn = tn - bn;
    float4 A0n = T0[bn*32+lane], A1n = T0[(bn+1)*32+lane];
    float4 B0n = T1[bn*32+lane], B1n = T1[(bn+1)*32+lane];
    int curi = ijn.x;
    float2 gm0 = *(const float2*)&gM0[curi*64+c];
    float2 gm1[3];
#pragma unroll
    for(int x=0;x<3;x++) gm1[x] = *(const float2*)&gM1[(curi*3+x)*64+c];
    float fi = 0.f;

    for(int e=e0;e<eend;e++){
        int2 ij = ijn; float4 m = mn; float2 h0j = hn; float fr = frn;
        float4 A0 = A0n, A1 = A1n, B0 = B0n, B1 = B1n;
        if(e+1 < eend){
            ijn = g_Iij[e+1];
            mn  = g_Im[e+1];
            hn  = *(const float2*)&h0[ijn.y*64+c];
            tn = mn.x*BINSCALE; bn = (int)tn; frn = tn - bn;
            A0n = T0[bn*32+lane]; A1n = T0[(bn+1)*32+lane];
            B0n = T1[bn*32+lane]; B1n = T1[(bn+1)*32+lane];
        }
        if(ij.x != curi){
            if(lane < 3) atomicAdd(&F[curi*3+lane], fi);
            fi = 0.f;
            curi = ij.x;
            gm0 = *(const float2*)&gM0[curi*64+c];
#pragma unroll
            for(int x=0;x<3;x++) gm1[x] = *(const float2*)&gM1[(curi*3+x)*64+c];
        }
        int j = ij.y;
        float d = m.x;
        float rh[3] = {m.y, m.z, m.w};
        float G1x = fmaf(fr, B1.x-B0.x, B0.x), G1y = fmaf(fr, B1.z-B0.z, B0.z);
        float Q0x = fmaf(fr, A1.y-A0.y, A0.y), Q0y = fmaf(fr, A1.w-A0.w, A0.w);
        float Q1x = fmaf(fr, B1.y-B0.y, B0.y), Q1y = fmaf(fr, B1.w-B0.w, B0.w);

        float gmrx = gm1[0].x*rh[0] + gm1[1].x*rh[1] + gm1[2].x*rh[2];
        float gmry = gm1[0].y*rh[0] + gm1[1].y*rh[1] + gm1[2].y*rh[2];
        float gf0x = gm0.x*h0j.x, gf0y = gm0.y*h0j.y;
        float gf1x = gmrx*h0j.x,  gf1y = gmry*h0j.y;
        float sd = gf0x*Q0x + gf0y*Q0y + gf1x*Q1x + gf1y*Q1y;
        float f1x = G1x*h0j.x, f1y = G1y*h0j.y;
        float gr0 = gm1[0].x*f1x + gm1[0].y*f1y;
        float gr1 = gm1[1].x*f1x + gm1[1].y*f1y;
        float gr2 = gm1[2].x*f1x + gm1[2].y*f1y;

        sd  = warpRed(sd);
        gr0 = warpRed(gr0);
        gr1 = warpRed(gr1);
        gr2 = warpRed(gr2);

        float gdr = gr0*rh[0] + gr1*rh[1] + gr2*rh[2];
        float invd = 1.0f/d;
        if(lane < 3){
            float gx = (lane==0) ? gr0 : ((lane==1) ? gr1 : gr2);
            float rx = rh[lane];
            float grij = (gx - gdr*rx)*invd + sd*rx;
            fi += grij;
            atomicAdd(&F[j*3+lane], -grij);
        }
    }
    if(lane < 3) atomicAdd(&F[curi*3+lane], fi);
}

// ---------------- backward layer-1 (j-sorted) ------------------------------
__global__ __launch_bounds__(256) void edge_bwd1_k(
    const float* __restrict__ h0, const float* __restrict__ h1,
    const float* __restrict__ gM0,
    float* __restrict__ gh0, float* __restrict__ gh1, float* __restrict__ F)
{
    int tid = threadIdx.x;
    int cnt = g_cnt;
    int e0 = (blockIdx.x*8 + (tid>>5))*EPW;
    if(e0 >= cnt) return;
    int lane = tid & 31;
    int c = 2*lane;
    int eend = min(e0 + EPW, cnt);
    const float4* T0 = (const float4*)g_tab2;
    const float4* T1 = (const float4*)g_tab3;

    int2   ijn = g_Jij[e0];
    float4 mn  = g_Jm[e0];
    float2 gmn = *(const float2*)&gM0[ijn.x*64+c];
    float  tn  = mn.x*BINSCALE; int bn = (int)tn; float frn = tn - bn;
    float4 A0n = T0[bn*32+lane], A1n = T0[(bn+1)*32+lane];
    float4 B0n = T1[bn*32+lane], B1n = T1[(bn+1)*32+lane];
    int curj = ijn.y;
    float2 h0j = *(const float2*)&h0[curj*64+c];
    float2 v[3];
#pragma unroll
    for(int x=0;x<3;x++) v[x] = *(const float2*)&h1[(curj*3+x)*64+c];
    float2 acc0 = make_float2(0,0);
    float2 acc1[3] = {{0,0},{0,0},{0,0}};
    float fj = 0.f;

    for(int e=e0;e<eend;e++){
        int2 ij = ijn; float4 m = mn; float2 gm0 = gmn; float fr = frn;
        float4 A0 = A0n, A1 = A1n, B0 = B0n, B1 = B1n;
        if(e+1 < eend){
            ijn = g_Jij[e+1];
            mn  = g_Jm[e+1];
            gmn = *(const float2*)&gM0[ijn.x*64+c];
            tn = mn.x*BINSCALE; bn = (int)tn; frn = tn - bn;
            A0n = T0[bn*32+lane]; A1n = T0[(bn+1)*32+lane];
            B0n = T1[bn*32+lane]; B1n = T1[(bn+1)*32+lane];
        }
        if(ij.y != curj){
            red2(&gh0[curj*64+c], acc0.x, acc0.y);
#pragma unroll
            for(int x=0;x<3;x++) red2(&gh1[(curj*3+x)*64+c], acc1[x].x, acc1[x].y);
            if(lane < 3) atomicAdd(&F[curj*3+lane], fj);
            acc0 = make_float2(0,0);
#pragma unroll
            for(int x=0;x<3;x++) acc1[x] = make_float2(0,0);
            fj = 0.f;
            curj = ij.y;
            h0j = *(const float2*)&h0[curj*64+c];
#pragma unroll
            for(int x=0;x<3;x++) v[x] = *(const float2*)&h1[(curj*3+x)*64+c];
        }
        int i = ij.x;
        float d = m.x;
        float rh[3] = {m.y, m.z, m.w};
        float G0x = fmaf(fr, A1.x-A0.x, A0.x), G0y = fmaf(fr, A1.z-A0.z, A0.z);
        float G2x = fmaf(fr, B1.x-B0.x, B0.x), G2y = fmaf(fr, B1.z-B0.z, B0.z);
        float Q0x = fmaf(fr, A1.y-A0.y, A0.y), Q0y = fmaf(fr, A1.w-A0.w, A0.w);
        float Q2x = fmaf(fr, B1.y-B0.y, B0.y), Q2y = fmaf(fr, B1.w-B0.w, B0.w);

        float tx = v[0].x*rh[0] + v[1].x*rh[1] + v[2].x*rh[2];
        float ty = v[0].y*rh[0] + v[1].y*rh[1] + v[2].y*rh[2];
        float sd = gm0.x*(Q0x*h0j.x + Q2x*tx) + gm0.y*(Q0y*h0j.y + Q2y*ty);
        float f2x = G2x*gm0.x, f2y = G2y*gm0.y;
        float gr0 = f2x*v[0].x + f2y*v[0].y;
        float gr1 = f2x*v[1].x + f2y*v[1].y;
        float gr2 = f2x*v[2].x + f2y*v[2].y;

        acc0.x += gm0.x*G0x;
        acc0.y += gm0.y*G0y;
#pragma unroll
        for(int x=0;x<3;x++){
            acc1[x].x += f2x*rh[x];
            acc1[x].y += f2y*rh[x];
        }

        sd  = warpRed(sd);
        gr0 = warpRed(gr0);
        gr1 = warpRed(gr1);
        gr2 = warpRed(gr2);

        float gdr = gr0*rh[0] + gr1*rh[1] + gr2*rh[2];
        float invd = 1.0f/d;
        if(lane < 3){
            float gx = (lane==0) ? gr0 : ((lane==1) ? gr1 : gr2);
            float rx = rh[lane];
            float grij = (gx - gdr*rx)*invd + sd*rx;
            atomicAdd(&F[i*3+lane], grij);
            fj -= grij;
        }
    }
    red2(&gh0[curj*64+c], acc0.x, acc0.y);
#pragma unroll
    for(int x=0;x<3;x++) red2(&gh1[(curj*3+x)*64+c], acc1[x].x, acc1[x].y);
    if(lane < 3) atomicAdd(&F[curj*3+lane], fj);
}

// ---------------- node GEMM: out = epilogue(A@W1 [+ B@W2] [+ bias]) --------
__global__ __launch_bounds__(256) void mm_fwd(
    const float* __restrict__ A, const float* __restrict__ W1,
    const float* __restrict__ B, const float* __restrict__ W2,
    const float* __restrict__ bias, const float* __restrict__ ro2,
    float* __restrict__ out, float* __restrict__ sOut, int rows)
{
    __shared__ float sW[64*64];
    __shared__ float sX[128*64];
    int tid = threadIdx.x;
    int row0 = blockIdx.x*128;
    int tc = tid & 15, tr = tid >> 4;
    float acc[8][4];
    if(bias){
        float4 b = *(const float4*)&bias[4*tc];
#pragma unroll
        for(int i=0;i<8;i++){ acc[i][0]=b.x; acc[i][1]=b.y; acc[i][2]=b.z; acc[i][3]=b.w; }
    } else {
#pragma unroll
        for(int i=0;i<8;i++){ acc[i][0]=acc[i][1]=acc[i][2]=acc[i][3]=0.f; }
    }
    int nph = B ? 2 : 1;
    for(int ph=0; ph<nph; ph++){
        const float* Xp = ph ? B : A;
        const float* Wp = ph ? W2 : W1;
        if(ph) __syncthreads();
        for(int k=tid;k<4096;k+=256) sW[k] = Wp[k];
        for(int k=tid;k<8192;k+=256){
            int r = k>>6, c = k&63;
            int gr = row0 + r;
            sX[k] = (gr < rows) ? Xp[gr*64+c] : 0.f;
        }
        __syncthreads();
        const float* xr = &sX[(tr*8)*64];
#pragma unroll 4
        for(int k=0;k<64;k++){
            float4 w = *(const float4*)&sW[k*64 + tc*4];
            float a[8];
#pragma unroll
            for(int i=0;i<8;i++) a[i] = xr[i*64+k];
#pragma unroll
            for(int i=0;i<8;i++){
                acc[i][0]=fmaf(a[i],w.x,acc[i][0]);
                acc[i][1]=fmaf(a[i],w.y,acc[i][1]);
                acc[i][2]=fmaf(a[i],w.z,acc[i][2]);
                acc[i][3]=fmaf(a[i],w.w,acc[i][3]);
            }
        }
    }
    float4 ro2v = make_float4(0,0,0,0);
    if(ro2) ro2v = *(const float4*)&ro2[4*tc];
#pragma unroll
    for(int i=0;i<8;i++){
        int r = row0 + tr*8 + i;
        if(r >= rows) continue;
        float4 o;
        float* oo = &o.x;
#pragma unroll
        for(int jj=0;jj<4;jj++){
            float u = acc[i][jj];
            float val;
            if(ro2){
                float sig = 1.f/(1.f + expf(-u));
                float rr = (&ro2v.x)[jj];
                val = rr*sig*fmaf(u, 1.f-sig, 1.f);
            } else if(sOut){
                float sig = 1.f/(1.f + expf(-u));
                val = u*sig;
            } else {
                val = u;
            }
            oo[jj] = val;
        }
        if(sOut){
            float4 so = make_float4(acc[i][0],acc[i][1],acc[i][2],acc[i][3]);
            *(float4*)&sOut[r*64 + tc*4] = so;
        }
        *(float4*)&out[r*64 + tc*4] = o;
    }
}

// ---------------- node GEMM transposed with fused dsilu --------------------
__global__ __launch_bounds__(256) void mm_bwdT(
    const float* __restrict__ G, const float* __restrict__ S,
    const float* __restrict__ W1, const float* __restrict__ W2,
    float* __restrict__ out1, float* __restrict__ out2, int rows)
{
    __shared__ float sWt[64*68];
    __shared__ float sG[64*65];
    int tid = threadIdx.x;
    int row0 = blockIdx.x*64;
    int tc = tid & 15, tr = tid >> 4;
    for(int k=tid;k<4096;k+=256){
        int r = k>>6, c = k&63;
        int gr = row0 + r;
        float v = 0.f;
        if(gr < rows){
            float g = G[gr*64+c];
            if(S){
                float x = S[gr*64+c];
                float sig = 1.f/(1.f + expf(-x));
                v = g*sig*fmaf(x, 1.f-sig, 1.f);
            } else v = g;
        }
        sG[r*65+c] = v;
    }
    int nph = out2 ? 2 : 1;
    for(int ph=0; ph<nph; ph++){
        const float* Wp = ph ? W2 : W1;
        float* op = ph ? out2 : out1;
        if(ph) __syncthreads();
        for(int k=tid;k<4096;k+=256){
            int cout = k>>6, dd = k&63;
            sWt[dd*68+cout] = Wp[k];
        }
        __syncthreads();
        float acc[4][4];
#pragma unroll
        for(int i=0;i<4;i++){ acc[i][0]=acc[i][1]=acc[i][2]=acc[i][3]=0.f; }
        const float* xr = &sG[(tr*4)*65];
#pragma unroll 8
        for(int k=0;k<64;k++){
            float a0 = xr[k], a1 = xr[65+k], a2 = xr[130+k], a3 = xr[195+k];
            float4 w = *(const float4*)&sWt[k*68 + tc*4];
            acc[0][0]=fmaf(a0,w.x,acc[0][0]); acc[0][1]=fmaf(a0,w.y,acc[0][1]);
            acc[0][2]=fmaf(a0,w.z,acc[0][2]); acc[0][3]=fmaf(a0,w.w,acc[0][3]);
            acc[1][0]=fmaf(a1,w.x,acc[1][0]); acc[1][1]=fmaf(a1,w.y,acc[1][1]);
            acc[1][2]=fmaf(a1,w.z,acc[1][2]); acc[1][3]=fmaf(a1,w.w,acc[1][3]);
            acc[2][0]=fmaf(a2,w.x,acc[2][0]); acc[2][1]=fmaf(a2,w.y,acc[2][1]);
            acc[2][2]=fmaf(a2,w.z,acc[2][2]); acc[2][3]=fmaf(a2,w.w,acc[2][3]);
            acc[3][0]=fmaf(a3,w.x,acc[3][0]); acc[3][1]=fmaf(a3,w.y,acc[3][1]);
            acc[3][2]=fmaf(a3,w.z,acc[3][2]); acc[3][3]=fmaf(a3,w.w,acc[3][3]);
        }
#pragma unroll
        for(int i=0;i<4;i++){
            int r = row0 + tr*4 + i;
            if(r >= rows) continue;
            float4 o = make_float4(acc[i][0],acc[i][1],acc[i][2],acc[i][3]);
            *(float4*)&op[r*64 + tc*4] = o;
        }
    }
}

// ---------------- fused readout backward -----------------------------------
__global__ __launch_bounds__(256) void readout_k(
    const float* __restrict__ A, const float* __restrict__ Wro1,
    const float* __restrict__ bro1, const float* __restrict__ Wro2,
    float* __restrict__ gA, int rows)
{
    __shared__ float sW[64*68];
    __shared__ float sX[64*65];
    int tid = threadIdx.x;
    int row0 = blockIdx.x*64;
    int tc = tid & 15, tr = tid >> 4;
    for(int k=tid;k<4096;k+=256) sW[k] = Wro1[k];
    for(int k=tid;k<4096;k+=256){
        int r = k>>6, c = k&63;
        int gr = row0 + r;
        sX[r*65+c] = (gr < rows) ? A[gr*64+c] : 0.f;
    }
    __syncthreads();
    float acc[4][4];
    {
        float4 b = *(const float4*)&bro1[4*tc];
#pragma unroll
        for(int i=0;i<4;i++){ acc[i][0]=b.x; acc[i][1]=b.y; acc[i][2]=b.z; acc[i][3]=b.w; }
    }
    {
        const float* xr = &sX[(tr*4)*65];
#pragma unroll 8
        for(int k=0;k<64;k++){
            float a0 = xr[k], a1 = xr[65+k], a2 = xr[130+k], a3 = xr[195+k];
            float4 w = *(const float4*)&sW[k*64 + tc*4];
            acc[0][0]=fmaf(a0,w.x,acc[0][0]); acc[0][1]=fmaf(a0,w.y,acc[0][1]);
            acc[0][2]=fmaf(a0,w.z,acc[0][2]); acc[0][3]=fmaf(a0,w.w,acc[0][3]);
            acc[1][0]=fmaf(a1,w.x,acc[1][0]); acc[1][1]=fmaf(a1,w.y,acc[1][1]);
            acc[1][2]=fmaf(a1,w.z,acc[1][2]); acc[1][3]=fmaf(a1,w.w,acc[1][3]);
            acc[2][0]=fmaf(a2,w.x,acc[2][0]); acc[2][1]=fmaf(a2,w.y,acc[2][1]);
            acc[2][2]=fmaf(a2,w.z,acc[2][2]); acc[2][3]=fmaf(a2,w.w,acc[2][3]);
            acc[3][0]=fmaf(a3,w.x,acc[3][0]); acc[3][1]=fmaf(a3,w.y,acc[3][1]);
            acc[3][2]=fmaf(a3,w.z,acc[3][2]); acc[3][3]=fmaf(a3,w.w,acc[3][3]);
        }
    }
    __syncthreads();
    {
        float4 ro2v = *(const float4*)&Wro2[4*tc];
#pragma unroll
        for(int i=0;i<4;i++){
#pragma unroll
            for(int jj=0;jj<4;jj++){
                float u = acc[i][jj];
                float sig = 1.f/(1.f + expf(-u));
                float w = (&ro2v.x)[jj]*sig*fmaf(u, 1.f-sig, 1.f);
                sX[(tr*4+i)*65 + tc*4 + jj] = w;
            }
        }
    }
    for(int k=tid;k<4096;k+=256){
        int cout = k>>6, dd = k&63;
        sW[dd*68+cout] = Wro1[k];
    }
    __syncthreads();
    float acc2[4][4];
#pragma unroll
    for(int i=0;i<4;i++){ acc2[i][0]=acc2[i][1]=acc2[i][2]=acc2[i][3]=0.f; }
    {
        const float* xr = &sX[(tr*4)*65];
#pragma unroll 8
        for(int k=0;k<64;k++){
            float a0 = xr[k], a1 = xr[65+k], a2 = xr[130+k], a3 = xr[195+k];
            float4 w = *(const float4*)&sW[k*68 + tc*4];
            acc2[0][0]=fmaf(a0,w.x,acc2[0][0]); acc2[0][1]=fmaf(a0,w.y,acc2[0][1]);
            acc2[0][2]=fmaf(a0,w.z,acc2[0][2]); acc2[0][3]=fmaf(a0,w.w,acc2[0][3]);
            acc2[1][0]=fmaf(a1,w.x,acc2[1][0]); acc2[1][1]=fmaf(a1,w.y,acc2[1][1]);
            acc2[1][2]=fmaf(a1,w.z,acc2[1][2]); acc2[1][3]=fmaf(a1,w.w,acc2[1][3]);
            acc2[2][0]=fmaf(a2,w.x,acc2[2][0]); acc2[2][1]=fmaf(a2,w.y,acc2[2][1]);
            acc2[2][2]=fmaf(a2,w.z,acc2[2][2]); acc2[2][3]=fmaf(a2,w.w,acc2[2][3]);
            acc2[3][0]=fmaf(a3,w.x,acc2[3][0]); acc2[3][1]=fmaf(a3,w.y,acc2[3][1]);
            acc2[3][2]=fmaf(a3,w.z,acc2[3][2]); acc2[3][3]=fmaf(a3,w.w,acc2[3][3]);
        }
    }
#pragma unroll
    for(int i=0;i<4;i++){
        int r = row0 + tr*4 + i;
        if(r >= rows) continue;
        float4 o = make_float4(acc2[i][0],acc2[i][1],acc2[i][2],acc2[i][3]);
        *(float4*)&gA[r*64 + tc*4] = o;
    }
}

// ---------------- host orchestration ---------------------------------------
extern "C" void kernel_launch(void* const* d_in, const int* in_sizes, int n_in,
                              void* d_out, int out_size)
{
    const float* coord  = (const float*)d_in[0];
    const float* emb    = (const float*)d_in[1];
    const float* Wr     = (const float*)d_in[2];
    const float* br     = (const float*)d_in[3];
    const float* Wself0 = (const float*)d_in[4];
    const float* Wmsg0  = (const float*)d_in[5];
    const float* b0     = (const float*)d_in[6];
    const float* Wmsg1  = (const float*)d_in[7];
    const float* Wro1   = (const float*)d_in[9];
    const float* bro1   = (const float*)d_in[10];
    const float* Wro2   = (const float*)d_in[11];
    const int*   z      = (const int*)d_in[13];
    const int*   ei     = (const int*)d_in[14];
    const int*   ej     = (const int*)d_in[15];
    float* F = (float*)d_out;
    (void)in_sizes; (void)n_in; (void)out_size;

    float *h0a,*h0b,*h0c,*s0,*s1,*h1b,*Mbuf,*gM0p,*gM1p,*gA,*gB,*gh1;
    cudaGetSymbolAddress((void**)&h0a, g_h0a);
    cudaGetSymbolAddress((void**)&h0b, g_h0b);
    cudaGetSymbolAddress((void**)&h0c, g_h0c);
    cudaGetSymbolAddress((void**)&s0,  g_s0);
    cudaGetSymbolAddress((void**)&s1,  g_s1);
    cudaGetSymbolAddress((void**)&h1b, g_h1b);
    cudaGetSymbolAddress((void**)&Mbuf,g_M);
    cudaGetSymbolAddress((void**)&gM0p,g_gM0);
    cudaGetSymbolAddress((void**)&gM1p,g_gM1);
    cudaGetSymbolAddress((void**)&gA,  g_gA);
    cudaGetSymbolAddress((void**)&gB,  g_gB);
    cudaGetSymbolAddress((void**)&gh1, g_gh1);
    float* M0 = Mbuf;
    float* M1 = Mbuf + NN*CC;

    const int EB  = (EE + EPB-1)/EPB;
    const int G1  = (NN + 127)/128;
    const int G3  = (3*NN + 127)/128;
    const int T1  = (NN + 63)/64;
    const int T3  = (3*NN + 63)/64;
    const int TABN = 4*(NB2+1)*CC;

    tabbuild_k<<<(TABN+255)/256, 256>>>(Wr, br);
    embed_zero_k<<<1024, 256>>>(emb, z, F);
    geomA_k<<<(EE+255)/256, 256>>>(coord, ei, ej);
    scan_k<<<1, 1024>>>();
    geomB_k<<<(EE+255)/256, 256>>>(coord, ei, ej);

    // ---- layer 0 forward
    edge_fwd0_k<<<EB, 256>>>(h0a);
    mm_fwd<<<G3, 256>>>(M1, Wmsg1, nullptr, nullptr, nullptr, nullptr, h1b, nullptr, 3*NN);
    mm_fwd<<<G1, 256>>>(M0, Wmsg0, h0a, Wself0, b0, nullptr, h0b, s0, NN);
    cudaMemsetAsync(M0, 0, NN*CC*sizeof(float));
    cudaMemsetAsync(gh1, 0, NN*3*CC*sizeof(float));

    // ---- layer 1 forward (M1/h1 outputs dead)
    edge_fwd1_k<<<EB, 256>>>(h0b, h1b);
    mm_fwd<<<G1, 256>>>(M0, Wmsg0 + 4096, h0b, Wself0 + 4096, b0 + 64, nullptr, h0c, s1, NN);

    // ---- readout backward (fused)
    readout_k<<<T1, 256>>>(h0c, Wro1, bro1, Wro2, gA, NN);

    // ---- layer 1 backward (j-sorted scatter)
    mm_bwdT<<<T1, 256>>>(gA, s1, Wmsg0 + 4096, Wself0 + 4096, gM0p, gB, NN);
    edge_bwd1_k<<<EB, 256>>>(h0b, h1b, gM0p, gB, gh1, F);

    // ---- layer 0 backward (i-sorted)
    mm_bwdT<<<T1, 256>>>(gB, s0, Wmsg0, nullptr, gM0p, nullptr, NN);
    mm_bwdT<<<T3, 256>>>(gh1, nullptr, Wmsg1, nullptr, gM1p, nullptr, 3*NN);
    edge_bwd0_k<<<EB, 256>>>(h0a, gM0p, gM1p, F);
}

// round 9
// speedup vs baseline: 1.2406x; 1.1235x over previous
#include <cuda_runtime.h>
#include <math.h>

#define NN   20000
#define EE   320000
#define CC   64
#define NBF  16
#define RCUT 5.0f
#define CSP  (RCUT/(NBF-1))
#define WIDTH (RCUT/NBF)
#define PI_F 3.14159265358979f
#define FULLMASK 0xffffffffu
#define EPW  16                      // edges per warp
#define EPB  (8*EPW)                 // edges per 256-thread block
#define NB2  2048
#define BINSCALE ((float)NB2/RCUT)
#define SCH  256                     // scan chunk
#define NBK  ((NN + SCH - 1)/SCH)    // blocks per half = 79

// ---------------- device scratch ------------------------------------------
static __device__ int   g_cnt;
static __device__ int   g_hist[2*NN];
static __device__ int   g_cur[2*NN];
static __device__ int   g_part[2*NBK];
static __device__ __align__(16) int2   g_Iij[EE];
static __device__ __align__(16) float4 g_Im[EE];
static __device__ __align__(16) int2   g_Jij[EE];
static __device__ __align__(16) float4 g_Jm[EE];

// filter tables: (G, G') interleaved per channel; sets: 0=(l0,p0) 1=(l0,p1) 2=(l1,p0) 3=(l1,p2)
static __device__ __align__(16) float2 g_tab0[(NB2+1)*CC];
static __device__ __align__(16) float2 g_tab1[(NB2+1)*CC];
static __device__ __align__(16) float2 g_tab2[(NB2+1)*CC];
static __device__ __align__(16) float2 g_tab3[(NB2+1)*CC];

static __device__ __align__(16) float g_h0a[NN*CC];
static __device__ __align__(16) float g_h0b[NN*CC];
static __device__ __align__(16) float g_h0c[NN*CC];
static __device__ __align__(16) float g_s0[NN*CC];
static __device__ __align__(16) float g_s1[NN*CC];
static __device__ __align__(16) float g_h1b[NN*3*CC];
static __device__ __align__(16) float g_M[NN*CC*4];      // M0 | M1
static __device__ __align__(16) float g_gM0[NN*CC];
static __device__ __align__(16) float g_gM1[NN*3*CC];
static __device__ __align__(16) float g_gA[NN*CC];
static __device__ __align__(16) float g_gB[NN*CC];
static __device__ __align__(16) float g_gh1[NN*3*CC];

__device__ __forceinline__ float warpRed(float v){
#pragma unroll
    for(int o=16;o>0;o>>=1) v += __shfl_xor_sync(FULLMASK, v, o);
    return v;
}

__device__ __forceinline__ void red2(float* addr, float a, float b){
    asm volatile("red.global.add.v2.f32 [%0], {%1, %2};"
                 :: "l"(addr), "f"(a), "f"(b) : "memory");
}

// ---------------- filter table build ---------------------------------------
__global__ void tabbuild_k(const float* __restrict__ Wr, const float* __restrict__ br)
{
    int idx = blockIdx.x*blockDim.x + threadIdx.x;
    const int per = (NB2+1)*CC;
    if(idx >= 4*per) return;
    int s = idx / per;
    int rem = idx - s*per;
    int bin = rem >> 6;
    int ch  = rem & 63;
    int l = (s >= 2) ? 1 : 0;
    int p = (s == 1) ? 1 : ((s == 3) ? 2 : 0);
    float d = (float)bin * (RCUT/(float)NB2);
    const float* W = Wr + ((l*4 + p)*NBF)*CC + ch;
    float pre = br[(l*4 + p)*CC + ch];
    float q = 0.f;
#pragma unroll
    for(int b=0;b<NBF;b++){
        float z = (d - b*CSP)/WIDTH;
        float rbf = expf(-z*z);
        float w = W[b*CC];
        pre = fmaf(rbf, w, pre);
        q   = fmaf(rbf*(-2.0f*z/WIDTH), w, q);
    }
    float fc  = (d < RCUT) ? 0.5f*(cosf(PI_F*d/RCUT) + 1.0f) : 0.f;
    float dfc = (d < RCUT) ? -0.5f*(PI_F/RCUT)*sinf(PI_F*d/RCUT) : 0.f;
    float2 out = make_float2(fc*pre, fc*q + dfc*pre);
    if(s == 0)      g_tab0[rem] = out;
    else if(s == 1) g_tab1[rem] = out;
    else if(s == 2) g_tab2[rem] = out;
    else            g_tab3[rem] = out;
}

// ---------------- embedding gather + M zero + F zero (fused) ---------------
__global__ void embed_zero_k(const float* __restrict__ emb, const int* __restrict__ z,
                             float* __restrict__ F)
{
    const int NH = NN*16;
    const int NM = NN*64;
    const int NF = NN*3;
    for(int idx = blockIdx.x*blockDim.x + threadIdx.x; idx < NH + NM;
        idx += gridDim.x*blockDim.x){
        if(idx < NH){
            int n = idx >> 4, q = idx & 15;
            int zn = __ldg(&z[n]);
            ((float4*)g_h0a)[idx] = ((const float4*)emb)[zn*16 + q];
        } else {
            ((float4*)g_M)[idx - NH] = make_float4(0.f,0.f,0.f,0.f);
        }
    }
    for(int idx = blockIdx.x*blockDim.x + threadIdx.x; idx < NF;
        idx += gridDim.x*blockDim.x) F[idx] = 0.f;
}

// ---------------- geometry pass 1: histograms ------------------------------
__global__ void geomA_k(const float* __restrict__ coord,
                        const int* __restrict__ ei, const int* __restrict__ ej)
{
    int e = blockIdx.x*blockDim.x + threadIdx.x;
    if(e >= EE) return;
    int i = ei[e], j = ej[e];
    float dx = coord[j*3+0] - coord[i*3+0];
    float dy = coord[j*3+1] - coord[i*3+1];
    float dz = coord[j*3+2] - coord[i*3+2];
    float d2 = dx*dx + dy*dy + dz*dz + 1e-12f;
    if(d2 < RCUT*RCUT){
        atomicAdd(&g_hist[i], 1);
        atomicAdd(&g_hist[NN+j], 1);
    }
}

// ---------------- multi-block scan -----------------------------------------
__device__ __forceinline__ int blockExclScan(int v, int tid, int* ws){
    int lane = tid & 31, w = tid >> 5;
    int inc = v;
#pragma unroll
    for(int o=1;o<32;o<<=1){
        int n = __shfl_up_sync(FULLMASK, inc, o);
        if(lane >= o) inc += n;
    }
    if(lane == 31) ws[w] = inc;
    __syncthreads();
    if(w == 0 && lane < 8){
        int x = ws[lane];
#pragma unroll
        for(int o=1;o<8;o<<=1){
            int n = __shfl_up_sync(0xff, x, o);
            if(lane >= o) x += n;
        }
        ws[lane] = x;
    }
    __syncthreads();
    int off = (w > 0) ? ws[w-1] : 0;
    return off + inc - v;
}

// Phase A: per-chunk sums
__global__ __launch_bounds__(SCH) void scanA_k()
{
    __shared__ int ws[8];
    int blk = blockIdx.x;           // 0..2*NBK-1
    int half = blk / NBK;
    int b = blk - half*NBK;
    int idx = b*SCH + threadIdx.x;
    int v = (idx < NN) ? g_hist[half*NN + idx] : 0;
    int excl = blockExclScan(v, threadIdx.x, ws);
    if(threadIdx.x == SCH-1) g_part[blk] = excl + v;
}

// Phase B: scan partials; rebase half 1; set g_cnt
__global__ __launch_bounds__(256) void scanB_k()
{
    __shared__ int ws[8];
    int t = threadIdx.x;
    int v = (t < 2*NBK) ? g_part[t] : 0;
    int excl = blockExclScan(v, t, ws);
    __shared__ int off1;
    if(t == NBK) off1 = excl;
    __syncthreads();
    if(t < 2*NBK) g_part[t] = (t >= NBK) ? (excl - off1) : excl;
    if(t == 0) g_cnt = off1;
}

// Phase C: final per-element offsets; re-zero hist
__global__ __launch_bounds__(SCH) void scanC_k()
{
    __shared__ int ws[8];
    int blk = blockIdx.x;
    int half = blk / NBK;
    int b = blk - half*NBK;
    int idx = b*SCH + threadIdx.x;
    int gi = half*NN + idx;
    int v = (idx < NN) ? g_hist[gi] : 0;
    int excl = blockExclScan(v, threadIdx.x, ws);
    if(idx < NN){
        g_cur[gi] = g_part[blk] + excl;
        g_hist[gi] = 0;
    }
}

// ---------------- geometry pass 2: write both sorted orders ----------------
__global__ void geomB_k(const float* __restrict__ coord,
                        const int* __restrict__ ei, const int* __restrict__ ej)
{
    int e = blockIdx.x*blockDim.x + threadIdx.x;
    if(e >= EE) return;
    int i = ei[e], j = ej[e];
    float dx = coord[j*3+0] - coord[i*3+0];
    float dy = coord[j*3+1] - coord[i*3+1];
    float dz = coord[j*3+2] - coord[i*3+2];
    float d2 = dx*dx + dy*dy + dz*dz + 1e-12f;
    if(d2 >= RCUT*RCUT) return;
    float d = sqrtf(d2);
    float inv = 1.0f/d;
    float4 m = make_float4(d, dx*inv, dy*inv, dz*inv);
    int2 ij = make_int2(i, j);
    int posI = atomicAdd(&g_cur[i], 1);
    g_Iij[posI] = ij;  g_Im[posI] = m;
    int posJ = atomicAdd(&g_cur[NN+j], 1);
    g_Jij[posJ] = ij;  g_Jm[posJ] = m;
}

// ---------------- forward layer-0 edge kernel (i-sorted) -------------------
__global__ __launch_bounds__(256) void edge_fwd0_k(const float* __restrict__ h0)
{
    int tid = threadIdx.x;
    int cnt = g_cnt;
    int e0 = (blockIdx.x*8 + (tid>>5))*EPW;
    if(e0 >= cnt) return;
    int lane = tid & 31;
    int c = 2*lane;
    int eend = min(e0 + EPW, cnt);
    const float4* T0 = (const float4*)g_tab0;
    const float4* T1 = (const float4*)g_tab1;

    float* M0 = g_M;
    float* M1 = g_M + NN*CC;
    float2 a0c = make_float2(0.f,0.f);
    float2 a1c[3] = {{0,0},{0,0},{0,0}};

    int2   ijn = g_Iij[e0];
    float4 mn  = g_Im[e0];
    float2 hn  = *(const float2*)&h0[ijn.y*64+c];
    float  tn  = mn.x*BINSCALE; int bn = (int)tn; float frn = tn - bn;
    float4 A0n = T0[bn*32+lane], A1n = T0[(bn+1)*32+lane];
    float4 B0n = T1[bn*32+lane], B1n = T1[(bn+1)*32+lane];
    int curi = ijn.x;

    for(int e=e0;e<eend;e++){
        int2 ij = ijn; float4 m = mn; float2 h0j = hn; float fr = frn;
        float4 A0 = A0n, A1 = A1n, B0 = B0n, B1 = B1n;
        if(e+1 < eend){
            ijn = g_Iij[e+1];
            mn  = g_Im[e+1];
            hn  = *(const float2*)&h0[ijn.y*64+c];
            tn = mn.x*BINSCALE; bn = (int)tn; frn = tn - bn;
            A0n = T0[bn*32+lane]; A1n = T0[(bn+1)*32+lane];
            B0n = T1[bn*32+lane]; B1n = T1[(bn+1)*32+lane];
        }
        if(ij.x != curi){
            red2(&M0[curi*64+c], a0c.x, a0c.y);
#pragma unroll
            for(int x=0;x<3;x++) red2(&M1[(curi*3+x)*64+c], a1c[x].x, a1c[x].y);
            a0c = make_float2(0.f,0.f);
#pragma unroll
            for(int x=0;x<3;x++) a1c[x] = make_float2(0.f,0.f);
            curi = ij.x;
        }
        float rh[3] = {m.y, m.z, m.w};
        float G0x = fmaf(fr, A1.x-A0.x, A0.x), G0y = fmaf(fr, A1.z-A0.z, A0.z);
        float G1x = fmaf(fr, B1.x-B0.x, B0.x), G1y = fmaf(fr, B1.z-B0.z, B0.z);
        a0c.x = fmaf(G0x, h0j.x, a0c.x);
        a0c.y = fmaf(G0y, h0j.y, a0c.y);
        float g1x = G1x*h0j.x, g1y = G1y*h0j.y;
#pragma unroll
        for(int x=0;x<3;x++){
            a1c[x].x = fmaf(g1x, rh[x], a1c[x].x);
            a1c[x].y = fmaf(g1y, rh[x], a1c[x].y);
        }
    }
    red2(&M0[curi*64+c], a0c.x, a0c.y);
#pragma unroll
    for(int x=0;x<3;x++) red2(&M1[(curi*3+x)*64+c], a1c[x].x, a1c[x].y);
}

// ---------------- forward layer-1 edge kernel (i-sorted) -------------------
__global__ __launch_bounds__(256) void edge_fwd1_k(
    const float* __restrict__ h0, const float* __restrict__ h1)
{
    int tid = threadIdx.x;
    int cnt = g_cnt;
    int e0 = (blockIdx.x*8 + (tid>>5))*EPW;
    if(e0 >= cnt) return;
    int lane = tid & 31;
    int c = 2*lane;
    int eend = min(e0 + EPW, cnt);
    const float4* T0 = (const float4*)g_tab2;
    const float4* T1 = (const float4*)g_tab3;

    float* M0 = g_M;
    float2 a0c = make_float2(0.f,0.f);

    int2   ijn = g_Iij[e0];
    float4 mn  = g_Im[e0];
    float2 hn  = *(const float2*)&h0[ijn.y*64+c];
    float2 vn0 = *(const float2*)&h1[(ijn.y*3+0)*64+c];
    float2 vn1 = *(const float2*)&h1[(ijn.y*3+1)*64+c];
    float2 vn2 = *(const float2*)&h1[(ijn.y*3+2)*64+c];
    float  tn  = mn.x*BINSCALE; int bn = (int)tn; float frn = tn - bn;
    float4 A0n = T0[bn*32+lane], A1n = T0[(bn+1)*32+lane];
    float4 B0n = T1[bn*32+lane], B1n = T1[(bn+1)*32+lane];
    int curi = ijn.x;

    for(int e=e0;e<eend;e++){
        int2 ij = ijn; float4 m = mn; float2 h0j = hn; float fr = frn;
        float2 v0 = vn0, v1 = vn1, v2 = vn2;
        float4 A0 = A0n, A1 = A1n, B0 = B0n, B1 = B1n;
        if(e+1 < eend){
            ijn = g_Iij[e+1];
            mn  = g_Im[e+1];
            hn  = *(const float2*)&h0[ijn.y*64+c];
            vn0 = *(const float2*)&h1[(ijn.y*3+0)*64+c];
            vn1 = *(const float2*)&h1[(ijn.y*3+1)*64+c];
            vn2 = *(const float2*)&h1[(ijn.y*3+2)*64+c];
            tn = mn.x*BINSCALE; bn = (int)tn; frn = tn - bn;
            A0n = T0[bn*32+lane]; A1n = T0[(bn+1)*32+lane];
            B0n = T1[bn*32+lane]; B1n = T1[(bn+1)*32+lane];
        }
        if(ij.x != curi){
            red2(&M0[curi*64+c], a0c.x, a0c.y);
            a0c = make_float2(0.f,0.f);
            curi = ij.x;
        }
        float rh[3] = {m.y, m.z, m.w};
        float G0x = fmaf(fr, A1.x-A0.x, A0.x), G0y = fmaf(fr, A1.z-A0.z, A0.z);
        float G2x = fmaf(fr, B1.x-B0.x, B0.x), G2y = fmaf(fr, B1.z-B0.z, B0.z);
        float tx = v0.x*rh[0] + v1.x*rh[1] + v2.x*rh[2];
        float ty = v0.y*rh[0] + v1.y*rh[1] + v2.y*rh[2];
        a0c.x += G0x*h0j.x + G2x*tx;
        a0c.y += G0y*h0j.y + G2y*ty;
    }
    red2(&M0[curi*64+c], a0c.x, a0c.y);
}

// ---------------- backward layer-0 (i-sorted; h1==0) -----------------------
__global__ __launch_bounds__(256) void edge_bwd0_k(
    const float* __restrict__ h0,
    const float* __restrict__ gM0, const float* __restrict__ gM1,
    float* __restrict__ F)
{
    int tid = threadIdx.x;
    int cnt = g_cnt;
    int e0 = (blockIdx.x*8 + (tid>>5))*EPW;
    if(e0 >= cnt) return;
    int lane = tid & 31;
    int c = 2*lane;
    int eend = min(e0 + EPW, cnt);
    const float4* T0 = (const float4*)g_tab0;
    const float4* T1 = (const float4*)g_tab1;

    int2   ijn = g_Iij[e0];
    float4 mn  = g_Im[e0];
    float2 hn  = *(const float2*)&h0[ijn.y*64+c];
    float  tn  = mn.x*BINSCALE; int bn = (int)tn; float frn = tn - bn;
    float4 A0n = T0[bn*32+lane], A1n = T0[(bn+1)*32+lane];
    float4 B0n = T1[bn*32+lane], B1n = T1[(bn+1)*32+lane];
    int curi = ijn.x;
    float2 gm0 = *(const float2*)&gM0[curi*64+c];
    float2 gm1[3];
#pragma unroll
    for(int x=0;x<3;x++) gm1[x] = *(const float2*)&gM1[(curi*3+x)*64+c];
    float fi = 0.f;

    for(int e=e0;e<eend;e++){
        int2 ij = ijn; float4 m = mn; float2 h0j = hn; float fr = frn;
        float4 A0 = A0n, A1 = A1n, B0 = B0n, B1 = B1n;
        if(e+1 < eend){
            ijn = g_Iij[e+1];
            mn  = g_Im[e+1];
            hn  = *(const float2*)&h0[ijn.y*64+c];
            tn = mn.x*BINSCALE; bn = (int)tn; frn = tn - bn;
            A0n = T0[bn*32+lane]; A1n = T0[(bn+1)*32+lane];
            B0n = T1[bn*32+lane]; B1n = T1[(bn+1)*32+lane];
        }
        if(ij.x != curi){
            if(lane < 3) atomicAdd(&F[curi*3+lane], fi);
            fi = 0.f;
            curi = ij.x;
            gm0 = *(const float2*)&gM0[curi*64+c];
#pragma unroll
            for(int x=0;x<3;x++) gm1[x] = *(const float2*)&gM1[(curi*3+x)*64+c];
        }
        int j = ij.y;
        float d = m.x;
        float rh[3] = {m.y, m.z, m.w};
        float G1x = fmaf(fr, B1.x-B0.x, B0.x), G1y = fmaf(fr, B1.z-B0.z, B0.z);
        float Q0x = fmaf(fr, A1.y-A0.y, A0.y), Q0y = fmaf(fr, A1.w-A0.w, A0.w);
        float Q1x = fmaf(fr, B1.y-B0.y, B0.y), Q1y = fmaf(fr, B1.w-B0.w, B0.w);

        float gmrx = gm1[0].x*rh[0] + gm1[1].x*rh[1] + gm1[2].x*rh[2];
        float gmry = gm1[0].y*rh[0] + gm1[1].y*rh[1] + gm1[2].y*rh[2];
        float gf0x = gm0.x*h0j.x, gf0y = gm0.y*h0j.y;
        float gf1x = gmrx*h0j.x,  gf1y = gmry*h0j.y;
        float sd = gf0x*Q0x + gf0y*Q0y + gf1x*Q1x + gf1y*Q1y;
        float f1x = G1x*h0j.x, f1y = G1y*h0j.y;
        float gr0 = gm1[0].x*f1x + gm1[0].y*f1y;
        float gr1 = gm1[1].x*f1x + gm1[1].y*f1y;
        float gr2 = gm1[2].x*f1x + gm1[2].y*f1y;

        sd  = warpRed(sd);
        gr0 = warpRed(gr0);
        gr1 = warpRed(gr1);
        gr2 = warpRed(gr2);

        float gdr = gr0*rh[0] + gr1*rh[1] + gr2*rh[2];
        float invd = 1.0f/d;
        if(lane < 3){
            float gx = (lane==0) ? gr0 : ((lane==1) ? gr1 : gr2);
            float rx = rh[lane];
            float grij = (gx - gdr*rx)*invd + sd*rx;
            fi += grij;
            atomicAdd(&F[j*3+lane], -grij);
        }
    }
    if(lane < 3) atomicAdd(&F[curi*3+lane], fi);
}

// ---------------- backward layer-1 (j-sorted) ------------------------------
__global__ __launch_bounds__(256) void edge_bwd1_k(
    const float* __restrict__ h0, const float* __restrict__ h1,
    const float* __restrict__ gM0,
    float* __restrict__ gh0, float* __restrict__ gh1, float* __restrict__ F)
{
    int tid = threadIdx.x;
    int cnt = g_cnt;
    int e0 = (blockIdx.x*8 + (tid>>5))*EPW;
    if(e0 >= cnt) return;
    int lane = tid & 31;
    int c = 2*lane;
    int eend = min(e0 + EPW, cnt);
    const float4* T0 = (const float4*)g_tab2;
    const float4* T1 = (const float4*)g_tab3;

    int2   ijn = g_Jij[e0];
    float4 mn  = g_Jm[e0];
    float2 gmn = *(const float2*)&gM0[ijn.x*64+c];
    float  tn  = mn.x*BINSCALE; int bn = (int)tn; float frn = tn - bn;
    float4 A0n = T0[bn*32+lane], A1n = T0[(bn+1)*32+lane];
    float4 B0n = T1[bn*32+lane], B1n = T1[(bn+1)*32+lane];
    int curj = ijn.y;
    float2 h0j = *(const float2*)&h0[curj*64+c];
    float2 v[3];
#pragma unroll
    for(int x=0;x<3;x++) v[x] = *(const float2*)&h1[(curj*3+x)*64+c];
    float2 acc0 = make_float2(0,0);
    float2 acc1[3] = {{0,0},{0,0},{0,0}};
    float fj = 0.f;

    for(int e=e0;e<eend;e++){
        int2 ij = ijn; float4 m = mn; float2 gm0 = gmn; float fr = frn;
        float4 A0 = A0n, A1 = A1n, B0 = B0n, B1 = B1n;
        if(e+1 < eend){
            ijn = g_Jij[e+1];
            mn  = g_Jm[e+1];
            gmn = *(const float2*)&gM0[ijn.x*64+c];
            tn = mn.x*BINSCALE; bn = (int)tn; frn = tn - bn;
            A0n = T0[bn*32+lane]; A1n = T0[(bn+1)*32+lane];
            B0n = T1[bn*32+lane]; B1n = T1[(bn+1)*32+lane];
        }
        if(ij.y != curj){
            red2(&gh0[curj*64+c], acc0.x, acc0.y);
#pragma unroll
            for(int x=0;x<3;x++) red2(&gh1[(curj*3+x)*64+c], acc1[x].x, acc1[x].y);
            if(lane < 3) atomicAdd(&F[curj*3+lane], fj);
            acc0 = make_float2(0,0);
#pragma unroll
            for(int x=0;x<3;x++) acc1[x] = make_float2(0,0);
            fj = 0.f;
            curj = ij.y;
            h0j = *(const float2*)&h0[curj*64+c];
#pragma unroll
            for(int x=0;x<3;x++) v[x] = *(const float2*)&h1[(curj*3+x)*64+c];
        }
        int i = ij.x;
        float d = m.x;
        float rh[3] = {m.y, m.z, m.w};
        float G0x = fmaf(fr, A1.x-A0.x, A0.x), G0y = fmaf(fr, A1.z-A0.z, A0.z);
        float G2x = fmaf(fr, B1.x-B0.x, B0.x), G2y = fmaf(fr, B1.z-B0.z, B0.z);
        float Q0x = fmaf(fr, A1.y-A0.y, A0.y), Q0y = fmaf(fr, A1.w-A0.w, A0.w);
        float Q2x = fmaf(fr, B1.y-B0.y, B0.y), Q2y = fmaf(fr, B1.w-B0.w, B0.w);

        float tx = v[0].x*rh[0] + v[1].x*rh[1] + v[2].x*rh[2];
        float ty = v[0].y*rh[0] + v[1].y*rh[1] + v[2].y*rh[2];
        float sd = gm0.x*(Q0x*h0j.x + Q2x*tx) + gm0.y*(Q0y*h0j.y + Q2y*ty);
        float f2x = G2x*gm0.x, f2y = G2y*gm0.y;
        float gr0 = f2x*v[0].x + f2y*v[0].y;
        float gr1 = f2x*v[1].x + f2y*v[1].y;
        float gr2 = f2x*v[2].x + f2y*v[2].y;

        acc0.x += gm0.x*G0x;
        acc0.y += gm0.y*G0y;
#pragma unroll
        for(int x=0;x<3;x++){
            acc1[x].x += f2x*rh[x];
            acc1[x].y += f2y*rh[x];
        }

        sd  = warpRed(sd);
        gr0 = warpRed(gr0);
        gr1 = warpRed(gr1);
        gr2 = warpRed(gr2);

        float gdr = gr0*rh[0] + gr1*rh[1] + gr2*rh[2];
        float invd = 1.0f/d;
        if(lane < 3){
            float gx = (lane==0) ? gr0 : ((lane==1) ? gr1 : gr2);
            float rx = rh[lane];
            float grij = (gx - gdr*rx)*invd + sd*rx;
            atomicAdd(&F[i*3+lane], grij);
            fj -= grij;
        }
    }
    red2(&gh0[curj*64+c], acc0.x, acc0.y);
#pragma unroll
    for(int x=0;x<3;x++) red2(&gh1[(curj*3+x)*64+c], acc1[x].x, acc1[x].y);
    if(lane < 3) atomicAdd(&F[curj*3+lane], fj);
}

// ---------------- node GEMM: out = epilogue(A@W1 [+ B@W2] [+ bias]) --------
__global__ __launch_bounds__(256) void mm_fwd(
    const float* __restrict__ A, const float* __restrict__ W1,
    const float* __restrict__ B, const float* __restrict__ W2,
    const float* __restrict__ bias, const float* __restrict__ ro2,
    float* __restrict__ out, float* __restrict__ sOut, int rows)
{
    __shared__ float sW[64*64];
    __shared__ float sX[128*64];
    int tid = threadIdx.x;
    int row0 = blockIdx.x*128;
    int tc = tid & 15, tr = tid >> 4;
    float acc[8][4];
    if(bias){
        float4 b = *(const float4*)&bias[4*tc];
#pragma unroll
        for(int i=0;i<8;i++){ acc[i][0]=b.x; acc[i][1]=b.y; acc[i][2]=b.z; acc[i][3]=b.w; }
    } else {
#pragma unroll
        for(int i=0;i<8;i++){ acc[i][0]=acc[i][1]=acc[i][2]=acc[i][3]=0.f; }
    }
    int nph = B ? 2 : 1;
    for(int ph=0; ph<nph; ph++){
        const float* Xp = ph ? B : A;
        const float* Wp = ph ? W2 : W1;
        if(ph) __syncthreads();
        for(int k=tid;k<4096;k+=256) sW[k] = Wp[k];
        for(int k=tid;k<8192;k+=256){
            int r = k>>6, c = k&63;
            int gr = row0 + r;
            sX[k] = (gr < rows) ? Xp[gr*64+c] : 0.f;
        }
        __syncthreads();
        const float* xr = &sX[(tr*8)*64];
#pragma unroll 4
        for(int k=0;k<64;k++){
            float4 w = *(const float4*)&sW[k*64 + tc*4];
            float a[8];
#pragma unroll
            for(int i=0;i<8;i++) a[i] = xr[i*64+k];
#pragma unroll
            for(int i=0;i<8;i++){
                acc[i][0]=fmaf(a[i],w.x,acc[i][0]);
                acc[i][1]=fmaf(a[i],w.y,acc[i][1]);
                acc[i][2]=fmaf(a[i],w.z,acc[i][2]);
                acc[i][3]=fmaf(a[i],w.w,acc[i][3]);
            }
        }
    }
    float4 ro2v = make_float4(0,0,0,0);
    if(ro2) ro2v = *(const float4*)&ro2[4*tc];
#pragma unroll
    for(int i=0;i<8;i++){
        int r = row0 + tr*8 + i;
        if(r >= rows) continue;
        float4 o;
        float* oo = &o.x;
#pragma unroll
        for(int jj=0;jj<4;jj++){
            float u = acc[i][jj];
            float val;
            if(ro2){
                float sig = 1.f/(1.f + expf(-u));
                float rr = (&ro2v.x)[jj];
                val = rr*sig*fmaf(u, 1.f-sig, 1.f);
            } else if(sOut){
                float sig = 1.f/(1.f + expf(-u));
                val = u*sig;
            } else {
                val = u;
            }
            oo[jj] = val;
        }
        if(sOut){
            float4 so = make_float4(acc[i][0],acc[i][1],acc[i][2],acc[i][3]);
            *(float4*)&sOut[r*64 + tc*4] = so;
        }
        *(float4*)&out[r*64 + tc*4] = o;
    }
}

// ---------------- node GEMM transposed with fused dsilu --------------------
__global__ __launch_bounds__(256) void mm_bwdT(
    const float* __restrict__ G, const float* __restrict__ S,
    const float* __restrict__ W1, const float* __restrict__ W2,
    float* __restrict__ out1, float* __restrict__ out2, int rows)
{
    __shared__ float sWt[64*68];
    __shared__ float sG[64*65];
    int tid = threadIdx.x;
    int row0 = blockIdx.x*64;
    int tc = tid & 15, tr = tid >> 4;
    for(int k=tid;k<4096;k+=256){
        int r = k>>6, c = k&63;
        int gr = row0 + r;
        float v = 0.f;
        if(gr < rows){
            float g = G[gr*64+c];
            if(S){
                float x = S[gr*64+c];
                float sig = 1.f/(1.f + expf(-x));
                v = g*sig*fmaf(x, 1.f-sig, 1.f);
            } else v = g;
        }
        sG[r*65+c] = v;
    }
    int nph = out2 ? 2 : 1;
    for(int ph=0; ph<nph; ph++){
        const float* Wp = ph ? W2 : W1;
        float* op = ph ? out2 : out1;
        if(ph) __syncthreads();
        for(int k=tid;k<4096;k+=256){
            int cout = k>>6, dd = k&63;
            sWt[dd*68+cout] = Wp[k];
        }
        __syncthreads();
        float acc[4][4];
#pragma unroll
        for(int i=0;i<4;i++){ acc[i][0]=acc[i][1]=acc[i][2]=acc[i][3]=0.f; }
        const float* xr = &sG[(tr*4)*65];
#pragma unroll 8
        for(int k=0;k<64;k++){
            float a0 = xr[k], a1 = xr[65+k], a2 = xr[130+k], a3 = xr[195+k];
            float4 w = *(const float4*)&sWt[k*68 + tc*4];
            acc[0][0]=fmaf(a0,w.x,acc[0][0]); acc[0][1]=fmaf(a0,w.y,acc[0][1]);
            acc[0][2]=fmaf(a0,w.z,acc[0][2]); acc[0][3]=fmaf(a0,w.w,acc[0][3]);
            acc[1][0]=fmaf(a1,w.x,acc[1][0]); acc[1][1]=fmaf(a1,w.y,acc[1][1]);
            acc[1][2]=fmaf(a1,w.z,acc[1][2]); acc[1][3]=fmaf(a1,w.w,acc[1][3]);
            acc[2][0]=fmaf(a2,w.x,acc[2][0]); acc[2][1]=fmaf(a2,w.y,acc[2][1]);
            acc[2][2]=fmaf(a2,w.z,acc[2][2]); acc[2][3]=fmaf(a2,w.w,acc[2][3]);
            acc[3][0]=fmaf(a3,w.x,acc[3][0]); acc[3][1]=fmaf(a3,w.y,acc[3][1]);
            acc[3][2]=fmaf(a3,w.z,acc[3][2]); acc[3][3]=fmaf(a3,w.w,acc[3][3]);
        }
#pragma unroll
        for(int i=0;i<4;i++){
            int r = row0 + tr*4 + i;
            if(r >= rows) continue;
            float4 o = make_float4(acc[i][0],acc[i][1],acc[i][2],acc[i][3]);
            *(float4*)&op[r*64 + tc*4] = o;
        }
    }
}

// ---------------- fused readout backward -----------------------------------
__global__ __launch_bounds__(256) void readout_k(
    const float* __restrict__ A, const float* __restrict__ Wro1,
    const float* __restrict__ bro1, const float* __restrict__ Wro2,
    float* __restrict__ gA, int rows)
{
    __shared__ float sW[64*68];
    __shared__ float sX[64*65];
    int tid = threadIdx.x;
    int row0 = blockIdx.x*64;
    int tc = tid & 15, tr = tid >> 4;
    for(int k=tid;k<4096;k+=256) sW[k] = Wro1[k];
    for(int k=tid;k<4096;k+=256){
        int r = k>>6, c = k&63;
        int gr = row0 + r;
        sX[r*65+c] = (gr < rows) ? A[gr*64+c] : 0.f;
    }
    __syncthreads();
    float acc[4][4];
    {
        float4 b = *(const float4*)&bro1[4*tc];
#pragma unroll
        for(int i=0;i<4;i++){ acc[i][0]=b.x; acc[i][1]=b.y; acc[i][2]=b.z; acc[i][3]=b.w; }
    }
    {
        const float* xr = &sX[(tr*4)*65];
#pragma unroll 8
        for(int k=0;k<64;k++){
            float a0 = xr[k], a1 = xr[65+k], a2 = xr[130+k], a3 = xr[195+k];
            float4 w = *(const float4*)&sW[k*64 + tc*4];
            acc[0][0]=fmaf(a0,w.x,acc[0][0]); acc[0][1]=fmaf(a0,w.y,acc[0][1]);
            acc[0][2]=fmaf(a0,w.z,acc[0][2]); acc[0][3]=fmaf(a0,w.w,acc[0][3]);
            acc[1][0]=fmaf(a1,w.x,acc[1][0]); acc[1][1]=fmaf(a1,w.y,acc[1][1]);
            acc[1][2]=fmaf(a1,w.z,acc[1][2]); acc[1][3]=fmaf(a1,w.w,acc[1][3]);
            acc[2][0]=fmaf(a2,w.x,acc[2][0]); acc[2][1]=fmaf(a2,w.y,acc[2][1]);
            acc[2][2]=fmaf(a2,w.z,acc[2][2]); acc[2][3]=fmaf(a2,w.w,acc[2][3]);
            acc[3][0]=fmaf(a3,w.x,acc[3][0]); acc[3][1]=fmaf(a3,w.y,acc[3][1]);
            acc[3][2]=fmaf(a3,w.z,acc[3][2]); acc[3][3]=fmaf(a3,w.w,acc[3][3]);
        }
    }
    __syncthreads();
    {
        float4 ro2v = *(const float4*)&Wro2[4*tc];
#pragma unroll
        for(int i=0;i<4;i++){
#pragma unroll
            for(int jj=0;jj<4;jj++){
                float u = acc[i][jj];
                float sig = 1.f/(1.f + expf(-u));
                float w = (&ro2v.x)[jj]*sig*fmaf(u, 1.f-sig, 1.f);
                sX[(tr*4+i)*65 + tc*4 + jj] = w;
            }
        }
    }
    for(int k=tid;k<4096;k+=256){
        int cout = k>>6, dd = k&63;
        sW[dd*68+cout] = Wro1[k];
    }
    __syncthreads();
    float acc2[4][4];
#pragma unroll
    for(int i=0;i<4;i++){ acc2[i][0]=acc2[i][1]=acc2[i][2]=acc2[i][3]=0.f; }
    {
        const float* xr = &sX[(tr*4)*65];
#pragma unroll 8
        for(int k=0;k<64;k++){
            float a0 = xr[k], a1 = xr[65+k], a2 = xr[130+k], a3 = xr[195+k];
            float4 w = *(const float4*)&sW[k*68 + tc*4];
            acc2[0][0]=fmaf(a0,w.x,acc2[0][0]); acc2[0][1]=fmaf(a0,w.y,acc2[0][1]);
            acc2[0][2]=fmaf(a0,w.z,acc2[0][2]); acc2[0][3]=fmaf(a0,w.w,acc2[0][3]);
            acc2[1][0]=fmaf(a1,w.x,acc2[1][0]); acc2[1][1]=fmaf(a1,w.y,acc2[1][1]);
            acc2[1][2]=fmaf(a1,w.z,acc2[1][2]); acc2[1][3]=fmaf(a1,w.w,acc2[1][3]);
            acc2[2][0]=fmaf(a2,w.x,acc2[2][0]); acc2[2][1]=fmaf(a2,w.y,acc2[2][1]);
            acc2[2][2]=fmaf(a2,w.z,acc2[2][2]); acc2[2][3]=fmaf(a2,w.w,acc2[2][3]);
            acc2[3][0]=fmaf(a3,w.x,acc2[3][0]); acc2[3][1]=fmaf(a3,w.y,acc2[3][1]);
            acc2[3][2]=fmaf(a3,w.z,acc2[3][2]); acc2[3][3]=fmaf(a3,w.w,acc2[3][3]);
        }
    }
#pragma unroll
    for(int i=0;i<4;i++){
        int r = row0 + tr*4 + i;
        if(r >= rows) continue;
        float4 o = make_float4(acc2[i][0],acc2[i][1],acc2[i][2],acc2[i][3]);
        *(float4*)&gA[r*64 + tc*4] = o;
    }
}

// ---------------- host orchestration ---------------------------------------
extern "C" void kernel_launch(void* const* d_in, const int* in_sizes, int n_in,
                              void* d_out, int out_size)
{
    const float* coord  = (const float*)d_in[0];
    const float* emb    = (const float*)d_in[1];
    const float* Wr     = (const float*)d_in[2];
    const float* br     = (const float*)d_in[3];
    const float* Wself0 = (const float*)d_in[4];
    const float* Wmsg0  = (const float*)d_in[5];
    const float* b0     = (const float*)d_in[6];
    const float* Wmsg1  = (const float*)d_in[7];
    const float* Wro1   = (const float*)d_in[9];
    const float* bro1   = (const float*)d_in[10];
    const float* Wro2   = (const float*)d_in[11];
    const int*   z      = (const int*)d_in[13];
    const int*   ei     = (const int*)d_in[14];
    const int*   ej     = (const int*)d_in[15];
    float* F = (float*)d_out;
    (void)in_sizes; (void)n_in; (void)out_size;

    float *h0a,*h0b,*h0c,*s0,*s1,*h1b,*Mbuf,*gM0p,*gM1p,*gA,*gB,*gh1;
    cudaGetSymbolAddress((void**)&h0a, g_h0a);
    cudaGetSymbolAddress((void**)&h0b, g_h0b);
    cudaGetSymbolAddress((void**)&h0c, g_h0c);
    cudaGetSymbolAddress((void**)&s0,  g_s0);
    cudaGetSymbolAddress((void**)&s1,  g_s1);
    cudaGetSymbolAddress((void**)&h1b, g_h1b);
    cudaGetSymbolAddress((void**)&Mbuf,g_M);
    cudaGetSymbolAddress((void**)&gM0p,g_gM0);
    cudaGetSymbolAddress((void**)&gM1p,g_gM1);
    cudaGetSymbolAddress((void**)&gA,  g_gA);
    cudaGetSymbolAddress((void**)&gB,  g_gB);
    cudaGetSymbolAddress((void**)&gh1, g_gh1);
    float* M0 = Mbuf;
    float* M1 = Mbuf + NN*CC;

    const int EB  = (EE + EPB-1)/EPB;
    const int G1  = (NN + 127)/128;
    const int G3  = (3*NN + 127)/128;
    const int T1  = (NN + 63)/64;
    const int T3  = (3*NN + 63)/64;
    const int TABN = 4*(NB2+1)*CC;

    tabbuild_k<<<(TABN+255)/256, 256>>>(Wr, br);
    embed_zero_k<<<1024, 256>>>(emb, z, F);
    geomA_k<<<(EE+255)/256, 256>>>(coord, ei, ej);
    scanA_k<<<2*NBK, SCH>>>();
    scanB_k<<<1, 256>>>();
    scanC_k<<<2*NBK, SCH>>>();
    geomB_k<<<(EE+255)/256, 256>>>(coord, ei, ej);

    // ---- layer 0 forward
    edge_fwd0_k<<<EB, 256>>>(h0a);
    mm_fwd<<<G3, 256>>>(M1, Wmsg1, nullptr, nullptr, nullptr, nullptr, h1b, nullptr, 3*NN);
    mm_fwd<<<G1, 256>>>(M0, Wmsg0, h0a, Wself0, b0, nullptr, h0b, s0, NN);
    cudaMemsetAsync(M0, 0, NN*CC*sizeof(float));
    cudaMemsetAsync(gh1, 0, NN*3*CC*sizeof(float));

    // ---- layer 1 forward (M1/h1 outputs dead)
    edge_fwd1_k<<<EB, 256>>>(h0b, h1b);
    mm_fwd<<<G1, 256>>>(M0, Wmsg0 + 4096, h0b, Wself0 + 4096, b0 + 64, nullptr, h0c, s1, NN);

    // ---- readout backward (fused)
    readout_k<<<T1, 256>>>(h0c, Wro1, bro1, Wro2, gA, NN);

    // ---- layer 1 backward (j-sorted scatter)
    mm_bwdT<<<T1, 256>>>(gA, s1, Wmsg0 + 4096, Wself0 + 4096, gM0p, gB, NN);
    edge_bwd1_k<<<EB, 256>>>(h0b, h1b, gM0p, gB, gh1, F);

    // ---- layer 0 backward (i-sorted)
    mm_bwdT<<<T1, 256>>>(gB, s0, Wmsg0, nullptr, gM0p, nullptr, NN);
    mm_bwdT<<<T3, 256>>>(gh1, nullptr, Wmsg1, nullptr, gM1p, nullptr, 3*NN);
    edge_bwd0_k<<<EB, 256>>>(h0a, gM0p, gM1p, F);
}

// round 10
// speedup vs baseline: 1.3138x; 1.0589x over previous
#include <cuda_runtime.h>
#include <math.h>

#define NN   20000
#define EE   320000
#define CC   64
#define NBF  16
#define RCUT 5.0f
#define CSP  (RCUT/(NBF-1))
#define WIDTH (RCUT/NBF)
#define PI_F 3.14159265358979f
#define FULLMASK 0xffffffffu
#define EPW  16
#define EPB  (8*EPW)
#define NB2  2048
#define BINSCALE ((float)NB2/RCUT)
#define SCH  256
#define NBK  ((NN + SCH - 1)/SCH)
#define T1B  ((NN + 63)/64)
#define T3B  ((3*NN + 63)/64)

// ---------------- device scratch ------------------------------------------
static __device__ int   g_cnt;
static __device__ int   g_hist[2*NN];
static __device__ int   g_cur[2*NN];
static __device__ int   g_part[2*NBK];
static __device__ __align__(16) int2   g_Iij[EE];
static __device__ __align__(16) float4 g_Im[EE];
static __device__ __align__(16) int2   g_Jij[EE];
static __device__ __align__(16) float4 g_Jm[EE];

static __device__ __align__(16) float2 g_tab0[(NB2+1)*CC];
static __device__ __align__(16) float2 g_tab1[(NB2+1)*CC];
static __device__ __align__(16) float2 g_tab2[(NB2+1)*CC];
static __device__ __align__(16) float2 g_tab3[(NB2+1)*CC];

static __device__ __align__(16) float g_h0a[NN*CC];
static __device__ __align__(16) float g_h0b[NN*CC];
static __device__ __align__(16) float g_s0[NN*CC];
static __device__ __align__(16) float g_h1b[NN*3*CC];
static __device__ __align__(16) float g_M[NN*CC*4];      // M0 | M1
static __device__ __align__(16) float g_gM0[NN*CC];
static __device__ __align__(16) float g_gM1[NN*3*CC];
static __device__ __align__(16) float g_gB[NN*CC];
static __device__ __align__(16) float g_gh1[NN*3*CC];

__device__ __forceinline__ float warpRed(float v){
#pragma unroll
    for(int o=16;o>0;o>>=1) v += __shfl_xor_sync(FULLMASK, v, o);
    return v;
}

__device__ __forceinline__ void red2(float* addr, float a, float b){
    asm volatile("red.global.add.v2.f32 [%0], {%1, %2};"
                 :: "l"(addr), "f"(a), "f"(b) : "memory");
}

__device__ __forceinline__ void dot64(const float* xr, const float* sw, int ws,
                                      float acc[4][4], int tc){
#pragma unroll 8
    for(int k=0;k<64;k++){
        float a0 = xr[k], a1 = xr[65+k], a2 = xr[130+k], a3 = xr[195+k];
        float4 w = *(const float4*)&sw[k*ws + tc*4];
        acc[0][0]=fmaf(a0,w.x,acc[0][0]); acc[0][1]=fmaf(a0,w.y,acc[0][1]);
        acc[0][2]=fmaf(a0,w.z,acc[0][2]); acc[0][3]=fmaf(a0,w.w,acc[0][3]);
        acc[1][0]=fmaf(a1,w.x,acc[1][0]); acc[1][1]=fmaf(a1,w.y,acc[1][1]);
        acc[1][2]=fmaf(a1,w.z,acc[1][2]); acc[1][3]=fmaf(a1,w.w,acc[1][3]);
        acc[2][0]=fmaf(a2,w.x,acc[2][0]); acc[2][1]=fmaf(a2,w.y,acc[2][1]);
        acc[2][2]=fmaf(a2,w.z,acc[2][2]); acc[2][3]=fmaf(a2,w.w,acc[2][3]);
        acc[3][0]=fmaf(a3,w.x,acc[3][0]); acc[3][1]=fmaf(a3,w.y,acc[3][1]);
        acc[3][2]=fmaf(a3,w.z,acc[3][2]); acc[3][3]=fmaf(a3,w.w,acc[3][3]);
    }
}

// ---------------- filter table build ---------------------------------------
__global__ void tabbuild_k(const float* __restrict__ Wr, const float* __restrict__ br)
{
    int idx = blockIdx.x*blockDim.x + threadIdx.x;
    const int per = (NB2+1)*CC;
    if(idx >= 4*per) return;
    int s = idx / per;
    int rem = idx - s*per;
    int bin = rem >> 6;
    int ch  = rem & 63;
    int l = (s >= 2) ? 1 : 0;
    int p = (s == 1) ? 1 : ((s == 3) ? 2 : 0);
    float d = (float)bin * (RCUT/(float)NB2);
    const float* W = Wr + ((l*4 + p)*NBF)*CC + ch;
    float pre = br[(l*4 + p)*CC + ch];
    float q = 0.f;
#pragma unroll
    for(int b=0;b<NBF;b++){
        float z = (d - b*CSP)/WIDTH;
        float rbf = expf(-z*z);
        float w = W[b*CC];
        pre = fmaf(rbf, w, pre);
        q   = fmaf(rbf*(-2.0f*z/WIDTH), w, q);
    }
    float fc  = (d < RCUT) ? 0.5f*(cosf(PI_F*d/RCUT) + 1.0f) : 0.f;
    float dfc = (d < RCUT) ? -0.5f*(PI_F/RCUT)*sinf(PI_F*d/RCUT) : 0.f;
    float2 out = make_float2(fc*pre, fc*q + dfc*pre);
    if(s == 0)      g_tab0[rem] = out;
    else if(s == 1) g_tab1[rem] = out;
    else if(s == 2) g_tab2[rem] = out;
    else            g_tab3[rem] = out;
}

// ---------------- embedding gather + M zero + F zero (fused) ---------------
__global__ void embed_zero_k(const float* __restrict__ emb, const int* __restrict__ z,
                             float* __restrict__ F)
{
    const int NH = NN*16;
    const int NM = NN*64;
    const int NF = NN*3;
    for(int idx = blockIdx.x*blockDim.x + threadIdx.x; idx < NH + NM;
        idx += gridDim.x*blockDim.x){
        if(idx < NH){
            int n = idx >> 4, q = idx & 15;
            int zn = __ldg(&z[n]);
            ((float4*)g_h0a)[idx] = ((const float4*)emb)[zn*16 + q];
        } else {
            ((float4*)g_M)[idx - NH] = make_float4(0.f,0.f,0.f,0.f);
        }
    }
    for(int idx = blockIdx.x*blockDim.x + threadIdx.x; idx < NF;
        idx += gridDim.x*blockDim.x) F[idx] = 0.f;
}

// ---------------- geometry pass 1: histograms ------------------------------
__global__ void geomA_k(const float* __restrict__ coord,
                        const int* __restrict__ ei, const int* __restrict__ ej)
{
    int e = blockIdx.x*blockDim.x + threadIdx.x;
    if(e >= EE) return;
    int i = ei[e], j = ej[e];
    float dx = coord[j*3+0] - coord[i*3+0];
    float dy = coord[j*3+1] - coord[i*3+1];
    float dz = coord[j*3+2] - coord[i*3+2];
    float d2 = dx*dx + dy*dy + dz*dz + 1e-12f;
    if(d2 < RCUT*RCUT){
        atomicAdd(&g_hist[i], 1);
        atomicAdd(&g_hist[NN+j], 1);
    }
}

// ---------------- multi-block scan -----------------------------------------
__device__ __forceinline__ int blockExclScan(int v, int tid, int* ws){
    int lane = tid & 31, w = tid >> 5;
    int inc = v;
#pragma unroll
    for(int o=1;o<32;o<<=1){
        int n = __shfl_up_sync(FULLMASK, inc, o);
        if(lane >= o) inc += n;
    }
    if(lane == 31) ws[w] = inc;
    __syncthreads();
    if(w == 0 && lane < 8){
        int x = ws[lane];
#pragma unroll
        for(int o=1;o<8;o<<=1){
            int n = __shfl_up_sync(0xff, x, o);
            if(lane >= o) x += n;
        }
        ws[lane] = x;
    }
    __syncthreads();
    int off = (w > 0) ? ws[w-1] : 0;
    return off + inc - v;
}

__global__ __launch_bounds__(SCH) void scanA_k()
{
    __shared__ int ws[8];
    int blk = blockIdx.x;
    int half = blk / NBK;
    int b = blk - half*NBK;
    int idx = b*SCH + threadIdx.x;
    int v = (idx < NN) ? g_hist[half*NN + idx] : 0;
    int excl = blockExclScan(v, threadIdx.x, ws);
    if(threadIdx.x == SCH-1) g_part[blk] = excl + v;
}

__global__ __launch_bounds__(256) void scanB_k()
{
    __shared__ int ws[8];
    int t = threadIdx.x;
    int v = (t < 2*NBK) ? g_part[t] : 0;
    int excl = blockExclScan(v, t, ws);
    __shared__ int off1;
    if(t == NBK) off1 = excl;
    __syncthreads();
    if(t < 2*NBK) g_part[t] = (t >= NBK) ? (excl - off1) : excl;
    if(t == 0) g_cnt = off1;
}

__global__ __launch_bounds__(SCH) void scanC_k()
{
    __shared__ int ws[8];
    int blk = blockIdx.x;
    int half = blk / NBK;
    int b = blk - half*NBK;
    int idx = b*SCH + threadIdx.x;
    int gi = half*NN + idx;
    int v = (idx < NN) ? g_hist[gi] : 0;
    int excl = blockExclScan(v, threadIdx.x, ws);
    if(idx < NN){
        g_cur[gi] = g_part[blk] + excl;
        g_hist[gi] = 0;
    }
}

// ---------------- geometry pass 2 ------------------------------------------
__global__ void geomB_k(const float* __restrict__ coord,
                        const int* __restrict__ ei, const int* __restrict__ ej)
{
    int e = blockIdx.x*blockDim.x + threadIdx.x;
    if(e >= EE) return;
    int i = ei[e], j = ej[e];
    float dx = coord[j*3+0] - coord[i*3+0];
    float dy = coord[j*3+1] - coord[i*3+1];
    float dz = coord[j*3+2] - coord[i*3+2];
    float d2 = dx*dx + dy*dy + dz*dz + 1e-12f;
    if(d2 >= RCUT*RCUT) return;
    float d = sqrtf(d2);
    float inv = 1.0f/d;
    float4 m = make_float4(d, dx*inv, dy*inv, dz*inv);
    int2 ij = make_int2(i, j);
    int posI = atomicAdd(&g_cur[i], 1);
    g_Iij[posI] = ij;  g_Im[posI] = m;
    int posJ = atomicAdd(&g_cur[NN+j], 1);
    g_Jij[posJ] = ij;  g_Jm[posJ] = m;
}

// ---------------- forward layer-0 edge kernel (i-sorted) -------------------
__global__ __launch_bounds__(256) void edge_fwd0_k(const float* __restrict__ h0)
{
    int tid = threadIdx.x;
    int cnt = g_cnt;
    int e0 = (blockIdx.x*8 + (tid>>5))*EPW;
    if(e0 >= cnt) return;
    int lane = tid & 31;
    int c = 2*lane;
    int eend = min(e0 + EPW, cnt);
    const float4* T0 = (const float4*)g_tab0;
    const float4* T1 = (const float4*)g_tab1;

    float* M0 = g_M;
    float* M1 = g_M + NN*CC;
    float2 a0c = make_float2(0.f,0.f);
    float2 a1c[3] = {{0,0},{0,0},{0,0}};

    int2   ijn = g_Iij[e0];
    float4 mn  = g_Im[e0];
    float2 hn  = *(const float2*)&h0[ijn.y*64+c];
    float  tn  = mn.x*BINSCALE; int bn = (int)tn; float frn = tn - bn;
    float4 A0n = T0[bn*32+lane], A1n = T0[(bn+1)*32+lane];
    float4 B0n = T1[bn*32+lane], B1n = T1[(bn+1)*32+lane];
    int curi = ijn.x;

    for(int e=e0;e<eend;e++){
        int2 ij = ijn; float4 m = mn; float2 h0j = hn; float fr = frn;
        float4 A0 = A0n, A1 = A1n, B0 = B0n, B1 = B1n;
        if(e+1 < eend){
            ijn = g_Iij[e+1];
            mn  = g_Im[e+1];
            hn  = *(const float2*)&h0[ijn.y*64+c];
            tn = mn.x*BINSCALE; bn = (int)tn; frn = tn - bn;
            A0n = T0[bn*32+lane]; A1n = T0[(bn+1)*32+lane];
            B0n = T1[bn*32+lane]; B1n = T1[(bn+1)*32+lane];
        }
        if(ij.x != curi){
            red2(&M0[curi*64+c], a0c.x, a0c.y);
#pragma unroll
            for(int x=0;x<3;x++) red2(&M1[(curi*3+x)*64+c], a1c[x].x, a1c[x].y);
            a0c = make_float2(0.f,0.f);
#pragma unroll
            for(int x=0;x<3;x++) a1c[x] = make_float2(0.f,0.f);
            curi = ij.x;
        }
        float rh[3] = {m.y, m.z, m.w};
        float G0x = fmaf(fr, A1.x-A0.x, A0.x), G0y = fmaf(fr, A1.z-A0.z, A0.z);
        float G1x = fmaf(fr, B1.x-B0.x, B0.x), G1y = fmaf(fr, B1.z-B0.z, B0.z);
        a0c.x = fmaf(G0x, h0j.x, a0c.x);
        a0c.y = fmaf(G0y, h0j.y, a0c.y);
        float g1x = G1x*h0j.x, g1y = G1y*h0j.y;
#pragma unroll
        for(int x=0;x<3;x++){
            a1c[x].x = fmaf(g1x, rh[x], a1c[x].x);
            a1c[x].y = fmaf(g1y, rh[x], a1c[x].y);
        }
    }
    red2(&M0[curi*64+c], a0c.x, a0c.y);
#pragma unroll
    for(int x=0;x<3;x++) red2(&M1[(curi*3+x)*64+c], a1c[x].x, a1c[x].y);
}

// ---------------- forward layer-1 edge kernel (i-sorted) -------------------
__global__ __launch_bounds__(256) void edge_fwd1_k(
    const float* __restrict__ h0, const float* __restrict__ h1)
{
    int tid = threadIdx.x;
    int cnt = g_cnt;
    int e0 = (blockIdx.x*8 + (tid>>5))*EPW;
    if(e0 >= cnt) return;
    int lane = tid & 31;
    int c = 2*lane;
    int eend = min(e0 + EPW, cnt);
    const float4* T0 = (const float4*)g_tab2;
    const float4* T1 = (const float4*)g_tab3;

    float* M0 = g_M;
    float2 a0c = make_float2(0.f,0.f);

    int2   ijn = g_Iij[e0];
    float4 mn  = g_Im[e0];
    float2 hn  = *(const float2*)&h0[ijn.y*64+c];
    float2 vn0 = *(const float2*)&h1[(ijn.y*3+0)*64+c];
    float2 vn1 = *(const float2*)&h1[(ijn.y*3+1)*64+c];
    float2 vn2 = *(const float2*)&h1[(ijn.y*3+2)*64+c];
    float  tn  = mn.x*BINSCALE; int bn = (int)tn; float frn = tn - bn;
    float4 A0n = T0[bn*32+lane], A1n = T0[(bn+1)*32+lane];
    float4 B0n = T1[bn*32+lane], B1n = T1[(bn+1)*32+lane];
    int curi = ijn.x;

    for(int e=e0;e<eend;e++){
        int2 ij = ijn; float4 m = mn; float2 h0j = hn; float fr = frn;
        float2 v0 = vn0, v1 = vn1, v2 = vn2;
        float4 A0 = A0n, A1 = A1n, B0 = B0n, B1 = B1n;
        if(e+1 < eend){
            ijn = g_Iij[e+1];
            mn  = g_Im[e+1];
            hn  = *(const float2*)&h0[ijn.y*64+c];
            vn0 = *(const float2*)&h1[(ijn.y*3+0)*64+c];
            vn1 = *(const float2*)&h1[(ijn.y*3+1)*64+c];
            vn2 = *(const float2*)&h1[(ijn.y*3+2)*64+c];
            tn = mn.x*BINSCALE; bn = (int)tn; frn = tn - bn;
            A0n = T0[bn*32+lane]; A1n = T0[(bn+1)*32+lane];
            B0n = T1[bn*32+lane]; B1n = T1[(bn+1)*32+lane];
        }
        if(ij.x != curi){
            red2(&M0[curi*64+c], a0c.x, a0c.y);
            a0c = make_float2(0.f,0.f);
            curi = ij.x;
        }
        float rh[3] = {m.y, m.z, m.w};
        float G0x = fmaf(fr, A1.x-A0.x, A0.x), G0y = fmaf(fr, A1.z-A0.z, A0.z);
        float G2x = fmaf(fr, B1.x-B0.x, B0.x), G2y = fmaf(fr, B1.z-B0.z, B0.z);
        float tx = v0.x*rh[0] + v1.x*rh[1] + v2.x*rh[2];
        float ty = v0.y*rh[0] + v1.y*rh[1] + v2.y*rh[2];
        a0c.x += G0x*h0j.x + G2x*tx;
        a0c.y += G0y*h0j.y + G2y*ty;
    }
    red2(&M0[curi*64+c], a0c.x, a0c.y);
}

// ---------------- backward layer-0 (i-sorted; h1==0) -----------------------
__global__ __launch_bounds__(256) void edge_bwd0_k(
    const float* __restrict__ h0,
    const float* __restrict__ gM0, const float* __restrict__ gM1,
    float* __restrict__ F)
{
    int tid = threadIdx.x;
    int cnt = g_cnt;
    int e0 = (blockIdx.x*8 + (tid>>5))*EPW;
    if(e0 >= cnt) return;
    int lane = tid & 31;
    int c = 2*lane;
    int eend = min(e0 + EPW, cnt);
    const float4* T0 = (const float4*)g_tab0;
    const float4* T1 = (const float4*)g_tab1;

    int2   ijn = g_Iij[e0];
    float4 mn  = g_Im[e0];
    float2 hn  = *(const float2*)&h0[ijn.y*64+c];
    float  tn  = mn.x*BINSCALE; int bn = (int)tn; float frn = tn - bn;
    float4 A0n = T0[bn*32+lane], A1n = T0[(bn+1)*32+lane];
    float4 B0n = T1[bn*32+lane], B1n = T1[(bn+1)*32+lane];
    int curi = ijn.x;
    float2 gm0 = *(const float2*)&gM0[curi*64+c];
    float2 gm1[3];
#pragma unroll
    for(int x=0;x<3;x++) gm1[x] = *(const float2*)&gM1[(curi*3+x)*64+c];
    float fi = 0.f;

    for(int e=e0;e<eend;e++){
        int2 ij = ijn; float4 m = mn; float2 h0j = hn; float fr = frn;
        float4 A0 = A0n, A1 = A1n, B0 = B0n, B1 = B1n;
        if(e+1 < eend){
            ijn = g_Iij[e+1];
            mn  = g_Im[e+1];
            hn  = *(const float2*)&h0[ijn.y*64+c];
            tn = mn.x*BINSCALE; bn = (int)tn; frn = tn - bn;
            A0n = T0[bn*32+lane]; A1n = T0[(bn+1)*32+lane];
            B0n = T1[bn*32+lane]; B1n = T1[(bn+1)*32+lane];
        }
        if(ij.x != curi){
            if(lane < 3) atomicAdd(&F[curi*3+lane], fi);
            fi = 0.f;
            curi = ij.x;
            gm0 = *(const float2*)&gM0[curi*64+c];
#pragma unroll
            for(int x=0;x<3;x++) gm1[x] = *(const float2*)&gM1[(curi*3+x)*64+c];
        }
        int j = ij.y;
        float d = m.x;
        float rh[3] = {m.y, m.z, m.w};
        float G1x = fmaf(fr, B1.x-B0.x, B0.x), G1y = fmaf(fr, B1.z-B0.z, B0.z);
        float Q0x = fmaf(fr, A1.y-A0.y, A0.y), Q0y = fmaf(fr, A1.w-A0.w, A0.w);
        float Q1x = fmaf(fr, B1.y-B0.y, B0.y), Q1y = fmaf(fr, B1.w-B0.w, B0.w);

        float gmrx = gm1[0].x*rh[0] + gm1[1].x*rh[1] + gm1[2].x*rh[2];
        float gmry = gm1[0].y*rh[0] + gm1[1].y*rh[1] + gm1[2].y*rh[2];
        float gf0x = gm0.x*h0j.x, gf0y = gm0.y*h0j.y;
        float gf1x = gmrx*h0j.x,  gf1y = gmry*h0j.y;
        float sd = gf0x*Q0x + gf0y*Q0y + gf1x*Q1x + gf1y*Q1y;
        float f1x = G1x*h0j.x, f1y = G1y*h0j.y;
        float gr0 = gm1[0].x*f1x + gm1[0].y*f1y;
        float gr1 = gm1[1].x*f1x + gm1[1].y*f1y;
        float gr2 = gm1[2].x*f1x + gm1[2].y*f1y;

        sd  = warpRed(sd);
        gr0 = warpRed(gr0);
        gr1 = warpRed(gr1);
        gr2 = warpRed(gr2);

        float gdr = gr0*rh[0] + gr1*rh[1] + gr2*rh[2];
        float invd = 1.0f/d;
        if(lane < 3){
            float gx = (lane==0) ? gr0 : ((lane==1) ? gr1 : gr2);
            float rx = rh[lane];
            float grij = (gx - gdr*rx)*invd + sd*rx;
            fi += grij;
            atomicAdd(&F[j*3+lane], -grij);
        }
    }
    if(lane < 3) atomicAdd(&F[curi*3+lane], fi);
}

// ---------------- backward layer-1 (j-sorted) ------------------------------
__global__ __launch_bounds__(256) void edge_bwd1_k(
    const float* __restrict__ h0, const float* __restrict__ h1,
    const float* __restrict__ gM0,
    float* __restrict__ gh0, float* __restrict__ gh1, float* __restrict__ F)
{
    int tid = threadIdx.x;
    int cnt = g_cnt;
    int e0 = (blockIdx.x*8 + (tid>>5))*EPW;
    if(e0 >= cnt) return;
    int lane = tid & 31;
    int c = 2*lane;
    int eend = min(e0 + EPW, cnt);
    const float4* T0 = (const float4*)g_tab2;
    const float4* T1 = (const float4*)g_tab3;

    int2   ijn = g_Jij[e0];
    float4 mn  = g_Jm[e0];
    float2 gmn = *(const float2*)&gM0[ijn.x*64+c];
    float  tn  = mn.x*BINSCALE; int bn = (int)tn; float frn = tn - bn;
    float4 A0n = T0[bn*32+lane], A1n = T0[(bn+1)*32+lane];
    float4 B0n = T1[bn*32+lane], B1n = T1[(bn+1)*32+lane];
    int curj = ijn.y;
    float2 h0j = *(const float2*)&h0[curj*64+c];
    float2 v[3];
#pragma unroll
    for(int x=0;x<3;x++) v[x] = *(const float2*)&h1[(curj*3+x)*64+c];
    float2 acc0 = make_float2(0,0);
    float2 acc1[3] = {{0,0},{0,0},{0,0}};
    float fj = 0.f;

    for(int e=e0;e<eend;e++){
        int2 ij = ijn; float4 m = mn; float2 gm0 = gmn; float fr = frn;
        float4 A0 = A0n, A1 = A1n, B0 = B0n, B1 = B1n;
        if(e+1 < eend){
            ijn = g_Jij[e+1];
            mn  = g_Jm[e+1];
            gmn = *(const float2*)&gM0[ijn.x*64+c];
            tn = mn.x*BINSCALE; bn = (int)tn; frn = tn - bn;
            A0n = T0[bn*32+lane]; A1n = T0[(bn+1)*32+lane];
            B0n = T1[bn*32+lane]; B1n = T1[(bn+1)*32+lane];
        }
        if(ij.y != curj){
            red2(&gh0[curj*64+c], acc0.x, acc0.y);
#pragma unroll
            for(int x=0;x<3;x++) red2(&gh1[(curj*3+x)*64+c], acc1[x].x, acc1[x].y);
            if(lane < 3) atomicAdd(&F[curj*3+lane], fj);
            acc0 = make_float2(0,0);
#pragma unroll
            for(int x=0;x<3;x++) acc1[x] = make_float2(0,0);
            fj = 0.f;
            curj = ij.y;
            h0j = *(const float2*)&h0[curj*64+c];
#pragma unroll
            for(int x=0;x<3;x++) v[x] = *(const float2*)&h1[(curj*3+x)*64+c];
        }
        int i = ij.x;
        float d = m.x;
        float rh[3] = {m.y, m.z, m.w};
        float G0x = fmaf(fr, A1.x-A0.x, A0.x), G0y = fmaf(fr, A1.z-A0.z, A0.z);
        float G2x = fmaf(fr, B1.x-B0.x, B0.x), G2y = fmaf(fr, B1.z-B0.z, B0.z);
        float Q0x = fmaf(fr, A1.y-A0.y, A0.y), Q0y = fmaf(fr, A1.w-A0.w, A0.w);
        float Q2x = fmaf(fr, B1.y-B0.y, B0.y), Q2y = fmaf(fr, B1.w-B0.w, B0.w);

        float tx = v[0].x*rh[0] + v[1].x*rh[1] + v[2].x*rh[2];
        float ty = v[0].y*rh[0] + v[1].y*rh[1] + v[2].y*rh[2];
        float sd = gm0.x*(Q0x*h0j.x + Q2x*tx) + gm0.y*(Q0y*h0j.y + Q2y*ty);
        float f2x = G2x*gm0.x, f2y = G2y*gm0.y;
        float gr0 = f2x*v[0].x + f2y*v[0].y;
        float gr1 = f2x*v[1].x + f2y*v[1].y;
        float gr2 = f2x*v[2].x + f2y*v[2].y;

        acc0.x += gm0.x*G0x;
        acc0.y += gm0.y*G0y;
#pragma unroll
        for(int x=0;x<3;x++){
            acc1[x].x += f2x*rh[x];
            acc1[x].y += f2y*rh[x];
        }

        sd  = warpRed(sd);
        gr0 = warpRed(gr0);
        gr1 = warpRed(gr1);
        gr2 = warpRed(gr2);

        float gdr = gr0*rh[0] + gr1*rh[1] + gr2*rh[2];
        float invd = 1.0f/d;
        if(lane < 3){
            float gx = (lane==0) ? gr0 : ((lane==1) ? gr1 : gr2);
            float rx = rh[lane];
            float grij = (gx - gdr*rx)*invd + sd*rx;
            atomicAdd(&F[i*3+lane], grij);
            fj -= grij;
        }
    }
    red2(&gh0[curj*64+c], acc0.x, acc0.y);
#pragma unroll
    for(int x=0;x<3;x++) red2(&gh1[(curj*3+x)*64+c], acc1[x].x, acc1[x].y);
    if(lane < 3) atomicAdd(&F[curj*3+lane], fj);
}

// ---------------- node GEMM (layer-0 fwd + h1b) ----------------------------
__global__ __launch_bounds__(256) void mm_fwd(
    const float* __restrict__ A, const float* __restrict__ W1,
    const float* __restrict__ B, const float* __restrict__ W2,
    const float* __restrict__ bias,
    float* __restrict__ out, float* __restrict__ sOut, int rows)
{
    __shared__ float sW[64*64];
    __shared__ float sX[128*64];
    int tid = threadIdx.x;
    int row0 = blockIdx.x*128;
    int tc = tid & 15, tr = tid >> 4;
    float acc[8][4];
    if(bias){
        float4 b = *(const float4*)&bias[4*tc];
#pragma unroll
        for(int i=0;i<8;i++){ acc[i][0]=b.x; acc[i][1]=b.y; acc[i][2]=b.z; acc[i][3]=b.w; }
    } else {
#pragma unroll
        for(int i=0;i<8;i++){ acc[i][0]=acc[i][1]=acc[i][2]=acc[i][3]=0.f; }
    }
    int nph = B ? 2 : 1;
    for(int ph=0; ph<nph; ph++){
        const float* Xp = ph ? B : A;
        const float* Wp = ph ? W2 : W1;
        if(ph) __syncthreads();
        for(int k=tid;k<4096;k+=256) sW[k] = Wp[k];
        for(int k=tid;k<8192;k+=256){
            int r = k>>6, c = k&63;
            int gr = row0 + r;
            sX[k] = (gr < rows) ? Xp[gr*64+c] : 0.f;
        }
        __syncthreads();
        const float* xr = &sX[(tr*8)*64];
#pragma unroll 4
        for(int k=0;k<64;k++){
            float4 w = *(const float4*)&sW[k*64 + tc*4];
            float a[8];
#pragma unroll
            for(int i=0;i<8;i++) a[i] = xr[i*64+k];
#pragma unroll
            for(int i=0;i<8;i++){
                acc[i][0]=fmaf(a[i],w.x,acc[i][0]);
                acc[i][1]=fmaf(a[i],w.y,acc[i][1]);
                acc[i][2]=fmaf(a[i],w.z,acc[i][2]);
                acc[i][3]=fmaf(a[i],w.w,acc[i][3]);
            }
        }
    }
#pragma unroll
    for(int i=0;i<8;i++){
        int r = row0 + tr*8 + i;
        if(r >= rows) continue;
        float4 o;
        float* oo = &o.x;
#pragma unroll
        for(int jj=0;jj<4;jj++){
            float u = acc[i][jj];
            float val;
            if(sOut){
                float sig = 1.f/(1.f + expf(-u));
                val = u*sig;
            } else {
                val = u;
            }
            oo[jj] = val;
        }
        if(sOut){
            float4 so = make_float4(acc[i][0],acc[i][1],acc[i][2],acc[i][3]);
            *(float4*)&sOut[r*64 + tc*4] = so;
        }
        *(float4*)&out[r*64 + tc*4] = o;
    }
}

// ---------------- fused layer-1 forward + readout + backward ---------------
// u1 = M0@Wmsg + h0b@Wself + b; h0c=silu(u1)
// u2 = h0c@Wro1 + bro1; w = Wro2*silu'(u2); gA = w@Wro1^T
// ds = gA*silu'(u1); gM0 = ds@Wmsg^T; gB = ds@Wself^T
__global__ __launch_bounds__(256) void l1_fused_k(
    const float* __restrict__ M0,    const float* __restrict__ h0b,
    const float* __restrict__ Wmsg,  const float* __restrict__ Wself,
    const float* __restrict__ bias,
    const float* __restrict__ Wro1,  const float* __restrict__ bro1,
    const float* __restrict__ Wro2,
    float* __restrict__ gM0, float* __restrict__ gB, int rows)
{
    __shared__ float sW[64*68];
    __shared__ float sX[64*65];
    int tid = threadIdx.x;
    int row0 = blockIdx.x*64;
    int tc = tid & 15, tr = tid >> 4;

    float acc[4][4], u1[4][4];
    {
        float4 b = *(const float4*)&bias[4*tc];
#pragma unroll
        for(int i=0;i<4;i++){ acc[i][0]=b.x; acc[i][1]=b.y; acc[i][2]=b.z; acc[i][3]=b.w; }
    }
    // phase 1: M0@Wmsg
    for(int k=tid;k<4096;k+=256) sW[k] = Wmsg[k];
    for(int k=tid;k<4096;k+=256){
        int r = k>>6, c = k&63;
        int gr = row0 + r;
        sX[r*65+c] = (gr < rows) ? M0[gr*64+c] : 0.f;
    }
    __syncthreads();
    dot64(&sX[(tr*4)*65], sW, 64, acc, tc);
    __syncthreads();
    // phase 2: + h0b@Wself
    for(int k=tid;k<4096;k+=256) sW[k] = Wself[k];
    for(int k=tid;k<4096;k+=256){
        int r = k>>6, c = k&63;
        int gr = row0 + r;
        sX[r*65+c] = (gr < rows) ? h0b[gr*64+c] : 0.f;
    }
    __syncthreads();
    dot64(&sX[(tr*4)*65], sW, 64, acc, tc);
#pragma unroll
    for(int i=0;i<4;i++)
#pragma unroll
        for(int jj=0;jj<4;jj++) u1[i][jj] = acc[i][jj];
    __syncthreads();
    // phase 3: silu(u1)@Wro1 + bro1
    for(int k=tid;k<4096;k+=256) sW[k] = Wro1[k];
#pragma unroll
    for(int i=0;i<4;i++)
#pragma unroll
        for(int jj=0;jj<4;jj++){
            float u = u1[i][jj];
            float sig = 1.f/(1.f + expf(-u));
            sX[(tr*4+i)*65 + tc*4 + jj] = u*sig;
        }
    {
        float4 b = *(const float4*)&bro1[4*tc];
#pragma unroll
        for(int i=0;i<4;i++){ acc[i][0]=b.x; acc[i][1]=b.y; acc[i][2]=b.z; acc[i][3]=b.w; }
    }
    __syncthreads();
    dot64(&sX[(tr*4)*65], sW, 64, acc, tc);
    __syncthreads();
    // phase 4: w = Wro2*silu'(u2); gA = w@Wro1^T
    {
        float4 ro2v = *(const float4*)&Wro2[4*tc];
#pragma unroll
        for(int i=0;i<4;i++)
#pragma unroll
            for(int jj=0;jj<4;jj++){
                float u = acc[i][jj];
                float sig = 1.f/(1.f + expf(-u));
                sX[(tr*4+i)*65 + tc*4 + jj] = (&ro2v.x)[jj]*sig*fmaf(u, 1.f-sig, 1.f);
            }
    }
    for(int k=tid;k<4096;k+=256){
        int cout = k>>6, dd = k&63;
        sW[dd*68+cout] = Wro1[k];
    }
    __syncthreads();
#pragma unroll
    for(int i=0;i<4;i++){ acc[i][0]=acc[i][1]=acc[i][2]=acc[i][3]=0.f; }
    dot64(&sX[(tr*4)*65], sW, 68, acc, tc);
    __syncthreads();
    // phase 5: ds = gA*silu'(u1); gM0 = ds@Wmsg^T
#pragma unroll
    for(int i=0;i<4;i++)
#pragma unroll
        for(int jj=0;jj<4;jj++){
            float u = u1[i][jj];
            float sig = 1.f/(1.f + expf(-u));
            sX[(tr*4+i)*65 + tc*4 + jj] = acc[i][jj]*sig*fmaf(u, 1.f-sig, 1.f);
        }
    for(int k=tid;k<4096;k+=256){
        int cout = k>>6, dd = k&63;
        sW[dd*68+cout] = Wmsg[k];
    }
    __syncthreads();
#pragma unroll
    for(int i=0;i<4;i++){ acc[i][0]=acc[i][1]=acc[i][2]=acc[i][3]=0.f; }
    dot64(&sX[(tr*4)*65], sW, 68, acc, tc);
#pragma unroll
    for(int i=0;i<4;i++){
        int r = row0 + tr*4 + i;
        if(r >= rows) continue;
        *(float4*)&gM0[r*64 + tc*4] = make_float4(acc[i][0],acc[i][1],acc[i][2],acc[i][3]);
    }
    __syncthreads();
    // phase 6: gB = ds@Wself^T  (sX unchanged)
    for(int k=tid;k<4096;k+=256){
        int cout = k>>6, dd = k&63;
        sW[dd*68+cout] = Wself[k];
    }
    __syncthreads();
#pragma unroll
    for(int i=0;i<4;i++){ acc[i][0]=acc[i][1]=acc[i][2]=acc[i][3]=0.f; }
    dot64(&sX[(tr*4)*65], sW, 68, acc, tc);
#pragma unroll
    for(int i=0;i<4;i++){
        int r = row0 + tr*4 + i;
        if(r >= rows) continue;
        *(float4*)&gB[r*64 + tc*4] = make_float4(acc[i][0],acc[i][1],acc[i][2],acc[i][3]);
    }
}

// ---------------- combined layer-0 backward GEMMs --------------------------
// blocks [0,T1B): gM0 = (gB*dsilu(s0))@Wmsg0^T  over NN rows
// blocks [T1B,T1B+T3B): gM1 = gh1@Wmsg1^T       over 3NN rows
__global__ __launch_bounds__(256) void bwd0mm_k(
    const float* __restrict__ gB, const float* __restrict__ s0,
    const float* __restrict__ Wmsg0, float* __restrict__ gM0,
    const float* __restrict__ gh1, const float* __restrict__ Wmsg1,
    float* __restrict__ gM1)
{
    __shared__ float sWt[64*68];
    __shared__ float sG[64*65];
    int tid = threadIdx.x;
    int blk = blockIdx.x;
    const float *G, *S, *W; float* out; int rows, row0;
    if(blk < T1B){ G = gB;  S = s0;      W = Wmsg0; out = gM0; rows = NN;   row0 = blk*64; }
    else         { G = gh1; S = nullptr; W = Wmsg1; out = gM1; rows = 3*NN; row0 = (blk-T1B)*64; }
    int tc = tid & 15, tr = tid >> 4;
    for(int k=tid;k<4096;k+=256){
        int r = k>>6, c = k&63;
        int gr = row0 + r;
        float v = 0.f;
        if(gr < rows){
            float g = G[gr*64+c];
            if(S){
                float x = S[gr*64+c];
                float sig = 1.f/(1.f + expf(-x));
                v = g*sig*fmaf(x, 1.f-sig, 1.f);
            } else v = g;
        }
        sG[r*65+c] = v;
    }
    for(int k=tid;k<4096;k+=256){
        int cout = k>>6, dd = k&63;
        sWt[dd*68+cout] = W[k];
    }
    __syncthreads();
    float acc[4][4];
#pragma unroll
    for(int i=0;i<4;i++){ acc[i][0]=acc[i][1]=acc[i][2]=acc[i][3]=0.f; }
    dot64(&sG[(tr*4)*65], sWt, 68, acc, tc);
#pragma unroll
    for(int i=0;i<4;i++){
        int r = row0 + tr*4 + i;
        if(r >= rows) continue;
        *(float4*)&out[r*64 + tc*4] = make_float4(acc[i][0],acc[i][1],acc[i][2],acc[i][3]);
    }
}

// ---------------- host orchestration ---------------------------------------
extern "C" void kernel_launch(void* const* d_in, const int* in_sizes, int n_in,
                              void* d_out, int out_size)
{
    const float* coord  = (const float*)d_in[0];
    const float* emb    = (const float*)d_in[1];
    const float* Wr     = (const float*)d_in[2];
    const float* br     = (const float*)d_in[3];
    const float* Wself0 = (const float*)d_in[4];
    const float* Wmsg0  = (const float*)d_in[5];
    const float* b0     = (const float*)d_in[6];
    const float* Wmsg1  = (const float*)d_in[7];
    const float* Wro1   = (const float*)d_in[9];
    const float* bro1   = (const float*)d_in[10];
    const float* Wro2   = (const float*)d_in[11];
    const int*   z      = (const int*)d_in[13];
    const int*   ei     = (const int*)d_in[14];
    const int*   ej     = (const int*)d_in[15];
    float* F = (float*)d_out;
    (void)in_sizes; (void)n_in; (void)out_size;

    float *h0a,*h0b,*s0,*h1b,*Mbuf,*gM0p,*gM1p,*gB,*gh1;
    cudaGetSymbolAddress((void**)&h0a, g_h0a);
    cudaGetSymbolAddress((void**)&h0b, g_h0b);
    cudaGetSymbolAddress((void**)&s0,  g_s0);
    cudaGetSymbolAddress((void**)&h1b, g_h1b);
    cudaGetSymbolAddress((void**)&Mbuf,g_M);
    cudaGetSymbolAddress((void**)&gM0p,g_gM0);
    cudaGetSymbolAddress((void**)&gM1p,g_gM1);
    cudaGetSymbolAddress((void**)&gB,  g_gB);
    cudaGetSymbolAddress((void**)&gh1, g_gh1);
    float* M0 = Mbuf;
    float* M1 = Mbuf + NN*CC;

    const int EB  = (EE + EPB-1)/EPB;
    const int G1  = (NN + 127)/128;
    const int G3  = (3*NN + 127)/128;
    const int TABN = 4*(NB2+1)*CC;

    tabbuild_k<<<(TABN+255)/256, 256>>>(Wr, br);
    embed_zero_k<<<1024, 256>>>(emb, z, F);
    geomA_k<<<(EE+255)/256, 256>>>(coord, ei, ej);
    scanA_k<<<2*NBK, SCH>>>();
    scanB_k<<<1, 256>>>();
    scanC_k<<<2*NBK, SCH>>>();
    geomB_k<<<(EE+255)/256, 256>>>(coord, ei, ej);

    // ---- layer 0 forward
    edge_fwd0_k<<<EB, 256>>>(h0a);
    mm_fwd<<<G3, 256>>>(M1, Wmsg1, nullptr, nullptr, nullptr, h1b, nullptr, 3*NN);
    mm_fwd<<<G1, 256>>>(M0, Wmsg0, h0a, Wself0, b0, h0b, s0, NN);
    cudaMemsetAsync(M0, 0, NN*CC*sizeof(float));
    cudaMemsetAsync(gh1, 0, NN*3*CC*sizeof(float));

    // ---- layer 1 forward (edge) + fused node fwd/readout/backward
    edge_fwd1_k<<<EB, 256>>>(h0b, h1b);
    l1_fused_k<<<T1B, 256>>>(M0, h0b, Wmsg0 + 4096, Wself0 + 4096, b0 + 64,
                             Wro1, bro1, Wro2, gM0p, gB, NN);

    // ---- layer 1 backward (j-sorted scatter)
    edge_bwd1_k<<<EB, 256>>>(h0b, h1b, gM0p, gB, gh1, F);

    // ---- layer 0 backward (combined GEMMs + i-sorted edge)
    bwd0mm_k<<<T1B + T3B, 256>>>(gB, s0, Wmsg0, gM0p, gh1, Wmsg1, gM1p);
    edge_bwd0_k<<<EB, 256>>>(h0a, gM0p, gM1p, F);
}

// round 12
// speedup vs baseline: 1.3781x; 1.0490x over previous
#include <cuda_runtime.h>
#include <math.h>

#define NN   20000
#define EE   320000
#define CC   64
#define NBF  16
#define RCUT 5.0f
#define CSP  (RCUT/(NBF-1))
#define WIDTH (RCUT/NBF)
#define PI_F 3.14159265358979f
#define FULLMASK 0xffffffffu
#define EPW  16
#define EPB  (8*EPW)
#define NB2  2048
#define BINSCALE ((float)NB2/RCUT)
#define SCH  256
#define NBK  ((NN + SCH - 1)/SCH)
#define T1B  ((NN + 63)/64)
#define T3B  ((3*NN + 63)/64)
#define G1B  ((NN + 127)/128)
#define G3B  ((3*NN + 127)/128)

// ---------------- device scratch ------------------------------------------
static __device__ int   g_cnt;
static __device__ int   g_hist[2*NN];
static __device__ int   g_cur[2*NN];
static __device__ int   g_part[2*NBK];
static __device__ __align__(16) int2   g_Iij[EE];
static __device__ __align__(16) float4 g_Im[EE];
static __device__ __align__(16) int2   g_Jij[EE];
static __device__ __align__(16) float4 g_Jm[EE];

// value+slope tables: F[s][bin*CC+ch] = (G, dG), Q[s][...] = (G', dG')
// sets: 0=(l0,p0) 1=(l0,p1) 2=(l1,p0) 3=(l1,p2)
static __device__ __align__(16) float2 g_F[4][NB2*CC];
static __device__ __align__(16) float2 g_Q[4][NB2*CC];

static __device__ __align__(16) float g_h0a[NN*CC];
static __device__ __align__(16) float g_h0b[NN*CC];
static __device__ __align__(16) float g_s0[NN*CC];
static __device__ __align__(16) float g_h1b[NN*3*CC];
static __device__ __align__(16) float g_M[NN*CC*4];      // M0 | (M1 ~ gh1 aliased)
static __device__ __align__(16) float g_gM0[NN*CC];
static __device__ __align__(16) float g_gM1[NN*3*CC];
static __device__ __align__(16) float g_gB[NN*CC];

__device__ __forceinline__ float warpRed(float v){
#pragma unroll
    for(int o=16;o>0;o>>=1) v += __shfl_xor_sync(FULLMASK, v, o);
    return v;
}

__device__ __forceinline__ void red2(float* addr, float a, float b){
    asm volatile("red.global.add.v2.f32 [%0], {%1, %2};"
                 :: "l"(addr), "f"(a), "f"(b) : "memory");
}

__device__ __forceinline__ void dot64(const float* xr, const float* sw, int ws,
                                      float acc[4][4], int tc){
#pragma unroll 8
    for(int k=0;k<64;k++){
        float a0 = xr[k], a1 = xr[65+k], a2 = xr[130+k], a3 = xr[195+k];
        float4 w = *(const float4*)&sw[k*ws + tc*4];
        acc[0][0]=fmaf(a0,w.x,acc[0][0]); acc[0][1]=fmaf(a0,w.y,acc[0][1]);
        acc[0][2]=fmaf(a0,w.z,acc[0][2]); acc[0][3]=fmaf(a0,w.w,acc[0][3]);
        acc[1][0]=fmaf(a1,w.x,acc[1][0]); acc[1][1]=fmaf(a1,w.y,acc[1][1]);
        acc[1][2]=fmaf(a1,w.z,acc[1][2]); acc[1][3]=fmaf(a1,w.w,acc[1][3]);
        acc[2][0]=fmaf(a2,w.x,acc[2][0]); acc[2][1]=fmaf(a2,w.y,acc[2][1]);
        acc[2][2]=fmaf(a2,w.z,acc[2][2]); acc[2][3]=fmaf(a2,w.w,acc[2][3]);
        acc[3][0]=fmaf(a3,w.x,acc[3][0]); acc[3][1]=fmaf(a3,w.y,acc[3][1]);
        acc[3][2]=fmaf(a3,w.z,acc[3][2]); acc[3][3]=fmaf(a3,w.w,acc[3][3]);
    }
}

// ---------------- filter table build (value + slope) -----------------------
__global__ void tabbuild_k(const float* __restrict__ Wr, const float* __restrict__ br)
{
    int idx = blockIdx.x*blockDim.x + threadIdx.x;
    const int per = NB2*CC;
    if(idx >= 4*per) return;
    int s = idx / per;
    int rem = idx - s*per;
    int l = (s >= 2) ? 1 : 0;
    int p = (s == 1) ? 1 : ((s == 3) ? 2 : 0);
    int bin = rem >> 6;
    int ch  = rem & 63;
    const float hstep = RCUT/(float)NB2;
    const float* W = Wr + ((l*4 + p)*NBF)*CC + ch;
    float bias = br[(l*4 + p)*CC + ch];
    float d0 = (float)bin * hstep;
    float d1 = d0 + hstep;
    float pre0 = bias, q0 = 0.f, pre1 = bias, q1 = 0.f;
#pragma unroll
    for(int b=0;b<NBF;b++){
        float w = W[b*CC];
        float z0 = (d0 - b*CSP)/WIDTH;
        float r0 = expf(-z0*z0);
        pre0 = fmaf(r0, w, pre0);
        q0   = fmaf(r0*(-2.0f*z0/WIDTH), w, q0);
        float z1 = (d1 - b*CSP)/WIDTH;
        float r1 = expf(-z1*z1);
        pre1 = fmaf(r1, w, pre1);
        q1   = fmaf(r1*(-2.0f*z1/WIDTH), w, q1);
    }
    float fc0  = 0.5f*(cosf(PI_F*d0/RCUT) + 1.0f);
    float dfc0 = -0.5f*(PI_F/RCUT)*sinf(PI_F*d0/RCUT);
    float G0 = fc0*pre0;
    float Q0 = fc0*q0 + dfc0*pre0;
    float G1 = 0.f, Q1 = 0.f;
    if(d1 < RCUT){
        float fc1  = 0.5f*(cosf(PI_F*d1/RCUT) + 1.0f);
        float dfc1 = -0.5f*(PI_F/RCUT)*sinf(PI_F*d1/RCUT);
        G1 = fc1*pre1;
        Q1 = fc1*q1 + dfc1*pre1;
    }
    g_F[s][rem] = make_float2(G0, G1 - G0);
    g_Q[s][rem] = make_float2(Q0, Q1 - Q0);
}

// ---------------- embedding gather + M zero + F zero (fused) ---------------
__global__ void embed_zero_k(const float* __restrict__ emb, const int* __restrict__ z,
                             float* __restrict__ F)
{
    const int NH = NN*16;
    const int NM = NN*64;
    const int NF = NN*3;
    for(int idx = blockIdx.x*blockDim.x + threadIdx.x; idx < NH + NM;
        idx += gridDim.x*blockDim.x){
        if(idx < NH){
            int n = idx >> 4, q = idx & 15;
            int zn = __ldg(&z[n]);
            ((float4*)g_h0a)[idx] = ((const float4*)emb)[zn*16 + q];
        } else {
            ((float4*)g_M)[idx - NH] = make_float4(0.f,0.f,0.f,0.f);
        }
    }
    for(int idx = blockIdx.x*blockDim.x + threadIdx.x; idx < NF;
        idx += gridDim.x*blockDim.x) F[idx] = 0.f;
}

// ---------------- geometry pass 1: histograms ------------------------------
__global__ void geomA_k(const float* __restrict__ coord,
                        const int* __restrict__ ei, const int* __restrict__ ej)
{
    int e = blockIdx.x*blockDim.x + threadIdx.x;
    if(e >= EE) return;
    int i = ei[e], j = ej[e];
    float dx = coord[j*3+0] - coord[i*3+0];
    float dy = coord[j*3+1] - coord[i*3+1];
    float dz = coord[j*3+2] - coord[i*3+2];
    float d2 = dx*dx + dy*dy + dz*dz + 1e-12f;
    if(d2 < RCUT*RCUT){
        atomicAdd(&g_hist[i], 1);
        atomicAdd(&g_hist[NN+j], 1);
    }
}

// ---------------- multi-block scan -----------------------------------------
__device__ __forceinline__ int blockExclScan(int v, int tid, int* ws){
    int lane = tid & 31, w = tid >> 5;
    int inc = v;
#pragma unroll
    for(int o=1;o<32;o<<=1){
        int n = __shfl_up_sync(FULLMASK, inc, o);
        if(lane >= o) inc += n;
    }
    if(lane == 31) ws[w] = inc;
    __syncthreads();
    if(w == 0 && lane < 8){
        int x = ws[lane];
#pragma unroll
        for(int o=1;o<8;o<<=1){
            int n = __shfl_up_sync(0xff, x, o);
            if(lane >= o) x += n;
        }
        ws[lane] = x;
    }
    __syncthreads();
    int off = (w > 0) ? ws[w-1] : 0;
    return off + inc - v;
}

__global__ __launch_bounds__(SCH) void scanA_k()
{
    __shared__ int ws[8];
    int blk = blockIdx.x;
    int half = blk / NBK;
    int b = blk - half*NBK;
    int idx = b*SCH + threadIdx.x;
    int v = (idx < NN) ? g_hist[half*NN + idx] : 0;
    int excl = blockExclScan(v, threadIdx.x, ws);
    if(threadIdx.x == SCH-1) g_part[blk] = excl + v;
}

__global__ __launch_bounds__(256) void scanB_k()
{
    __shared__ int ws[8];
    int t = threadIdx.x;
    int v = (t < 2*NBK) ? g_part[t] : 0;
    int excl = blockExclScan(v, t, ws);
    __shared__ int off1;
    if(t == NBK) off1 = excl;
    __syncthreads();
    if(t < 2*NBK) g_part[t] = (t >= NBK) ? (excl - off1) : excl;
    if(t == 0) g_cnt = off1;
}

__global__ __launch_bounds__(SCH) void scanC_k()
{
    __shared__ int ws[8];
    int blk = blockIdx.x;
    int half = blk / NBK;
    int b = blk - half*NBK;
    int idx = b*SCH + threadIdx.x;
    int gi = half*NN + idx;
    int v = (idx < NN) ? g_hist[gi] : 0;
    int excl = blockExclScan(v, threadIdx.x, ws);
    if(idx < NN){
        g_cur[gi] = g_part[blk] + excl;
        g_hist[gi] = 0;
    }
}

// ---------------- geometry pass 2 ------------------------------------------
__global__ void geomB_k(const float* __restrict__ coord,
                        const int* __restrict__ ei, const int* __restrict__ ej)
{
    int e = blockIdx.x*blockDim.x + threadIdx.x;
    if(e >= EE) return;
    int i = ei[e], j = ej[e];
    float dx = coord[j*3+0] - coord[i*3+0];
    float dy = coord[j*3+1] - coord[i*3+1];
    float dz = coord[j*3+2] - coord[i*3+2];
    float d2 = dx*dx + dy*dy + dz*dz + 1e-12f;
    if(d2 >= RCUT*RCUT) return;
    float d = sqrtf(d2);
    float inv = 1.0f/d;
    float4 m = make_float4(d, dx*inv, dy*inv, dz*inv);
    int2 ij = make_int2(i, j);
    int posI = atomicAdd(&g_cur[i], 1);
    g_Iij[posI] = ij;  g_Im[posI] = m;
    int posJ = atomicAdd(&g_cur[NN+j], 1);
    g_Jij[posJ] = ij;  g_Jm[posJ] = m;
}

// lerp from value+slope float4: (v0, s0, v1, s1) for channels (2l, 2l+1)
#define LERP2(P, fr, ox, oy) { ox = fmaf(fr, (P).y, (P).x); oy = fmaf(fr, (P).w, (P).z); }

// ---------------- forward layer-0 edge kernel (i-sorted) -------------------
__global__ __launch_bounds__(256) void edge_fwd0_k(const float* __restrict__ h0)
{
    int tid = threadIdx.x;
    int cnt = g_cnt;
    int e0 = (blockIdx.x*8 + (tid>>5))*EPW;
    if(e0 >= cnt) return;
    int lane = tid & 31;
    int c = 2*lane;
    int eend = min(e0 + EPW, cnt);
    const float4* F0t = (const float4*)g_F[0];
    const float4* F1t = (const float4*)g_F[1];

    float* M0 = g_M;
    float* M1 = g_M + NN*CC;
    float2 a0c = make_float2(0.f,0.f);
    float2 a1c[3] = {{0,0},{0,0},{0,0}};

    int2   ijn = g_Iij[e0];
    float4 mn  = g_Im[e0];
    float2 hn  = *(const float2*)&h0[ijn.y*64+c];
    float  tn  = mn.x*BINSCALE; int bn = (int)tn; float frn = tn - bn;
    float4 P0n = F0t[bn*32+lane];
    float4 P1n = F1t[bn*32+lane];
    int curi = ijn.x;

    for(int e=e0;e<eend;e++){
        int2 ij = ijn; float4 m = mn; float2 h0j = hn; float fr = frn;
        float4 P0 = P0n, P1 = P1n;
        if(e+1 < eend){
            ijn = g_Iij[e+1];
            mn  = g_Im[e+1];
            hn  = *(const float2*)&h0[ijn.y*64+c];
            tn = mn.x*BINSCALE; bn = (int)tn; frn = tn - bn;
            P0n = F0t[bn*32+lane];
            P1n = F1t[bn*32+lane];
        }
        if(ij.x != curi){
            red2(&M0[curi*64+c], a0c.x, a0c.y);
#pragma unroll
            for(int x=0;x<3;x++) red2(&M1[(curi*3+x)*64+c], a1c[x].x, a1c[x].y);
            a0c = make_float2(0.f,0.f);
#pragma unroll
            for(int x=0;x<3;x++) a1c[x] = make_float2(0.f,0.f);
            curi = ij.x;
        }
        float rh[3] = {m.y, m.z, m.w};
        float G0x, G0y, G1x, G1y;
        LERP2(P0, fr, G0x, G0y);
        LERP2(P1, fr, G1x, G1y);
        a0c.x = fmaf(G0x, h0j.x, a0c.x);
        a0c.y = fmaf(G0y, h0j.y, a0c.y);
        float g1x = G1x*h0j.x, g1y = G1y*h0j.y;
#pragma unroll
        for(int x=0;x<3;x++){
            a1c[x].x = fmaf(g1x, rh[x], a1c[x].x);
            a1c[x].y = fmaf(g1y, rh[x], a1c[x].y);
        }
    }
    red2(&M0[curi*64+c], a0c.x, a0c.y);
#pragma unroll
    for(int x=0;x<3;x++) red2(&M1[(curi*3+x)*64+c], a1c[x].x, a1c[x].y);
}

// ---------------- forward layer-1 edge kernel (i-sorted) -------------------
__global__ __launch_bounds__(256) void edge_fwd1_k(
    const float* __restrict__ h0, const float* __restrict__ h1)
{
    int tid = threadIdx.x;
    int cnt = g_cnt;
    int e0 = (blockIdx.x*8 + (tid>>5))*EPW;
    if(e0 >= cnt) return;
    int lane = tid & 31;
    int c = 2*lane;
    int eend = min(e0 + EPW, cnt);
    const float4* F2t = (const float4*)g_F[2];
    const float4* F3t = (const float4*)g_F[3];

    float* M0 = g_M;
    float2 a0c = make_float2(0.f,0.f);

    int2   ijn = g_Iij[e0];
    float4 mn  = g_Im[e0];
    float2 hn  = *(const float2*)&h0[ijn.y*64+c];
    float2 vn0 = *(const float2*)&h1[(ijn.y*3+0)*64+c];
    float2 vn1 = *(const float2*)&h1[(ijn.y*3+1)*64+c];
    float2 vn2 = *(const float2*)&h1[(ijn.y*3+2)*64+c];
    float  tn  = mn.x*BINSCALE; int bn = (int)tn; float frn = tn - bn;
    float4 P0n = F2t[bn*32+lane];
    float4 P1n = F3t[bn*32+lane];
    int curi = ijn.x;

    for(int e=e0;e<eend;e++){
        int2 ij = ijn; float4 m = mn; float2 h0j = hn; float fr = frn;
        float2 v0 = vn0, v1 = vn1, v2 = vn2;
        float4 P0 = P0n, P1 = P1n;
        if(e+1 < eend){
            ijn = g_Iij[e+1];
            mn  = g_Im[e+1];
            hn  = *(const float2*)&h0[ijn.y*64+c];
            vn0 = *(const float2*)&h1[(ijn.y*3+0)*64+c];
            vn1 = *(const float2*)&h1[(ijn.y*3+1)*64+c];
            vn2 = *(const float2*)&h1[(ijn.y*3+2)*64+c];
            tn = mn.x*BINSCALE; bn = (int)tn; frn = tn - bn;
            P0n = F2t[bn*32+lane];
            P1n = F3t[bn*32+lane];
        }
        if(ij.x != curi){
            red2(&M0[curi*64+c], a0c.x, a0c.y);
            a0c = make_float2(0.f,0.f);
            curi = ij.x;
        }
        float rh[3] = {m.y, m.z, m.w};
        float G0x, G0y, G2x, G2y;
        LERP2(P0, fr, G0x, G0y);
        LERP2(P1, fr, G2x, G2y);
        float tx = v0.x*rh[0] + v1.x*rh[1] + v2.x*rh[2];
        float ty = v0.y*rh[0] + v1.y*rh[1] + v2.y*rh[2];
        a0c.x += G0x*h0j.x + G2x*tx;
        a0c.y += G0y*h0j.y + G2y*ty;
    }
    red2(&M0[curi*64+c], a0c.x, a0c.y);
}

// ---------------- backward layer-0 (i-sorted; h1==0) -----------------------
__global__ __launch_bounds__(256) void edge_bwd0_k(
    const float* __restrict__ h0,
    const float* __restrict__ gM0, const float* __restrict__ gM1,
    float* __restrict__ F)
{
    int tid = threadIdx.x;
    int cnt = g_cnt;
    int e0 = (blockIdx.x*8 + (tid>>5))*EPW;
    if(e0 >= cnt) return;
    int lane = tid & 31;
    int c = 2*lane;
    int eend = min(e0 + EPW, cnt);
    const float4* F1t = (const float4*)g_F[1];
    const float4* Q0t = (const float4*)g_Q[0];
    const float4* Q1t = (const float4*)g_Q[1];

    int2   ijn = g_Iij[e0];
    float4 mn  = g_Im[e0];
    float2 hn  = *(const float2*)&h0[ijn.y*64+c];
    float  tn  = mn.x*BINSCALE; int bn = (int)tn; float frn = tn - bn;
    float4 PF1n = F1t[bn*32+lane];
    float4 PQ0n = Q0t[bn*32+lane];
    float4 PQ1n = Q1t[bn*32+lane];
    int curi = ijn.x;
    float2 gm0 = *(const float2*)&gM0[curi*64+c];
    float2 gm1[3];
#pragma unroll
    for(int x=0;x<3;x++) gm1[x] = *(const float2*)&gM1[(curi*3+x)*64+c];
    float fi = 0.f;

    for(int e=e0;e<eend;e++){
        int2 ij = ijn; float4 m = mn; float2 h0j = hn; float fr = frn;
        float4 PF1 = PF1n, PQ0 = PQ0n, PQ1 = PQ1n;
        if(e+1 < eend){
            ijn = g_Iij[e+1];
            mn  = g_Im[e+1];
            hn  = *(const float2*)&h0[ijn.y*64+c];
            tn = mn.x*BINSCALE; bn = (int)tn; frn = tn - bn;
            PF1n = F1t[bn*32+lane];
            PQ0n = Q0t[bn*32+lane];
            PQ1n = Q1t[bn*32+lane];
        }
        if(ij.x != curi){
            if(lane < 3) atomicAdd(&F[curi*3+lane], fi);
            fi = 0.f;
            curi = ij.x;
            gm0 = *(const float2*)&gM0[curi*64+c];
#pragma unroll
            for(int x=0;x<3;x++) gm1[x] = *(const float2*)&gM1[(curi*3+x)*64+c];
        }
        int j = ij.y;
        float d = m.x;
        float rh[3] = {m.y, m.z, m.w};
        float G1x, G1y, Q0x, Q0y, Q1x, Q1y;
        LERP2(PF1, fr, G1x, G1y);
        LERP2(PQ0, fr, Q0x, Q0y);
        LERP2(PQ1, fr, Q1x, Q1y);

        float gmrx = gm1[0].x*rh[0] + gm1[1].x*rh[1] + gm1[2].x*rh[2];
        float gmry = gm1[0].y*rh[0] + gm1[1].y*rh[1] + gm1[2].y*rh[2];
        float gf0x = gm0.x*h0j.x, gf0y = gm0.y*h0j.y;
        float gf1x = gmrx*h0j.x,  gf1y = gmry*h0j.y;
        float sd = gf0x*Q0x + gf0y*Q0y + gf1x*Q1x + gf1y*Q1y;
        float f1x = G1x*h0j.x, f1y = G1y*h0j.y;
        float gr0 = gm1[0].x*f1x + gm1[0].y*f1y;
        float gr1 = gm1[1].x*f1x + gm1[1].y*f1y;
        float gr2 = gm1[2].x*f1x + gm1[2].y*f1y;

        sd  = warpRed(sd);
        gr0 = warpRed(gr0);
        gr1 = warpRed(gr1);
        gr2 = warpRed(gr2);

        float gdr = gr0*rh[0] + gr1*rh[1] + gr2*rh[2];
        float invd = 1.0f/d;
        if(lane < 3){
            float gx = (lane==0) ? gr0 : ((lane==1) ? gr1 : gr2);
            float rx = rh[lane];
            float grij = (gx - gdr*rx)*invd + sd*rx;
            fi += grij;
            atomicAdd(&F[j*3+lane], -grij);
        }
    }
    if(lane < 3) atomicAdd(&F[curi*3+lane], fi);
}

// ---------------- backward layer-1 (j-sorted) ------------------------------
__global__ __launch_bounds__(256) void edge_bwd1_k(
    const float* __restrict__ h0, const float* __restrict__ h1,
    const float* __restrict__ gM0,
    float* __restrict__ gh0, float* __restrict__ gh1, float* __restrict__ F)
{
    int tid = threadIdx.x;
    int cnt = g_cnt;
    int e0 = (blockIdx.x*8 + (tid>>5))*EPW;
    if(e0 >= cnt) return;
    int lane = tid & 31;
    int c = 2*lane;
    int eend = min(e0 + EPW, cnt);
    const float4* F2t = (const float4*)g_F[2];
    const float4* F3t = (const float4*)g_F[3];
    const float4* Q2t = (const float4*)g_Q[2];
    const float4* Q3t = (const float4*)g_Q[3];

    int2   ijn = g_Jij[e0];
    float4 mn  = g_Jm[e0];
    float2 gmn = *(const float2*)&gM0[ijn.x*64+c];
    float  tn  = mn.x*BINSCALE; int bn = (int)tn; float frn = tn - bn;
    float4 PF2n = F2t[bn*32+lane];
    float4 PF3n = F3t[bn*32+lane];
    float4 PQ2n = Q2t[bn*32+lane];
    float4 PQ3n = Q3t[bn*32+lane];
    int curj = ijn.y;
    float2 h0j = *(const float2*)&h0[curj*64+c];
    float2 v[3];
#pragma unroll
    for(int x=0;x<3;x++) v[x] = *(const float2*)&h1[(curj*3+x)*64+c];
    float2 acc0 = make_float2(0,0);
    float2 acc1[3] = {{0,0},{0,0},{0,0}};
    float fj = 0.f;

    for(int e=e0;e<eend;e++){
        int2 ij = ijn; float4 m = mn; float2 gm0 = gmn; float fr = frn;
        float4 PF2 = PF2n, PF3 = PF3n, PQ2 = PQ2n, PQ3 = PQ3n;
        if(e+1 < eend){
            ijn = g_Jij[e+1];
            mn  = g_Jm[e+1];
            gmn = *(const float2*)&gM0[ijn.x*64+c];
            tn = mn.x*BINSCALE; bn = (int)tn; frn = tn - bn;
            PF2n = F2t[bn*32+lane];
            PF3n = F3t[bn*32+lane];
            PQ2n = Q2t[bn*32+lane];
            PQ3n = Q3t[bn*32+lane];
        }
        if(ij.y != curj){
            red2(&gh0[curj*64+c], acc0.x, acc0.y);
#pragma unroll
            for(int x=0;x<3;x++) red2(&gh1[(curj*3+x)*64+c], acc1[x].x, acc1[x].y);
            if(lane < 3) atomicAdd(&F[curj*3+lane], fj);
            acc0 = make_float2(0,0);
#pragma unroll
            for(int x=0;x<3;x++) acc1[x] = make_float2(0,0);
            fj = 0.f;
            curj = ij.y;
            h0j = *(const float2*)&h0[curj*64+c];
#pragma unroll
            for(int x=0;x<3;x++) v[x] = *(const float2*)&h1[(curj*3+x)*64+c];
        }
        int i = ij.x;
        float d = m.x;
        float rh[3] = {m.y, m.z, m.w};
        float G0x, G0y, G2x, G2y, Q0x, Q0y, Q2x, Q2y;
        LERP2(PF2, fr, G0x, G0y);
        LERP2(PF3, fr, G2x, G2y);
        LERP2(PQ2, fr, Q0x, Q0y);
        LERP2(PQ3, fr, Q2x, Q2y);

        float tx = v[0].x*rh[0] + v[1].x*rh[1] + v[2].x*rh[2];
        float ty = v[0].y*rh[0] + v[1].y*rh[1] + v[2].y*rh[2];
        float sd = gm0.x*(Q0x*h0j.x + Q2x*tx) + gm0.y*(Q0y*h0j.y + Q2y*ty);
        float f2x = G2x*gm0.x, f2y = G2y*gm0.y;
        float gr0 = f2x*v[0].x + f2y*v[0].y;
        float gr1 = f2x*v[1].x + f2y*v[1].y;
        float gr2 = f2x*v[2].x + f2y*v[2].y;

        acc0.x += gm0.x*G0x;
        acc0.y += gm0.y*G0y;
#pragma unroll
        for(int x=0;x<3;x++){
            acc1[x].x += f2x*rh[x];
            acc1[x].y += f2y*rh[x];
        }

        sd  = warpRed(sd);
        gr0 = warpRed(gr0);
        gr1 = warpRed(gr1);
        gr2 = warpRed(gr2);

        float gdr = gr0*rh[0] + gr1*rh[1] + gr2*rh[2];
        float invd = 1.0f/d;
        if(lane < 3){
            float gx = (lane==0) ? gr0 : ((lane==1) ? gr1 : gr2);
            float rx = rh[lane];
            float grij = (gx - gdr*rx)*invd + sd*rx;
            atomicAdd(&F[i*3+lane], grij);
            fj -= grij;
        }
    }
    red2(&gh0[curj*64+c], acc0.x, acc0.y);
#pragma unroll
    for(int x=0;x<3;x++) red2(&gh1[(curj*3+x)*64+c], acc1[x].x, acc1[x].y);
    if(lane < 3) atomicAdd(&F[curj*3+lane], fj);
}

// ---------------- combined forward node GEMMs ------------------------------
// blocks [0,G3B): h1b = M1@Wmsg1 (3NN rows)
// blocks [G3B,G3B+G1B): h0b = silu(M0@Wmsg0 + h0a@Wself0 + b0), s0 = preact
__global__ __launch_bounds__(256) void mmfwdC_k(
    const float* __restrict__ M0, const float* __restrict__ M1,
    const float* __restrict__ h0a,
    const float* __restrict__ Wmsg0, const float* __restrict__ Wself0,
    const float* __restrict__ Wmsg1, const float* __restrict__ b0,
    float* __restrict__ h0b, float* __restrict__ s0, float* __restrict__ h1b)
{
    __shared__ float sW[64*64];
    __shared__ float sX[128*64];
    int tid = threadIdx.x;
    int blk = blockIdx.x;
    bool second = (blk >= G3B);
    const float* A    = second ? M0 : M1;
    const float* W1   = second ? Wmsg0 : Wmsg1;
    const float* B    = second ? h0a : nullptr;
    const float* W2   = second ? Wself0 : nullptr;
    const float* bias = second ? b0 : nullptr;
    float* out  = second ? h0b : h1b;
    float* sOut = second ? s0 : nullptr;
    int rows = second ? NN : 3*NN;
    int row0 = (second ? (blk - G3B) : blk)*128;

    int tc = tid & 15, tr = tid >> 4;
    float acc[8][4];
    if(bias){
        float4 b = *(const float4*)&bias[4*tc];
#pragma unroll
        for(int i=0;i<8;i++){ acc[i][0]=b.x; acc[i][1]=b.y; acc[i][2]=b.z; acc[i][3]=b.w; }
    } else {
#pragma unroll
        for(int i=0;i<8;i++){ acc[i][0]=acc[i][1]=acc[i][2]=acc[i][3]=0.f; }
    }
    int nph = B ? 2 : 1;
    for(int ph=0; ph<nph; ph++){
        const float* Xp = ph ? B : A;
        const float* Wp = ph ? W2 : W1;
        if(ph) __syncthreads();
        for(int k=tid;k<4096;k+=256) sW[k] = Wp[k];
        for(int k=tid;k<8192;k+=256){
            int r = k>>6, c = k&63;
            int gr = row0 + r;
            sX[k] = (gr < rows) ? Xp[gr*64+c] : 0.f;
        }
        __syncthreads();
        const float* xr = &sX[(tr*8)*64];
#pragma unroll 4
        for(int k=0;k<64;k++){
            float4 w = *(const float4*)&sW[k*64 + tc*4];
            float a[8];
#pragma unroll
            for(int i=0;i<8;i++) a[i] = xr[i*64+k];
#pragma unroll
            for(int i=0;i<8;i++){
                acc[i][0]=fmaf(a[i],w.x,acc[i][0]);
                acc[i][1]=fmaf(a[i],w.y,acc[i][1]);
                acc[i][2]=fmaf(a[i],w.z,acc[i][2]);
                acc[i][3]=fmaf(a[i],w.w,acc[i][3]);
            }
        }
    }
#pragma unroll
    for(int i=0;i<8;i++){
        int r = row0 + tr*8 + i;
        if(r >= rows) continue;
        float4 o;
        float* oo = &o.x;
#pragma unroll
        for(int jj=0;jj<4;jj++){
            float u = acc[i][jj];
            if(sOut){
                float sig = 1.f/(1.f + expf(-u));
                oo[jj] = u*sig;
            } else oo[jj] = u;
        }
        if(sOut){
            *(float4*)&sOut[r*64 + tc*4] = make_float4(acc[i][0],acc[i][1],acc[i][2],acc[i][3]);
        }
        *(float4*)&out[r*64 + tc*4] = o;
    }
}

// ---------------- fused layer-1 forward + readout + backward ---------------
__global__ __launch_bounds__(256) void l1_fused_k(
    const float* __restrict__ M0,    const float* __restrict__ h0b,
    const float* __restrict__ Wmsg,  const float* __restrict__ Wself,
    const float* __restrict__ bias,
    const float* __restrict__ Wro1,  const float* __restrict__ bro1,
    const float* __restrict__ Wro2,
    float* __restrict__ gM0, float* __restrict__ gB, int rows)
{
    __shared__ float sW[64*68];
    __shared__ float sX[64*65];
    int tid = threadIdx.x;
    int row0 = blockIdx.x*64;
    int tc = tid & 15, tr = tid >> 4;

    float acc[4][4], u1[4][4];
    {
        float4 b = *(const float4*)&bias[4*tc];
#pragma unroll
        for(int i=0;i<4;i++){ acc[i][0]=b.x; acc[i][1]=b.y; acc[i][2]=b.z; acc[i][3]=b.w; }
    }
    for(int k=tid;k<4096;k+=256) sW[k] = Wmsg[k];
    for(int k=tid;k<4096;k+=256){
        int r = k>>6, c = k&63;
        int gr = row0 + r;
        sX[r*65+c] = (gr < rows) ? M0[gr*64+c] : 0.f;
    }
    __syncthreads();
    dot64(&sX[(tr*4)*65], sW, 64, acc, tc);
    __syncthreads();
    for(int k=tid;k<4096;k+=256) sW[k] = Wself[k];
    for(int k=tid;k<4096;k+=256){
        int r = k>>6, c = k&63;
        int gr = row0 + r;
        sX[r*65+c] = (gr < rows) ? h0b[gr*64+c] : 0.f;
    }
    __syncthreads();
    dot64(&sX[(tr*4)*65], sW, 64, acc, tc);
#pragma unroll
    for(int i=0;i<4;i++)
#pragma unroll
        for(int jj=0;jj<4;jj++) u1[i][jj] = acc[i][jj];
    __syncthreads();
    for(int k=tid;k<4096;k+=256) sW[k] = Wro1[k];
#pragma unroll
    for(int i=0;i<4;i++)
#pragma unroll
        for(int jj=0;jj<4;jj++){
            float u = u1[i][jj];
            float sig = 1.f/(1.f + expf(-u));
            sX[(tr*4+i)*65 + tc*4 + jj] = u*sig;
        }
    {
        float4 b = *(const float4*)&bro1[4*tc];
#pragma unroll
        for(int i=0;i<4;i++){ acc[i][0]=b.x; acc[i][1]=b.y; acc[i][2]=b.z; acc[i][3]=b.w; }
    }
    __syncthreads();
    dot64(&sX[(tr*4)*65], sW, 64, acc, tc);
    __syncthreads();
    {
        float4 ro2v = *(const float4*)&Wro2[4*tc];
#pragma unroll
        for(int i=0;i<4;i++)
#pragma unroll
            for(int jj=0;jj<4;jj++){
                float u = acc[i][jj];
                float sig = 1.f/(1.f + expf(-u));
                sX[(tr*4+i)*65 + tc*4 + jj] = (&ro2v.x)[jj]*sig*fmaf(u, 1.f-sig, 1.f);
            }
    }
    for(int k=tid;k<4096;k+=256){
        int cout = k>>6, dd = k&63;
        sW[dd*68+cout] = Wro1[k];
    }
    __syncthreads();
#pragma unroll
    for(int i=0;i<4;i++){ acc[i][0]=acc[i][1]=acc[i][2]=acc[i][3]=0.f; }
    dot64(&sX[(tr*4)*65], sW, 68, acc, tc);
    __syncthreads();
#pragma unroll
    for(int i=0;i<4;i++)
#pragma unroll
        for(int jj=0;jj<4;jj++){
            float u = u1[i][jj];
            float sig = 1.f/(1.f + expf(-u));
            sX[(tr*4+i)*65 + tc*4 + jj] = acc[i][jj]*sig*fmaf(u, 1.f-sig, 1.f);
        }
    for(int k=tid;k<4096;k+=256){
        int cout = k>>6, dd = k&63;
        sW[dd*68+cout] = Wmsg[k];
    }
    __syncthreads();
#pragma unroll
    for(int i=0;i<4;i++){ acc[i][0]=acc[i][1]=acc[i][2]=acc[i][3]=0.f; }
    dot64(&sX[(tr*4)*65], sW, 68, acc, tc);
#pragma unroll
    for(int i=0;i<4;i++){
        int r = row0 + tr*4 + i;
        if(r >= rows) continue;
        *(float4*)&gM0[r*64 + tc*4] = make_float4(acc[i][0],acc[i][1],acc[i][2],acc[i][3]);
    }
    __syncthreads();
    for(int k=tid;k<4096;k+=256){
        int cout = k>>6, dd = k&63;
        sW[dd*68+cout] = Wself[k];
    }
    __syncthreads();
#pragma unroll
    for(int i=0;i<4;i++){ acc[i][0]=acc[i][1]=acc[i][2]=acc[i][3]=0.f; }
    dot64(&sX[(tr*4)*65], sW, 68, acc, tc);
#pragma unroll
    for(int i=0;i<4;i++){
        int r = row0 + tr*4 + i;
        if(r >= rows) continue;
        *(float4*)&gB[r*64 + tc*4] = make_float4(acc[i][0],acc[i][1],acc[i][2],acc[i][3]);
    }
}

// ---------------- combined layer-0 backward GEMMs --------------------------
__global__ __launch_bounds__(256) void bwd0mm_k(
    const float* __restrict__ gB, const float* __restrict__ s0,
    const float* __restrict__ Wmsg0, float* __restrict__ gM0,
    const float* __restrict__ gh1, const float* __restrict__ Wmsg1,
    float* __restrict__ gM1)
{
    __shared__ float sWt[64*68];
    __shared__ float sG[64*65];
    int tid = threadIdx.x;
    int blk = blockIdx.x;
    const float *G, *S, *W; float* out; int rows, row0;
    if(blk < T1B){ G = gB;  S = s0;      W = Wmsg0; out = gM0; rows = NN;   row0 = blk*64; }
    else         { G = gh1; S = nullptr; W = Wmsg1; out = gM1; rows = 3*NN; row0 = (blk-T1B)*64; }
    int tc = tid & 15, tr = tid >> 4;
    for(int k=tid;k<4096;k+=256){
        int r = k>>6, c = k&63;
        int gr = row0 + r;
        float v = 0.f;
        if(gr < rows){
            float g = G[gr*64+c];
            if(S){
                float x = S[gr*64+c];
                float sig = 1.f/(1.f + expf(-x));
                v = g*sig*fmaf(x, 1.f-sig, 1.f);
            } else v = g;
        }
        sG[r*65+c] = v;
    }
    for(int k=tid;k<4096;k+=256){
        int cout = k>>6, dd = k&63;
        sWt[dd*68+cout] = W[k];
    }
    __syncthreads();
    float acc[4][4];
#pragma unroll
    for(int i=0;i<4;i++){ acc[i][0]=acc[i][1]=acc[i][2]=acc[i][3]=0.f; }
    dot64(&sG[(tr*4)*65], sWt, 68, acc, tc);
#pragma unroll
    for(int i=0;i<4;i++){
        int r = row0 + tr*4 + i;
        if(r >= rows) continue;
        *(float4*)&out[r*64 + tc*4] = make_float4(acc[i][0],acc[i][1],acc[i][2],acc[i][3]);
    }
}

// ---------------- host orchestration ---------------------------------------
extern "C" void kernel_launch(void* const* d_in, const int* in_sizes, int n_in,
                              void* d_out, int out_size)
{
    const float* coord  = (const float*)d_in[0];
    const float* emb    = (const float*)d_in[1];
    const float* Wr     = (const float*)d_in[2];
    const float* br     = (const float*)d_in[3];
    const float* Wself0 = (const float*)d_in[4];
    const float* Wmsg0  = (const float*)d_in[5];
    const float* b0     = (const float*)d_in[6];
    const float* Wmsg1  = (const float*)d_in[7];
    const float* Wro1   = (const float*)d_in[9];
    const float* bro1   = (const float*)d_in[10];
    const float* Wro2   = (const float*)d_in[11];
    const int*   z      = (const int*)d_in[13];
    const int*   ei     = (const int*)d_in[14];
    const int*   ej     = (const int*)d_in[15];
    float* F = (float*)d_out;
    (void)in_sizes; (void)n_in; (void)out_size;

    float *h0a,*h0b,*s0,*h1b,*Mbuf,*gM0p,*gM1p,*gB;
    cudaGetSymbolAddress((void**)&h0a, g_h0a);
    cudaGetSymbolAddress((void**)&h0b, g_h0b);
    cudaGetSymbolAddress((void**)&s0,  g_s0);
    cudaGetSymbolAddress((void**)&h1b, g_h1b);
    cudaGetSymbolAddress((void**)&Mbuf,g_M);
    cudaGetSymbolAddress((void**)&gM0p,g_gM0);
    cudaGetSymbolAddress((void**)&gM1p,g_gM1);
    cudaGetSymbolAddress((void**)&gB,  g_gB);
    float* M0  = Mbuf;
    float* M1  = Mbuf + NN*CC;     // aliased: gh1 lives here after M1 is consumed
    float* gh1 = M1;

    const int EB  = (EE + EPB-1)/EPB;
    const int TABN = 4*NB2*CC;

    tabbuild_k<<<(TABN+255)/256, 256>>>(Wr, br);
    embed_zero_k<<<1024, 256>>>(emb, z, F);
    geomA_k<<<(EE+255)/256, 256>>>(coord, ei, ej);
    scanA_k<<<2*NBK, SCH>>>();
    scanB_k<<<1, 256>>>();
    scanC_k<<<2*NBK, SCH>>>();
    geomB_k<<<(EE+255)/256, 256>>>(coord, ei, ej);

    // ---- layer 0 forward
    edge_fwd0_k<<<EB, 256>>>(h0a);
    mmfwdC_k<<<G3B + G1B, 256>>>(M0, M1, h0a, Wmsg0, Wself0, Wmsg1, b0, h0b, s0, h1b);
    cudaMemsetAsync(Mbuf, 0, NN*CC*4*sizeof(float));   // zeros M0 AND gh1 (aliased M1)

    // ---- layer 1 forward (edge) + fused node fwd/readout/backward
    edge_fwd1_k<<<EB, 256>>>(h0b, h1b);
    l1_fused_k<<<T1B, 256>>>(M0, h0b, Wmsg0 + 4096, Wself0 + 4096, b0 + 64,
                             Wro1, bro1, Wro2, gM0p, gB, NN);

    // ---- layer 1 backward (j-sorted scatter)
    edge_bwd1_k<<<EB, 256>>>(h0b, h1b, gM0p, gB, gh1, F);

    // ---- layer 0 backward (combined GEMMs + i-sorted edge)
    bwd0mm_k<<<T1B + T3B, 256>>>(gB, s0, Wmsg0, gM0p, gh1, Wmsg1, gM1p);
    edge_bwd0_k<<<EB, 256>>>(h0a, gM0p, gM1p, F);
}